// round 1
// baseline (speedup 1.0000x reference)
#include <cuda_runtime.h>
#include <math.h>

// ---------------- fixed problem geometry ----------------
#define MAXN 50000
#define MAXE 800000
// C=128, A_ALL=256, RAD_IN=32, FC1=FC2=64, H=8, AH=VH=16

// ---------------- scratch (device globals: no allocation allowed) ----------
__device__ __align__(16) float g_msg_src[(size_t)MAXN * 128];
__device__ __align__(16) float g_msg_dst[(size_t)MAXN * 128];
__device__ __align__(16) float g_m[(size_t)MAXE * 128];      // premultiplied message
__device__ __align__(16) float g_value[(size_t)MAXE * 128];  // per-head values
__device__ __align__(16) float g_score[(size_t)MAXE * 8];
__device__ __align__(16) float g_nmax[(size_t)MAXN * 8];
__device__ __align__(16) float g_nsum[(size_t)MAXN * 8];
__device__ __align__(16) float g_nacc[(size_t)MAXN * 128];

// float atomic max via signed/unsigned int ordering trick (init = -inf)
__device__ __forceinline__ void atomicMaxFloat(float* addr, float v) {
    if (v >= 0.0f) atomicMax((int*)addr, __float_as_int(v));
    else           atomicMin((unsigned int*)addr, __float_as_uint(v));
}

// ---------------- K0: init segment buffers ----------------
__global__ void init_kernel(int n) {
    int i = blockIdx.x * blockDim.x + threadIdx.x;
    if (i < n * 128) g_nacc[i] = 0.0f;
    if (i < n * 8) {
        g_nmax[i] = __int_as_float(0xFF800000); // -inf
        g_nsum[i] = 0.0f;
    }
}

// ---------------- K1: node GEMM  out = X(128) @ W(128x128) [+bias] ----------
// BM=64, BN=128, BK=32, 256 threads, each thread 4x8 outputs.
__global__ __launch_bounds__(256) void node_gemm_kernel(
    const float* __restrict__ X, const float* __restrict__ W,
    const float* __restrict__ bias, int n, int which)
{
    float* __restrict__ out = which ? g_msg_dst : g_msg_src;
    __shared__ float At[32 * 64];   // [k][m]
    __shared__ float Bs[32 * 128];  // [k][n]
    int tid = threadIdx.x;
    int r0 = blockIdx.x * 64;
    int cg = tid & 15, rg = tid >> 4;
    int col = cg * 8, row = rg * 4;

    float acc[4][8];
#pragma unroll
    for (int i = 0; i < 4; i++)
#pragma unroll
        for (int j = 0; j < 8; j++) acc[i][j] = 0.0f;

    int lm = tid >> 2, lk = (tid & 3) * 8;
    int lkr = tid >> 3, lc = (tid & 7) * 16;

    for (int k0 = 0; k0 < 128; k0 += 32) {
        float4 a0, a1;
        int gr = r0 + lm;
        if (gr < n) {
            a0 = *(const float4*)(X + (size_t)gr * 128 + k0 + lk);
            a1 = *(const float4*)(X + (size_t)gr * 128 + k0 + lk + 4);
        } else {
            a0 = make_float4(0.f, 0.f, 0.f, 0.f); a1 = a0;
        }
        At[(lk + 0) * 64 + lm] = a0.x; At[(lk + 1) * 64 + lm] = a0.y;
        At[(lk + 2) * 64 + lm] = a0.z; At[(lk + 3) * 64 + lm] = a0.w;
        At[(lk + 4) * 64 + lm] = a1.x; At[(lk + 5) * 64 + lm] = a1.y;
        At[(lk + 6) * 64 + lm] = a1.z; At[(lk + 7) * 64 + lm] = a1.w;
#pragma unroll
        for (int q = 0; q < 4; q++)
            *(float4*)(Bs + lkr * 128 + lc + 4 * q) =
                *(const float4*)(W + (size_t)(k0 + lkr) * 128 + lc + 4 * q);
        __syncthreads();
#pragma unroll
        for (int kk = 0; kk < 32; kk++) {
            float a[4], b[8];
            *(float4*)a       = *(float4*)(At + kk * 64 + row);
            *(float4*)(b)     = *(float4*)(Bs + kk * 128 + col);
            *(float4*)(b + 4) = *(float4*)(Bs + kk * 128 + col + 4);
#pragma unroll
            for (int i = 0; i < 4; i++)
#pragma unroll
                for (int j = 0; j < 8; j++) acc[i][j] += a[i] * b[j];
        }
        __syncthreads();
    }

    float bj[8];
    if (bias) {
        *(float4*)bj       = *(const float4*)(bias + col);
        *(float4*)(bj + 4) = *(const float4*)(bias + col + 4);
    } else {
#pragma unroll
        for (int j = 0; j < 8; j++) bj[j] = 0.0f;
    }
#pragma unroll
    for (int i = 0; i < 4; i++) {
        int gr = r0 + row + i;
        if (gr >= n) continue;
        float4 o0 = make_float4(acc[i][0] + bj[0], acc[i][1] + bj[1],
                                acc[i][2] + bj[2], acc[i][3] + bj[3]);
        float4 o1 = make_float4(acc[i][4] + bj[4], acc[i][5] + bj[5],
                                acc[i][6] + bj[6], acc[i][7] + bj[7]);
        *(float4*)(out + (size_t)gr * 128 + col)     = o0;
        *(float4*)(out + (size_t)gr * 128 + col + 4) = o1;
    }
}

// ---------------- K2: radial MLP + gather + premultiply -> g_m --------------
// 64 edges per block, 128 threads. All weights staged in SMEM.
__global__ __launch_bounds__(128) void edge_mlp_kernel(
    const float* __restrict__ edge_scalars, const float* __restrict__ edge_attr,
    const int* __restrict__ edge_src, const int* __restrict__ edge_dst,
    const float* __restrict__ w1, const float* __restrict__ b1,
    const float* __restrict__ w2, const float* __restrict__ b2,
    const float* __restrict__ w3, const float* __restrict__ b3,
    int E)
{
    extern __shared__ float sm[];
    float* sW1  = sm;              // 32*64  = 2048
    float* sB1  = sW1 + 2048;      // 64
    float* sW2  = sB1 + 64;        // 64*64  = 4096
    float* sB2  = sW2 + 4096;      // 64
    float* sW3  = sB2 + 64;        // 64*128 = 8192
    float* sB3  = sW3 + 8192;      // 128
    float* sXt  = sB3 + 128;       // 32*64  = 2048   [k][m]
    float* sH1t = sXt + 2048;      // 64*68  = 4352   [k][m] padded stride 68
    float* sH2t = sH1t + 4352;     // 64*68  = 4352
    __shared__ int   sSrc[64];
    __shared__ int   sDst[64];
    __shared__ float sAttr[64];

    int tid = threadIdx.x;
    int e0 = blockIdx.x * 64;

    for (int i = tid * 4; i < 2048; i += 512) *(float4*)(sW1 + i) = *(const float4*)(w1 + i);
    for (int i = tid * 4; i < 4096; i += 512) *(float4*)(sW2 + i) = *(const float4*)(w2 + i);
    for (int i = tid * 4; i < 8192; i += 512) *(float4*)(sW3 + i) = *(const float4*)(w3 + i);
    if (tid < 64)  { sB1[tid] = b1[tid]; sB2[tid] = b2[tid]; }
    if (tid < 128) sB3[tid] = b3[tid];
    if (tid < 64) {
        int e = min(e0 + tid, E - 1);
        sSrc[tid] = edge_src[e];
        sDst[tid] = edge_dst[e];
        sAttr[tid] = edge_attr[e];
    }
    {
        int m = tid >> 1, kb = (tid & 1) * 16;
        int e = min(e0 + m, E - 1);
#pragma unroll
        for (int q = 0; q < 4; q++) {
            float4 v = *(const float4*)(edge_scalars + (size_t)e * 32 + kb + 4 * q);
            sXt[(kb + 4 * q + 0) * 64 + m] = v.x;
            sXt[(kb + 4 * q + 1) * 64 + m] = v.y;
            sXt[(kb + 4 * q + 2) * 64 + m] = v.z;
            sXt[(kb + 4 * q + 3) * 64 + m] = v.w;
        }
    }
    __syncthreads();

    int rg = tid >> 3, cg = tid & 7;
    int row = rg * 4;

    // GEMM1: H1 = silu(X @ w1 + b1)   (64x64, K=32)
    {
        int col = cg * 8;
        float acc[4][8];
#pragma unroll
        for (int i = 0; i < 4; i++)
#pragma unroll
            for (int j = 0; j < 8; j++) acc[i][j] = 0.0f;
#pragma unroll
        for (int k = 0; k < 32; k++) {
            float a[4], b[8];
            *(float4*)a       = *(float4*)(sXt + k * 64 + row);
            *(float4*)(b)     = *(float4*)(sW1 + k * 64 + col);
            *(float4*)(b + 4) = *(float4*)(sW1 + k * 64 + col + 4);
#pragma unroll
            for (int i = 0; i < 4; i++)
#pragma unroll
                for (int j = 0; j < 8; j++) acc[i][j] += a[i] * b[j];
        }
#pragma unroll
        for (int i = 0; i < 4; i++)
#pragma unroll
            for (int j = 0; j < 8; j++) {
                float x = acc[i][j] + sB1[col + j];
                x = x / (1.0f + __expf(-x));
                sH1t[(col + j) * 68 + (row + i)] = x;
            }
    }
    __syncthreads();

    // GEMM2: H2 = silu(H1 @ w2 + b2)  (64x64, K=64)
    {
        int col = cg * 8;
        float acc[4][8];
#pragma unroll
        for (int i = 0; i < 4; i++)
#pragma unroll
            for (int j = 0; j < 8; j++) acc[i][j] = 0.0f;
#pragma unroll
        for (int k = 0; k < 64; k++) {
            float a[4], b[8];
            *(float4*)a       = *(float4*)(sH1t + k * 68 + row);
            *(float4*)(b)     = *(float4*)(sW2 + k * 64 + col);
            *(float4*)(b + 4) = *(float4*)(sW2 + k * 64 + col + 4);
#pragma unroll
            for (int i = 0; i < 4; i++)
#pragma unroll
                for (int j = 0; j < 8; j++) acc[i][j] += a[i] * b[j];
        }
        __syncthreads();  // all reads of sH1t done before sH2t region reuse? (distinct; kept for ordering of sH2t writes)
#pragma unroll
        for (int i = 0; i < 4; i++)
#pragma unroll
            for (int j = 0; j < 8; j++) {
                float x = acc[i][j] + sB2[col + j];
                x = x / (1.0f + __expf(-x));
                sH2t[(col + j) * 68 + (row + i)] = x;
            }
    }
    __syncthreads();

    // GEMM3: rad = H2 @ w3 + b3 (64x128, K=64); fuse gather+premultiply
    {
        int col = cg * 16;
        float acc[4][16];
#pragma unroll
        for (int i = 0; i < 4; i++)
#pragma unroll
            for (int j = 0; j < 16; j++) acc[i][j] = 0.0f;
#pragma unroll
        for (int k = 0; k < 64; k++) {
            float a[4], b[16];
            *(float4*)a        = *(float4*)(sH2t + k * 68 + row);
            *(float4*)(b)      = *(float4*)(sW3 + k * 128 + col);
            *(float4*)(b + 4)  = *(float4*)(sW3 + k * 128 + col + 4);
            *(float4*)(b + 8)  = *(float4*)(sW3 + k * 128 + col + 8);
            *(float4*)(b + 12) = *(float4*)(sW3 + k * 128 + col + 12);
#pragma unroll
            for (int i = 0; i < 4; i++)
#pragma unroll
                for (int j = 0; j < 16; j++) acc[i][j] += a[i] * b[j];
        }
#pragma unroll
        for (int i = 0; i < 4; i++) {
            int e = e0 + row + i;
            if (e >= E) continue;
            int src = sSrc[row + i], dstn = sDst[row + i];
            float at = sAttr[row + i];
#pragma unroll
            for (int q = 0; q < 4; q++) {
                float4 ms = *(const float4*)(g_msg_src + (size_t)src * 128 + col + 4 * q);
                float4 md = *(const float4*)(g_msg_dst + (size_t)dstn * 128 + col + 4 * q);
                float4 o;
                o.x = (ms.x + md.x) * at * (acc[i][4 * q + 0] + sB3[col + 4 * q + 0]);
                o.y = (ms.y + md.y) * at * (acc[i][4 * q + 1] + sB3[col + 4 * q + 1]);
                o.z = (ms.z + md.z) * at * (acc[i][4 * q + 2] + sB3[col + 4 * q + 2]);
                o.w = (ms.w + md.w) * at * (acc[i][4 * q + 3] + sB3[col + 4 * q + 3]);
                *(float4*)(g_m + (size_t)e * 128 + col + 4 * q) = o;
            }
        }
    }
}

// ---------------- K3: t = m @ w_sep + b_sep; alpha/score/value; seg-max -----
// BM=64 edges, BN=256, BK=32, 256 threads, 8x8 per thread.
__global__ __launch_bounds__(256) void edge_attn_kernel(
    const float* __restrict__ w_sep, const float* __restrict__ b_sep,
    const float* __restrict__ alpha_dot, const int* __restrict__ edge_dst,
    int E)
{
    extern __shared__ float sm3[];
    float* sAt = sm3;          // 32*64  = 2048  [k][m]
    float* sB  = sAt + 2048;   // 32*256 = 8192  [k][n]
    __shared__ int   sDst[64];
    __shared__ float sAD[128];

    int tid = threadIdx.x;
    int e0 = blockIdx.x * 64;
    if (tid < 64)  sDst[tid] = edge_dst[min(e0 + tid, E - 1)];
    if (tid < 128) sAD[tid] = alpha_dot[tid];

    int cg = tid & 31, rg = tid >> 5;
    int col = cg * 8, row = rg * 8;

    float acc[8][8];
#pragma unroll
    for (int i = 0; i < 8; i++)
#pragma unroll
        for (int j = 0; j < 8; j++) acc[i][j] = 0.0f;

    int lm = tid >> 2, lk = (tid & 3) * 8;
    int lkr = tid >> 3, lc = (tid & 7) * 32;

    for (int k0 = 0; k0 < 128; k0 += 32) {
        int e = min(e0 + lm, E - 1);
        float4 a0 = *(const float4*)(g_m + (size_t)e * 128 + k0 + lk);
        float4 a1 = *(const float4*)(g_m + (size_t)e * 128 + k0 + lk + 4);
        sAt[(lk + 0) * 64 + lm] = a0.x; sAt[(lk + 1) * 64 + lm] = a0.y;
        sAt[(lk + 2) * 64 + lm] = a0.z; sAt[(lk + 3) * 64 + lm] = a0.w;
        sAt[(lk + 4) * 64 + lm] = a1.x; sAt[(lk + 5) * 64 + lm] = a1.y;
        sAt[(lk + 6) * 64 + lm] = a1.z; sAt[(lk + 7) * 64 + lm] = a1.w;
#pragma unroll
        for (int q = 0; q < 8; q++)
            *(float4*)(sB + lkr * 256 + lc + 4 * q) =
                *(const float4*)(w_sep + (size_t)(k0 + lkr) * 256 + lc + 4 * q);
        __syncthreads();
#pragma unroll
        for (int kk = 0; kk < 32; kk++) {
            float a[8], b[8];
            *(float4*)(a)     = *(float4*)(sAt + kk * 64 + row);
            *(float4*)(a + 4) = *(float4*)(sAt + kk * 64 + row + 4);
            *(float4*)(b)     = *(float4*)(sB + kk * 256 + col);
            *(float4*)(b + 4) = *(float4*)(sB + kk * 256 + col + 4);
#pragma unroll
            for (int i = 0; i < 8; i++)
#pragma unroll
                for (int j = 0; j < 8; j++) acc[i][j] += a[i] * b[j];
        }
        __syncthreads();
    }

    // bias
    float bj[8];
    *(float4*)(bj)     = *(const float4*)(b_sep + col);
    *(float4*)(bj + 4) = *(const float4*)(b_sep + col + 4);
#pragma unroll
    for (int i = 0; i < 8; i++)
#pragma unroll
        for (int j = 0; j < 8; j++) acc[i][j] += bj[j];

    int h = cg >> 2;      // head 0..7   (each head spans 32 output cols)
    int sub = cg & 3;     // 0,1: alpha halves; 2,3: value halves

    if (sub >= 2) {
        // value columns: store straight to g_value[e][h*16 + 0..15]
        int vb = h * 16 + (sub - 2) * 8;
#pragma unroll
        for (int i = 0; i < 8; i++) {
            int e = e0 + row + i;
            if (e >= E) continue;
            float4 v0 = make_float4(acc[i][0], acc[i][1], acc[i][2], acc[i][3]);
            float4 v1 = make_float4(acc[i][4], acc[i][5], acc[i][6], acc[i][7]);
            *(float4*)(g_value + (size_t)e * 128 + vb)     = v0;
            *(float4*)(g_value + (size_t)e * 128 + vb + 4) = v1;
        }
    }

    // smooth-leaky + score partial dot (all lanes compute; only sub==0 commits)
    float part[8];
#pragma unroll
    for (int i = 0; i < 8; i++) {
        float p = 0.0f;
#pragma unroll
        for (int j = 0; j < 8; j++) {
            float x = acc[i][j];
            float sg = 1.0f / (1.0f + __expf(-x));
            float a = x * (0.2f + 0.8f * sg);  // 0.6x + 0.4x*(2*sig-1)
            p += a * sAD[h * 16 + (sub & 1) * 8 + j];
        }
        part[i] = p;
    }
#pragma unroll
    for (int i = 0; i < 8; i++) {
        float tot = part[i] + __shfl_xor_sync(0xffffffffu, part[i], 1);
        int e = e0 + row + i;
        if (sub == 0 && e < E) {
            g_score[(size_t)e * 8 + h] = tot;
            atomicMaxFloat(&g_nmax[(size_t)sDst[row + i] * 8 + h], tot);
        }
    }
}

// ---------------- K4: exp + segment sums (one warp per edge) ----------------
__global__ __launch_bounds__(256) void scatter_kernel(const int* __restrict__ edge_dst, int E)
{
    int gw = (blockIdx.x * blockDim.x + threadIdx.x) >> 5;
    int lane = threadIdx.x & 31;
    if (gw >= E) return;
    int d = edge_dst[gw];
    int h = lane >> 2;
    float s = g_score[(size_t)gw * 8 + h];
    float mx = g_nmax[(size_t)d * 8 + h];
    float w = __expf(s - mx);
    if ((lane & 3) == 0) atomicAdd(&g_nsum[(size_t)d * 8 + h], w);
    float4 v = *(const float4*)(g_value + (size_t)gw * 128 + lane * 4);
    float* p = g_nacc + (size_t)d * 128 + lane * 4;
    atomicAdd(p + 0, v.x * w);
    atomicAdd(p + 1, v.y * w);
    atomicAdd(p + 2, v.z * w);
    atomicAdd(p + 3, v.w * w);
}

// ---------------- K5: out = (nacc / (nsum+eps)) @ w_proj + b_proj -----------
__global__ __launch_bounds__(256) void out_gemm_kernel(
    const float* __restrict__ W, const float* __restrict__ bias,
    float* __restrict__ out, int n)
{
    __shared__ float At[32 * 64];
    __shared__ float Bs[32 * 128];
    int tid = threadIdx.x;
    int r0 = blockIdx.x * 64;
    int cg = tid & 15, rg = tid >> 4;
    int col = cg * 8, row = rg * 4;

    float acc[4][8];
#pragma unroll
    for (int i = 0; i < 4; i++)
#pragma unroll
        for (int j = 0; j < 8; j++) acc[i][j] = 0.0f;

    int lm = tid >> 2, lk = (tid & 3) * 8;
    int lkr = tid >> 3, lc = (tid & 7) * 16;

    for (int k0 = 0; k0 < 128; k0 += 32) {
        float4 a0, a1;
        int gr = r0 + lm;
        if (gr < n) {
            a0 = *(const float4*)(g_nacc + (size_t)gr * 128 + k0 + lk);
            a1 = *(const float4*)(g_nacc + (size_t)gr * 128 + k0 + lk + 4);
            int hh = (k0 + lk) >> 4;  // 8-aligned chunk stays within one head
            float inv = 1.0f / (g_nsum[(size_t)gr * 8 + hh] + 1e-16f);
            a0.x *= inv; a0.y *= inv; a0.z *= inv; a0.w *= inv;
            a1.x *= inv; a1.y *= inv; a1.z *= inv; a1.w *= inv;
        } else {
            a0 = make_float4(0.f, 0.f, 0.f, 0.f); a1 = a0;
        }
        At[(lk + 0) * 64 + lm] = a0.x; At[(lk + 1) * 64 + lm] = a0.y;
        At[(lk + 2) * 64 + lm] = a0.z; At[(lk + 3) * 64 + lm] = a0.w;
        At[(lk + 4) * 64 + lm] = a1.x; At[(lk + 5) * 64 + lm] = a1.y;
        At[(lk + 6) * 64 + lm] = a1.z; At[(lk + 7) * 64 + lm] = a1.w;
#pragma unroll
        for (int q = 0; q < 4; q++)
            *(float4*)(Bs + lkr * 128 + lc + 4 * q) =
                *(const float4*)(W + (size_t)(k0 + lkr) * 128 + lc + 4 * q);
        __syncthreads();
#pragma unroll
        for (int kk = 0; kk < 32; kk++) {
            float a[4], b[8];
            *(float4*)a       = *(float4*)(At + kk * 64 + row);
            *(float4*)(b)     = *(float4*)(Bs + kk * 128 + col);
            *(float4*)(b + 4) = *(float4*)(Bs + kk * 128 + col + 4);
#pragma unroll
            for (int i = 0; i < 4; i++)
#pragma unroll
                for (int j = 0; j < 8; j++) acc[i][j] += a[i] * b[j];
        }
        __syncthreads();
    }

    float bj[8];
    *(float4*)(bj)     = *(const float4*)(bias + col);
    *(float4*)(bj + 4) = *(const float4*)(bias + col + 4);
#pragma unroll
    for (int i = 0; i < 4; i++) {
        int gr = r0 + row + i;
        if (gr >= n) continue;
        float4 o0 = make_float4(acc[i][0] + bj[0], acc[i][1] + bj[1],
                                acc[i][2] + bj[2], acc[i][3] + bj[3]);
        float4 o1 = make_float4(acc[i][4] + bj[4], acc[i][5] + bj[5],
                                acc[i][6] + bj[6], acc[i][7] + bj[7]);
        *(float4*)(out + (size_t)gr * 128 + col)     = o0;
        *(float4*)(out + (size_t)gr * 128 + col + 4) = o1;
    }
}

// ---------------- launch ----------------
extern "C" void kernel_launch(void* const* d_in, const int* in_sizes, int n_in,
                              void* d_out, int out_size)
{
    const float* node_input = (const float*)d_in[0];
    // d_in[1] node_attr: unused
    const float* edge_attr  = (const float*)d_in[2];
    const float* edge_scal  = (const float*)d_in[3];
    const int*   edge_src   = (const int*)d_in[4];
    const int*   edge_dst   = (const int*)d_in[5];
    // d_in[6] batch: unused
    const float* w_src      = (const float*)d_in[7];
    const float* b_src      = (const float*)d_in[8];
    const float* w_dst      = (const float*)d_in[9];
    const float* fc_w1      = (const float*)d_in[10];
    const float* fc_b1      = (const float*)d_in[11];
    const float* fc_w2      = (const float*)d_in[12];
    const float* fc_b2      = (const float*)d_in[13];
    const float* fc_w3      = (const float*)d_in[14];
    const float* fc_b3      = (const float*)d_in[15];
    const float* w_sep      = (const float*)d_in[16];
    const float* b_sep      = (const float*)d_in[17];
    const float* alpha_dot  = (const float*)d_in[18];
    const float* w_proj     = (const float*)d_in[19];
    const float* b_proj     = (const float*)d_in[20];
    float* out = (float*)d_out;

    int N = in_sizes[0] / 128;
    int E = in_sizes[4];

    // dynamic smem opt-ins (idempotent; not stream ops, safe under capture)
    cudaFuncSetAttribute(edge_mlp_kernel,  cudaFuncAttributeMaxDynamicSharedMemorySize, 25344 * 4);
    cudaFuncSetAttribute(edge_attn_kernel, cudaFuncAttributeMaxDynamicSharedMemorySize, 10240 * 4);

    init_kernel<<<(N * 128 + 255) / 256, 256>>>(N);

    int nb = (N + 63) / 64;
    node_gemm_kernel<<<nb, 256>>>(node_input, w_src, b_src, N, 0);
    node_gemm_kernel<<<nb, 256>>>(node_input, w_dst, nullptr, N, 1);

    int eb = (E + 63) / 64;
    edge_mlp_kernel<<<eb, 128, 25344 * 4>>>(edge_scal, edge_attr, edge_src, edge_dst,
                                            fc_w1, fc_b1, fc_w2, fc_b2, fc_w3, fc_b3, E);
    edge_attn_kernel<<<eb, 256, 10240 * 4>>>(w_sep, b_sep, alpha_dot, edge_dst, E);

    scatter_kernel<<<(E + 7) / 8, 256>>>(edge_dst, E);

    out_gemm_kernel<<<nb, 256>>>(w_proj, b_proj, out, N);
}

// round 4
// speedup vs baseline: 1.2718x; 1.2718x over previous
#include <cuda_runtime.h>
#include <cuda_bf16.h>
#include <cstdint>
#include <math.h>

// ---------------- fixed problem geometry ----------------
#define MAXN 50000
#define MAXE 800000
// C=128, A_ALL=256, RAD_IN=32, FC1=FC2=64, H=8, AH=VH=16

// ---------------- scratch (device globals: no allocation allowed) ----------
__device__ __align__(16) float g_msg_src[(size_t)MAXN * 128];
__device__ __align__(16) float g_msg_dst[(size_t)MAXN * 128];
__device__ __align__(16) float g_m[(size_t)MAXE * 128];      // premultiplied message
__device__ __align__(16) float g_value[(size_t)MAXE * 128];  // per-head values
__device__ __align__(16) float g_score[(size_t)MAXE * 8];
__device__ __align__(16) float g_nmax[(size_t)MAXN * 8];
__device__ __align__(16) float g_nsum[(size_t)MAXN * 8];
__device__ __align__(16) float g_nacc[(size_t)MAXN * 128];

// ---------------- helpers ----------------
__device__ __forceinline__ uint32_t smem_u32(const void* p) {
    uint32_t a;
    asm("{ .reg .u64 t; cvta.to.shared.u64 t, %1; cvt.u32.u64 %0, t; }"
        : "=r"(a) : "l"(p));
    return a;
}

#define LDSM4(r, addr) \
    asm volatile("ldmatrix.sync.aligned.m8n8.x4.shared.b16 {%0,%1,%2,%3}, [%4];" \
        : "=r"((r)[0]), "=r"((r)[1]), "=r"((r)[2]), "=r"((r)[3]) : "r"(addr))

#define LDSM4T(r, addr) \
    asm volatile("ldmatrix.sync.aligned.m8n8.x4.trans.shared.b16 {%0,%1,%2,%3}, [%4];" \
        : "=r"((r)[0]), "=r"((r)[1]), "=r"((r)[2]), "=r"((r)[3]) : "r"(addr))

#define MMA16816(d, a, b0v, b1v) \
    asm volatile("mma.sync.aligned.m16n8k16.row.col.f32.bf16.bf16.f32 " \
        "{%0,%1,%2,%3}, {%4,%5,%6,%7}, {%8,%9}, {%0,%1,%2,%3};" \
        : "+f"((d)[0]), "+f"((d)[1]), "+f"((d)[2]), "+f"((d)[3]) \
        : "r"((a)[0]), "r"((a)[1]), "r"((a)[2]), "r"((a)[3]), "r"(b0v), "r"(b1v))

// float atomic max via int ordering trick (init = -inf)
__device__ __forceinline__ void atomicMaxFloat(float* addr, float v) {
    if (v >= 0.0f) atomicMax((int*)addr, __float_as_int(v));
    else           atomicMin((unsigned int*)addr, __float_as_uint(v));
}

__device__ __forceinline__ uint32_t pack2bf(float x, float y) {
    __nv_bfloat162 t = __floats2bfloat162_rn(x, y);
    return *(uint32_t*)&t;
}

// ---------------- K0: init segment buffers ----------------
__global__ void init_kernel(int n) {
    int i = blockIdx.x * blockDim.x + threadIdx.x;
    if (i < n * 128) g_nacc[i] = 0.0f;
    if (i < n * 8) {
        g_nmax[i] = __int_as_float(0xFF800000);
        g_nsum[i] = 0.0f;
    }
}

// ---------------- K1: node GEMM  out = X(128) @ W(128x128) [+bias] ----------
__global__ __launch_bounds__(256) void node_gemm_kernel(
    const float* __restrict__ X, const float* __restrict__ W,
    const float* __restrict__ bias, int n, int which)
{
    float* __restrict__ out = which ? g_msg_dst : g_msg_src;
    __shared__ float At[32 * 64];
    __shared__ float Bs[32 * 128];
    int tid = threadIdx.x;
    int r0 = blockIdx.x * 64;
    int cg = tid & 15, rg = tid >> 4;
    int col = cg * 8, row = rg * 4;

    float acc[4][8];
#pragma unroll
    for (int i = 0; i < 4; i++)
#pragma unroll
        for (int j = 0; j < 8; j++) acc[i][j] = 0.0f;

    int lm = tid >> 2, lk = (tid & 3) * 8;
    int lkr = tid >> 3, lc = (tid & 7) * 16;

    for (int k0 = 0; k0 < 128; k0 += 32) {
        float4 a0, a1;
        int gr = r0 + lm;
        if (gr < n) {
            a0 = *(const float4*)(X + (size_t)gr * 128 + k0 + lk);
            a1 = *(const float4*)(X + (size_t)gr * 128 + k0 + lk + 4);
        } else {
            a0 = make_float4(0.f, 0.f, 0.f, 0.f); a1 = a0;
        }
        At[(lk + 0) * 64 + lm] = a0.x; At[(lk + 1) * 64 + lm] = a0.y;
        At[(lk + 2) * 64 + lm] = a0.z; At[(lk + 3) * 64 + lm] = a0.w;
        At[(lk + 4) * 64 + lm] = a1.x; At[(lk + 5) * 64 + lm] = a1.y;
        At[(lk + 6) * 64 + lm] = a1.z; At[(lk + 7) * 64 + lm] = a1.w;
#pragma unroll
        for (int q = 0; q < 4; q++)
            *(float4*)(Bs + lkr * 128 + lc + 4 * q) =
                *(const float4*)(W + (size_t)(k0 + lkr) * 128 + lc + 4 * q);
        __syncthreads();
#pragma unroll
        for (int kk = 0; kk < 32; kk++) {
            float a[4], b[8];
            *(float4*)a       = *(float4*)(At + kk * 64 + row);
            *(float4*)(b)     = *(float4*)(Bs + kk * 128 + col);
            *(float4*)(b + 4) = *(float4*)(Bs + kk * 128 + col + 4);
#pragma unroll
            for (int i = 0; i < 4; i++)
#pragma unroll
                for (int j = 0; j < 8; j++) acc[i][j] += a[i] * b[j];
        }
        __syncthreads();
    }

    float bj[8];
    if (bias) {
        *(float4*)bj       = *(const float4*)(bias + col);
        *(float4*)(bj + 4) = *(const float4*)(bias + col + 4);
    } else {
#pragma unroll
        for (int j = 0; j < 8; j++) bj[j] = 0.0f;
    }
#pragma unroll
    for (int i = 0; i < 4; i++) {
        int gr = r0 + row + i;
        if (gr >= n) continue;
        float4 o0 = make_float4(acc[i][0] + bj[0], acc[i][1] + bj[1],
                                acc[i][2] + bj[2], acc[i][3] + bj[3]);
        float4 o1 = make_float4(acc[i][4] + bj[4], acc[i][5] + bj[5],
                                acc[i][6] + bj[6], acc[i][7] + bj[7]);
        *(float4*)(out + (size_t)gr * 128 + col)     = o0;
        *(float4*)(out + (size_t)gr * 128 + col + 4) = o1;
    }
}

// ---------------- K2: radial MLP + gather + premultiply -> g_m --------------
__global__ __launch_bounds__(128) void edge_mlp_kernel(
    const float* __restrict__ edge_scalars, const float* __restrict__ edge_attr,
    const int* __restrict__ edge_src, const int* __restrict__ edge_dst,
    const float* __restrict__ w1, const float* __restrict__ b1,
    const float* __restrict__ w2, const float* __restrict__ b2,
    const float* __restrict__ w3, const float* __restrict__ b3,
    int E)
{
    extern __shared__ float sm[];
    float* sW1  = sm;
    float* sB1  = sW1 + 2048;
    float* sW2  = sB1 + 64;
    float* sB2  = sW2 + 4096;
    float* sW3  = sB2 + 64;
    float* sB3  = sW3 + 8192;
    float* sXt  = sB3 + 128;
    float* sH1t = sXt + 2048;
    float* sH2t = sH1t + 4352;
    __shared__ int   sSrc[64];
    __shared__ int   sDst[64];
    __shared__ float sAttr[64];

    int tid = threadIdx.x;
    int e0 = blockIdx.x * 64;

    for (int i = tid * 4; i < 2048; i += 512) *(float4*)(sW1 + i) = *(const float4*)(w1 + i);
    for (int i = tid * 4; i < 4096; i += 512) *(float4*)(sW2 + i) = *(const float4*)(w2 + i);
    for (int i = tid * 4; i < 8192; i += 512) *(float4*)(sW3 + i) = *(const float4*)(w3 + i);
    if (tid < 64)  { sB1[tid] = b1[tid]; sB2[tid] = b2[tid]; }
    if (tid < 128) sB3[tid] = b3[tid];
    if (tid < 64) {
        int e = min(e0 + tid, E - 1);
        sSrc[tid] = edge_src[e];
        sDst[tid] = edge_dst[e];
        sAttr[tid] = edge_attr[e];
    }
    {
        int m = tid >> 1, kb = (tid & 1) * 16;
        int e = min(e0 + m, E - 1);
#pragma unroll
        for (int q = 0; q < 4; q++) {
            float4 v = *(const float4*)(edge_scalars + (size_t)e * 32 + kb + 4 * q);
            sXt[(kb + 4 * q + 0) * 64 + m] = v.x;
            sXt[(kb + 4 * q + 1) * 64 + m] = v.y;
            sXt[(kb + 4 * q + 2) * 64 + m] = v.z;
            sXt[(kb + 4 * q + 3) * 64 + m] = v.w;
        }
    }
    __syncthreads();

    int rg = tid >> 3, cg = tid & 7;
    int row = rg * 4;

    {
        int col = cg * 8;
        float acc[4][8];
#pragma unroll
        for (int i = 0; i < 4; i++)
#pragma unroll
            for (int j = 0; j < 8; j++) acc[i][j] = 0.0f;
#pragma unroll
        for (int k = 0; k < 32; k++) {
            float a[4], b[8];
            *(float4*)a       = *(float4*)(sXt + k * 64 + row);
            *(float4*)(b)     = *(float4*)(sW1 + k * 64 + col);
            *(float4*)(b + 4) = *(float4*)(sW1 + k * 64 + col + 4);
#pragma unroll
            for (int i = 0; i < 4; i++)
#pragma unroll
                for (int j = 0; j < 8; j++) acc[i][j] += a[i] * b[j];
        }
#pragma unroll
        for (int i = 0; i < 4; i++)
#pragma unroll
            for (int j = 0; j < 8; j++) {
                float x = acc[i][j] + sB1[col + j];
                x = x / (1.0f + __expf(-x));
                sH1t[(col + j) * 68 + (row + i)] = x;
            }
    }
    __syncthreads();

    {
        int col = cg * 8;
        float acc[4][8];
#pragma unroll
        for (int i = 0; i < 4; i++)
#pragma unroll
            for (int j = 0; j < 8; j++) acc[i][j] = 0.0f;
#pragma unroll
        for (int k = 0; k < 64; k++) {
            float a[4], b[8];
            *(float4*)a       = *(float4*)(sH1t + k * 68 + row);
            *(float4*)(b)     = *(float4*)(sW2 + k * 64 + col);
            *(float4*)(b + 4) = *(float4*)(sW2 + k * 64 + col + 4);
#pragma unroll
            for (int i = 0; i < 4; i++)
#pragma unroll
                for (int j = 0; j < 8; j++) acc[i][j] += a[i] * b[j];
        }
        __syncthreads();
#pragma unroll
        for (int i = 0; i < 4; i++)
#pragma unroll
            for (int j = 0; j < 8; j++) {
                float x = acc[i][j] + sB2[col + j];
                x = x / (1.0f + __expf(-x));
                sH2t[(col + j) * 68 + (row + i)] = x;
            }
    }
    __syncthreads();

    {
        int col = cg * 16;
        float acc[4][16];
#pragma unroll
        for (int i = 0; i < 4; i++)
#pragma unroll
            for (int j = 0; j < 16; j++) acc[i][j] = 0.0f;
#pragma unroll
        for (int k = 0; k < 64; k++) {
            float a[4], b[16];
            *(float4*)a        = *(float4*)(sH2t + k * 68 + row);
            *(float4*)(b)      = *(float4*)(sW3 + k * 128 + col);
            *(float4*)(b + 4)  = *(float4*)(sW3 + k * 128 + col + 4);
            *(float4*)(b + 8)  = *(float4*)(sW3 + k * 128 + col + 8);
            *(float4*)(b + 12) = *(float4*)(sW3 + k * 128 + col + 12);
#pragma unroll
            for (int i = 0; i < 4; i++)
#pragma unroll
                for (int j = 0; j < 16; j++) acc[i][j] += a[i] * b[j];
        }
#pragma unroll
        for (int i = 0; i < 4; i++) {
            int e = e0 + row + i;
            if (e >= E) continue;
            int src = sSrc[row + i], dstn = sDst[row + i];
            float at = sAttr[row + i];
#pragma unroll
            for (int q = 0; q < 4; q++) {
                float4 ms = *(const float4*)(g_msg_src + (size_t)src * 128 + col + 4 * q);
                float4 md = *(const float4*)(g_msg_dst + (size_t)dstn * 128 + col + 4 * q);
                float4 o;
                o.x = (ms.x + md.x) * at * (acc[i][4 * q + 0] + sB3[col + 4 * q + 0]);
                o.y = (ms.y + md.y) * at * (acc[i][4 * q + 1] + sB3[col + 4 * q + 1]);
                o.z = (ms.z + md.z) * at * (acc[i][4 * q + 2] + sB3[col + 4 * q + 2]);
                o.w = (ms.w + md.w) * at * (acc[i][4 * q + 3] + sB3[col + 4 * q + 3]);
                *(float4*)(g_m + (size_t)e * 128 + col + 4 * q) = o;
            }
        }
    }
}

// ---------------- K3: mma.sync bf16 w_sep GEMM + attention epilogue ---------
// Per CTA: 128 edges, D[128,256] = A[128,128] @ w_sep[128,256].
// 3-term error-compensated bf16 split: AhBh + AhBl + AlBh, fp32 accumulate.
// SMEM (dynamic, 196608 B):
//   [0,32K)      A_hi [m][k]  bf16, XOR-chunk swizzled
//   [32K,64K)    A_lo
//   [64K,128K)   B_hi [k][n]  bf16 (w_sep layout), XOR-chunk swizzled
//   [128K,192K)  B_lo
__global__ __launch_bounds__(512, 1) void edge_attn_mma(
    const float* __restrict__ w_sep, const float* __restrict__ b_sep,
    const float* __restrict__ alpha_dot, const int* __restrict__ edge_dst,
    int E)
{
    extern __shared__ char dynsm[];
    __shared__ float sBsep[256];
    __shared__ float sAD[128];

    const int tid = threadIdx.x;
    const int wid = tid >> 5, lane = tid & 31;
    const int e0 = blockIdx.x * 128;

    if (tid < 256) sBsep[tid] = b_sep[tid];
    if (tid < 128) sAD[tid] = alpha_dot[tid];

    const uint32_t sb = smem_u32(dynsm);
    const uint32_t Ahi = sb, Alo = sb + 32768, Bhi = sb + 65536, Blo = sb + 131072;

    // ---- stage B = w_sep [k][n] (coalesced read, swizzled store)
#pragma unroll 4
    for (int it = 0; it < 16; it++) {
        int idx = tid + 512 * it;            // 0..8191 : (k, n/4)
        int k = idx >> 6, n4 = (idx & 63) << 2;
        float4 v = *(const float4*)(w_sep + (size_t)k * 256 + n4);
        __nv_bfloat16 h0 = __float2bfloat16_rn(v.x), h1 = __float2bfloat16_rn(v.y);
        __nv_bfloat16 h2 = __float2bfloat16_rn(v.z), h3 = __float2bfloat16_rn(v.w);
        uint32_t hiA = pack2bf(v.x, v.y), hiB = pack2bf(v.z, v.w);
        uint32_t loA = pack2bf(v.x - __bfloat162float(h0), v.y - __bfloat162float(h1));
        uint32_t loB = pack2bf(v.z - __bfloat162float(h2), v.w - __bfloat162float(h3));
        uint32_t addr = (uint32_t)k * 512 + ((uint32_t)((n4 >> 3) ^ (k & 7)) << 4) + (n4 & 7) * 2;
        asm volatile("st.shared.v2.b32 [%0], {%1,%2};" :: "r"(Bhi + addr), "r"(hiA), "r"(hiB));
        asm volatile("st.shared.v2.b32 [%0], {%1,%2};" :: "r"(Blo + addr), "r"(loA), "r"(loB));
    }

    // ---- stage A = g_m tile [m][k]
#pragma unroll 4
    for (int it = 0; it < 8; it++) {
        int idx = tid + 512 * it;            // 0..4095 : (m, k/4)
        int m = idx >> 5, k4 = (idx & 31) << 2;
        int e = e0 + m;
        float4 v = make_float4(0.f, 0.f, 0.f, 0.f);
        if (e < E) v = *(const float4*)(g_m + (size_t)e * 128 + k4);
        __nv_bfloat16 h0 = __float2bfloat16_rn(v.x), h1 = __float2bfloat16_rn(v.y);
        __nv_bfloat16 h2 = __float2bfloat16_rn(v.z), h3 = __float2bfloat16_rn(v.w);
        uint32_t hiA = pack2bf(v.x, v.y), hiB = pack2bf(v.z, v.w);
        uint32_t loA = pack2bf(v.x - __bfloat162float(h0), v.y - __bfloat162float(h1));
        uint32_t loB = pack2bf(v.z - __bfloat162float(h2), v.w - __bfloat162float(h3));
        uint32_t addr = (uint32_t)m * 256 + ((uint32_t)((k4 >> 3) ^ (m & 7)) << 4) + (k4 & 7) * 2;
        asm volatile("st.shared.v2.b32 [%0], {%1,%2};" :: "r"(Ahi + addr), "r"(hiA), "r"(hiB));
        asm volatile("st.shared.v2.b32 [%0], {%1,%2};" :: "r"(Alo + addr), "r"(loA), "r"(loB));
    }
    __syncthreads();

    // ---- warp tiles: 4 M x 4 N
    const int mi = wid & 3, ni = wid >> 2;
    const int mrow0 = mi * 32, ncol0 = ni * 64;

    float d[2][8][4];
#pragma unroll
    for (int a = 0; a < 2; a++)
#pragma unroll
        for (int b = 0; b < 8; b++)
#pragma unroll
            for (int c = 0; c < 4; c++) d[a][b][c] = 0.0f;

    const int mtx = lane >> 3, rin = lane & 7;

#pragma unroll
    for (int t = 0; t < 3; t++) {
        const uint32_t Ab = (t == 2) ? Alo : Ahi;
        const uint32_t Bb = (t == 1) ? Blo : Bhi;
#pragma unroll
        for (int ks = 0; ks < 8; ks++) {
            uint32_t a[2][4];
#pragma unroll
            for (int mt = 0; mt < 2; mt++) {
                int m = mrow0 + mt * 16 + (mtx & 1) * 8 + rin;
                int kchunk = ks * 2 + (mtx >> 1);
                uint32_t ad = Ab + (uint32_t)m * 256 + ((uint32_t)(kchunk ^ (m & 7)) << 4);
                LDSM4(a[mt], ad);
            }
            uint32_t b[4][4];
#pragma unroll
            for (int ntp = 0; ntp < 4; ntp++) {
                int k = ks * 16 + (mtx & 1) * 8 + rin;
                int nchunk = (ncol0 >> 3) + ntp * 2 + (mtx >> 1);
                uint32_t bd = Bb + (uint32_t)k * 512 + ((uint32_t)(nchunk ^ (k & 7)) << 4);
                LDSM4T(b[ntp], bd);
            }
#pragma unroll
            for (int mt = 0; mt < 2; mt++)
#pragma unroll
                for (int nt = 0; nt < 8; nt++)
                    MMA16816(d[mt][nt], a[mt], b[nt >> 1][(nt & 1) * 2], b[nt >> 1][(nt & 1) * 2 + 1]);
        }
    }

    // ---- epilogue (register accumulators) ----
    const int lr = lane >> 2;          // row within 8
    const int lc = lane & 3;           // col pair group
#pragma unroll
    for (int hh = 0; hh < 2; hh++) {
        const int h = ni * 2 + hh;
#pragma unroll
        for (int mt = 0; mt < 2; mt++) {
            const int ebase = e0 + mrow0 + mt * 16 + lr;
            // score from alpha tiles (nt = hh*4 + {0,1})
            float p0 = 0.0f, p1 = 0.0f;
#pragma unroll
            for (int q = 0; q < 2; q++) {
                const int nt = hh * 4 + q;
                const int colb = ncol0 + nt * 8 + lc * 2;
                const int jb = q * 8 + lc * 2;
                const float bb0 = sBsep[colb], bb1 = sBsep[colb + 1];
                const float w0 = sAD[h * 16 + jb], w1 = sAD[h * 16 + jb + 1];
                float x, sg;
                x = d[mt][nt][0] + bb0; sg = 1.0f / (1.0f + __expf(-x)); p0 += x * (0.2f + 0.8f * sg) * w0;
                x = d[mt][nt][1] + bb1; sg = 1.0f / (1.0f + __expf(-x)); p0 += x * (0.2f + 0.8f * sg) * w1;
                x = d[mt][nt][2] + bb0; sg = 1.0f / (1.0f + __expf(-x)); p1 += x * (0.2f + 0.8f * sg) * w0;
                x = d[mt][nt][3] + bb1; sg = 1.0f / (1.0f + __expf(-x)); p1 += x * (0.2f + 0.8f * sg) * w1;
            }
            p0 += __shfl_xor_sync(0xffffffffu, p0, 1);
            p0 += __shfl_xor_sync(0xffffffffu, p0, 2);
            p1 += __shfl_xor_sync(0xffffffffu, p1, 1);
            p1 += __shfl_xor_sync(0xffffffffu, p1, 2);
            if (lc == 0) {
                if (ebase < E) {
                    g_score[(size_t)ebase * 8 + h] = p0;
                    atomicMaxFloat(&g_nmax[(size_t)edge_dst[ebase] * 8 + h], p0);
                }
                if (ebase + 8 < E) {
                    g_score[(size_t)(ebase + 8) * 8 + h] = p1;
                    atomicMaxFloat(&g_nmax[(size_t)edge_dst[ebase + 8] * 8 + h], p1);
                }
            }
            // values (nt = hh*4 + {2,3}) -> g_value[e][h*16 + 0..15]
#pragma unroll
            for (int q = 0; q < 2; q++) {
                const int nt = hh * 4 + 2 + q;
                const int colb = ncol0 + nt * 8 + lc * 2;
                const int vidx = q * 8 + lc * 2;
                const float bb0 = sBsep[colb], bb1 = sBsep[colb + 1];
                if (ebase < E)
                    *(float2*)(g_value + (size_t)ebase * 128 + h * 16 + vidx) =
                        make_float2(d[mt][nt][0] + bb0, d[mt][nt][1] + bb1);
                if (ebase + 8 < E)
                    *(float2*)(g_value + (size_t)(ebase + 8) * 128 + h * 16 + vidx) =
                        make_float2(d[mt][nt][2] + bb0, d[mt][nt][3] + bb1);
            }
        }
    }
}

// ---------------- K4: exp + segment sums (one warp per edge) ----------------
__global__ __launch_bounds__(256) void scatter_kernel(const int* __restrict__ edge_dst, int E)
{
    int gw = (blockIdx.x * blockDim.x + threadIdx.x) >> 5;
    int lane = threadIdx.x & 31;
    if (gw >= E) return;
    int d = edge_dst[gw];
    int h = lane >> 2;
    float s = g_score[(size_t)gw * 8 + h];
    float mx = g_nmax[(size_t)d * 8 + h];
    float w = __expf(s - mx);
    if ((lane & 3) == 0) atomicAdd(&g_nsum[(size_t)d * 8 + h], w);
    float4 v = *(const float4*)(g_value + (size_t)gw * 128 + lane * 4);
    float* p = g_nacc + (size_t)d * 128 + lane * 4;
    atomicAdd(p + 0, v.x * w);
    atomicAdd(p + 1, v.y * w);
    atomicAdd(p + 2, v.z * w);
    atomicAdd(p + 3, v.w * w);
}

// ---------------- K5: out = (nacc / (nsum+eps)) @ w_proj + b_proj -----------
__global__ __launch_bounds__(256) void out_gemm_kernel(
    const float* __restrict__ W, const float* __restrict__ bias,
    float* __restrict__ out, int n)
{
    __shared__ float At[32 * 64];
    __shared__ float Bs[32 * 128];
    int tid = threadIdx.x;
    int r0 = blockIdx.x * 64;
    int cg = tid & 15, rg = tid >> 4;
    int col = cg * 8, row = rg * 4;

    float acc[4][8];
#pragma unroll
    for (int i = 0; i < 4; i++)
#pragma unroll
        for (int j = 0; j < 8; j++) acc[i][j] = 0.0f;

    int lm = tid >> 2, lk = (tid & 3) * 8;
    int lkr = tid >> 3, lc = (tid & 7) * 16;

    for (int k0 = 0; k0 < 128; k0 += 32) {
        float4 a0, a1;
        int gr = r0 + lm;
        if (gr < n) {
            a0 = *(const float4*)(g_nacc + (size_t)gr * 128 + k0 + lk);
            a1 = *(const float4*)(g_nacc + (size_t)gr * 128 + k0 + lk + 4);
            int hh = (k0 + lk) >> 4;
            float inv = 1.0f / (g_nsum[(size_t)gr * 8 + hh] + 1e-16f);
            a0.x *= inv; a0.y *= inv; a0.z *= inv; a0.w *= inv;
            a1.x *= inv; a1.y *= inv; a1.z *= inv; a1.w *= inv;
        } else {
            a0 = make_float4(0.f, 0.f, 0.f, 0.f); a1 = a0;
        }
        At[(lk + 0) * 64 + lm] = a0.x; At[(lk + 1) * 64 + lm] = a0.y;
        At[(lk + 2) * 64 + lm] = a0.z; At[(lk + 3) * 64 + lm] = a0.w;
        At[(lk + 4) * 64 + lm] = a1.x; At[(lk + 5) * 64 + lm] = a1.y;
        At[(lk + 6) * 64 + lm] = a1.z; At[(lk + 7) * 64 + lm] = a1.w;
#pragma unroll
        for (int q = 0; q < 4; q++)
            *(float4*)(Bs + lkr * 128 + lc + 4 * q) =
                *(const float4*)(W + (size_t)(k0 + lkr) * 128 + lc + 4 * q);
        __syncthreads();
#pragma unroll
        for (int kk = 0; kk < 32; kk++) {
            float a[4], b[8];
            *(float4*)a       = *(float4*)(At + kk * 64 + row);
            *(float4*)(b)     = *(float4*)(Bs + kk * 128 + col);
            *(float4*)(b + 4) = *(float4*)(Bs + kk * 128 + col + 4);
#pragma unroll
            for (int i = 0; i < 4; i++)
#pragma unroll
                for (int j = 0; j < 8; j++) acc[i][j] += a[i] * b[j];
        }
        __syncthreads();
    }

    float bj[8];
    *(float4*)(bj)     = *(const float4*)(bias + col);
    *(float4*)(bj + 4) = *(const float4*)(bias + col + 4);
#pragma unroll
    for (int i = 0; i < 4; i++) {
        int gr = r0 + row + i;
        if (gr >= n) continue;
        float4 o0 = make_float4(acc[i][0] + bj[0], acc[i][1] + bj[1],
                                acc[i][2] + bj[2], acc[i][3] + bj[3]);
        float4 o1 = make_float4(acc[i][4] + bj[4], acc[i][5] + bj[5],
                                acc[i][6] + bj[6], acc[i][7] + bj[7]);
        *(float4*)(out + (size_t)gr * 128 + col)     = o0;
        *(float4*)(out + (size_t)gr * 128 + col + 4) = o1;
    }
}

// ---------------- launch ----------------
extern "C" void kernel_launch(void* const* d_in, const int* in_sizes, int n_in,
                              void* d_out, int out_size)
{
    const float* node_input = (const float*)d_in[0];
    const float* edge_attr  = (const float*)d_in[2];
    const float* edge_scal  = (const float*)d_in[3];
    const int*   edge_src   = (const int*)d_in[4];
    const int*   edge_dst   = (const int*)d_in[5];
    const float* w_src      = (const float*)d_in[7];
    const float* b_src      = (const float*)d_in[8];
    const float* w_dst      = (const float*)d_in[9];
    const float* fc_w1      = (const float*)d_in[10];
    const float* fc_b1      = (const float*)d_in[11];
    const float* fc_w2      = (const float*)d_in[12];
    const float* fc_b2      = (const float*)d_in[13];
    const float* fc_w3      = (const float*)d_in[14];
    const float* fc_b3      = (const float*)d_in[15];
    const float* w_sep      = (const float*)d_in[16];
    const float* b_sep      = (const float*)d_in[17];
    const float* alpha_dot  = (const float*)d_in[18];
    const float* w_proj     = (const float*)d_in[19];
    const float* b_proj     = (const float*)d_in[20];
    float* out = (float*)d_out;

    int N = in_sizes[0] / 128;
    int E = in_sizes[4];

    cudaFuncSetAttribute(edge_mlp_kernel, cudaFuncAttributeMaxDynamicSharedMemorySize, 25344 * 4);
    cudaFuncSetAttribute(edge_attn_mma,   cudaFuncAttributeMaxDynamicSharedMemorySize, 196608);

    init_kernel<<<(N * 128 + 255) / 256, 256>>>(N);

    int nb = (N + 63) / 64;
    node_gemm_kernel<<<nb, 256>>>(node_input, w_src, b_src, N, 0);
    node_gemm_kernel<<<nb, 256>>>(node_input, w_dst, nullptr, N, 1);

    int eb = (E + 63) / 64;
    edge_mlp_kernel<<<eb, 128, 25344 * 4>>>(edge_scal, edge_attr, edge_src, edge_dst,
                                            fc_w1, fc_b1, fc_w2, fc_b2, fc_w3, fc_b3, E);

    int tb = (E + 127) / 128;
    edge_attn_mma<<<tb, 512, 196608>>>(w_sep, b_sep, alpha_dot, edge_dst, E);

    scatter_kernel<<<(E + 7) / 8, 256>>>(edge_dst, E);

    out_gemm_kernel<<<nb, 256>>>(w_proj, b_proj, out, N);
}

// round 5
// speedup vs baseline: 2.2603x; 1.7772x over previous
#include <cuda_runtime.h>
#include <cuda_bf16.h>
#include <cstdint>
#include <math.h>

// ---------------- fixed problem geometry ----------------
#define MAXN 50000
#define MAXE 800000
// C=128, A_ALL=256, RAD_IN=32, FC1=FC2=64, H=8, AH=VH=16

// ---------------- scratch ----------------
__device__ __align__(16) float g_msg_src[(size_t)MAXN * 128];
__device__ __align__(16) float g_msg_dst[(size_t)MAXN * 128];
__device__ __align__(16) float g_value[(size_t)MAXE * 128];
__device__ __align__(16) float g_score[(size_t)MAXE * 8];
__device__ __align__(16) float g_nmax[(size_t)MAXN * 8];
__device__ __align__(16) float g_nsum[(size_t)MAXN * 8];
__device__ __align__(16) float g_nacc[(size_t)MAXN * 128];

// ---------------- helpers ----------------
__device__ __forceinline__ uint32_t smem_u32(const void* p) {
    uint32_t a;
    asm("{ .reg .u64 t; cvta.to.shared.u64 t, %1; cvt.u32.u64 %0, t; }"
        : "=r"(a) : "l"(p));
    return a;
}

#define LDSM4(r, addr) \
    asm volatile("ldmatrix.sync.aligned.m8n8.x4.shared.b16 {%0,%1,%2,%3}, [%4];" \
        : "=r"((r)[0]), "=r"((r)[1]), "=r"((r)[2]), "=r"((r)[3]) : "r"(addr))

#define LDSM4T(r, addr) \
    asm volatile("ldmatrix.sync.aligned.m8n8.x4.trans.shared.b16 {%0,%1,%2,%3}, [%4];" \
        : "=r"((r)[0]), "=r"((r)[1]), "=r"((r)[2]), "=r"((r)[3]) : "r"(addr))

#define MMA16816(d, a, b0v, b1v) \
    asm volatile("mma.sync.aligned.m16n8k16.row.col.f32.bf16.bf16.f32 " \
        "{%0,%1,%2,%3}, {%4,%5,%6,%7}, {%8,%9}, {%0,%1,%2,%3};" \
        : "+f"((d)[0]), "+f"((d)[1]), "+f"((d)[2]), "+f"((d)[3]) \
        : "r"((a)[0]), "r"((a)[1]), "r"((a)[2]), "r"((a)[3]), "r"(b0v), "r"(b1v))

#define STS32(addr, v) \
    asm volatile("st.shared.b32 [%0], %1;" :: "r"(addr), "r"(v))
#define STS64(addr, v0, v1) \
    asm volatile("st.shared.v2.b32 [%0], {%1,%2};" :: "r"(addr), "r"(v0), "r"(v1))

__device__ __forceinline__ void atomicMaxFloat(float* addr, float v) {
    if (v >= 0.0f) atomicMax((int*)addr, __float_as_int(v));
    else           atomicMin((unsigned int*)addr, __float_as_uint(v));
}

__device__ __forceinline__ uint32_t pack2bf(float x, float y) {
    __nv_bfloat162 t = __floats2bfloat162_rn(x, y);
    return *(uint32_t*)&t;
}
// split (x,y) into hi-bf16x2 and residual lo-bf16x2
__device__ __forceinline__ void split2(float x, float y, uint32_t& hi, uint32_t& lo) {
    __nv_bfloat16 h0 = __float2bfloat16_rn(x), h1 = __float2bfloat16_rn(y);
    hi = (uint32_t)__bfloat16_as_ushort(h0) | ((uint32_t)__bfloat16_as_ushort(h1) << 16);
    lo = pack2bf(x - __bfloat162float(h0), y - __bfloat162float(h1));
}
__device__ __forceinline__ void split4(float4 v, uint32_t& hA, uint32_t& hB,
                                       uint32_t& lA, uint32_t& lB) {
    split2(v.x, v.y, hA, lA);
    split2(v.z, v.w, hB, lB);
}
__device__ __forceinline__ float silu(float x) {
    return x / (1.0f + __expf(-x));
}

// ---------------- K0: init segment buffers ----------------
__global__ void init_kernel(int n) {
    int i = blockIdx.x * blockDim.x + threadIdx.x;
    if (i < n * 128) g_nacc[i] = 0.0f;
    if (i < n * 8) {
        g_nmax[i] = __int_as_float(0xFF800000);
        g_nsum[i] = 0.0f;
    }
}

// ---------------- K1: node GEMM  out = X(128) @ W(128x128) [+bias] ----------
__global__ __launch_bounds__(256) void node_gemm_kernel(
    const float* __restrict__ X, const float* __restrict__ W,
    const float* __restrict__ bias, int n, int which)
{
    float* __restrict__ out = which ? g_msg_dst : g_msg_src;
    __shared__ float At[32 * 64];
    __shared__ float Bs[32 * 128];
    int tid = threadIdx.x;
    int r0 = blockIdx.x * 64;
    int cg = tid & 15, rg = tid >> 4;
    int col = cg * 8, row = rg * 4;

    float acc[4][8];
#pragma unroll
    for (int i = 0; i < 4; i++)
#pragma unroll
        for (int j = 0; j < 8; j++) acc[i][j] = 0.0f;

    int lm = tid >> 2, lk = (tid & 3) * 8;
    int lkr = tid >> 3, lc = (tid & 7) * 16;

    for (int k0 = 0; k0 < 128; k0 += 32) {
        float4 a0, a1;
        int gr = r0 + lm;
        if (gr < n) {
            a0 = *(const float4*)(X + (size_t)gr * 128 + k0 + lk);
            a1 = *(const float4*)(X + (size_t)gr * 128 + k0 + lk + 4);
        } else {
            a0 = make_float4(0.f, 0.f, 0.f, 0.f); a1 = a0;
        }
        At[(lk + 0) * 64 + lm] = a0.x; At[(lk + 1) * 64 + lm] = a0.y;
        At[(lk + 2) * 64 + lm] = a0.z; At[(lk + 3) * 64 + lm] = a0.w;
        At[(lk + 4) * 64 + lm] = a1.x; At[(lk + 5) * 64 + lm] = a1.y;
        At[(lk + 6) * 64 + lm] = a1.z; At[(lk + 7) * 64 + lm] = a1.w;
#pragma unroll
        for (int q = 0; q < 4; q++)
            *(float4*)(Bs + lkr * 128 + lc + 4 * q) =
                *(const float4*)(W + (size_t)(k0 + lkr) * 128 + lc + 4 * q);
        __syncthreads();
#pragma unroll
        for (int kk = 0; kk < 32; kk++) {
            float a[4], b[8];
            *(float4*)a       = *(float4*)(At + kk * 64 + row);
            *(float4*)(b)     = *(float4*)(Bs + kk * 128 + col);
            *(float4*)(b + 4) = *(float4*)(Bs + kk * 128 + col + 4);
#pragma unroll
            for (int i = 0; i < 4; i++)
#pragma unroll
                for (int j = 0; j < 8; j++) acc[i][j] += a[i] * b[j];
        }
        __syncthreads();
    }

    float bj[8];
    if (bias) {
        *(float4*)bj       = *(const float4*)(bias + col);
        *(float4*)(bj + 4) = *(const float4*)(bias + col + 4);
    } else {
#pragma unroll
        for (int j = 0; j < 8; j++) bj[j] = 0.0f;
    }
#pragma unroll
    for (int i = 0; i < 4; i++) {
        int gr = r0 + row + i;
        if (gr >= n) continue;
        float4 o0 = make_float4(acc[i][0] + bj[0], acc[i][1] + bj[1],
                                acc[i][2] + bj[2], acc[i][3] + bj[3]);
        float4 o1 = make_float4(acc[i][4] + bj[4], acc[i][5] + bj[5],
                                acc[i][6] + bj[6], acc[i][7] + bj[7]);
        *(float4*)(out + (size_t)gr * 128 + col)     = o0;
        *(float4*)(out + (size_t)gr * 128 + col + 4) = o1;
    }
}

// ============================================================================
// K23: FUSED radial-MLP + gather + w_sep GEMM + attention epilogue
// 128 edges per CTA, 512 threads (16 warps). All GEMMs on HMMA (mma.sync bf16)
// with 3-term error-compensated split (AhBh + AhBl + AlBh, fp32 accumulate).
//
// Dynamic SMEM (196608 B), phase-aliased:
//  phase2:  A_hi[0,32K) A_lo[32K,64K) B_hi[64K,128K) B_lo[128K,192K)
//  phase1:  W3 hi/lo  [0,32K)      | H1 hi/lo [32K,64K)
//           X  hi/lo  [64K,96K)    | W1 hi/lo [96K,104K)
//           W2 hi/lo  [104K,120K)  | H2 hi/lo [120K,152K)
//  All [m][k]/[k][n] bf16 images use 16B-chunk XOR swizzle: chunk ^= (row&7).
// ============================================================================
__global__ __launch_bounds__(512, 1) void fused_edge_kernel(
    const float* __restrict__ edge_scalars, const float* __restrict__ edge_attr,
    const int* __restrict__ edge_src, const int* __restrict__ edge_dst,
    const float* __restrict__ w1, const float* __restrict__ b1,
    const float* __restrict__ w2, const float* __restrict__ b2,
    const float* __restrict__ w3, const float* __restrict__ b3,
    const float* __restrict__ w_sep, const float* __restrict__ b_sep,
    const float* __restrict__ alpha_dot, int E)
{
    extern __shared__ char dynsm[];
    __shared__ float sB1[64], sB2[64], sB3[128];
    __shared__ float sBsep[256], sAD[128];
    __shared__ int   sSrc[128], sDst[128];
    __shared__ float sAttr[128];

    const int tid = threadIdx.x;
    const int wid = tid >> 5, lane = tid & 31;
    const int e0 = blockIdx.x * 128;
    const int mtx = lane >> 3, rin = lane & 7;
    const int lr = lane >> 2, lc = lane & 3;

    const uint32_t sb = smem_u32(dynsm);
    // phase2 regions
    const uint32_t Ahi = sb, Alo = sb + 32768, Bhi = sb + 65536, Blo = sb + 131072;
    // phase1 regions
    const uint32_t W3hi = sb,          W3lo = sb + 16384;
    const uint32_t H1hi = sb + 32768,  H1lo = sb + 49152;
    const uint32_t Xhi  = sb + 65536,  Xlo  = sb + 81920;
    const uint32_t W1hi = sb + 98304,  W1lo = sb + 102400;
    const uint32_t W2hi = sb + 106496, W2lo = sb + 114688;
    const uint32_t H2hi = sb + 122880, H2lo = sb + 139264;

    // ---------------- stage phase-1 inputs ----------------
    if (tid < 64)  { sB1[tid] = b1[tid]; sB2[tid] = b2[tid]; }
    if (tid < 128) { sB3[tid] = b3[tid]; sAD[tid] = alpha_dot[tid]; }
    if (tid < 256) sBsep[tid] = b_sep[tid];
    if (tid < 128) {
        int e = min(e0 + tid, E - 1);
        sSrc[tid] = edge_src[e];
        sDst[tid] = edge_dst[e];
        sAttr[tid] = (e0 + tid < E) ? edge_attr[e] : 0.0f;
    }
    // X: 128 x 32 fp32 (1024 float4), padded rows 128B
    {
#pragma unroll
        for (int it = 0; it < 2; it++) {
            int i = tid + 512 * it;
            int m = i >> 3, k4 = (i & 7) << 2;
            int e = min(e0 + m, E - 1);
            float4 v = *(const float4*)(edge_scalars + (size_t)e * 32 + k4);
            uint32_t hA, hB, lA, lB; split4(v, hA, hB, lA, lB);
            uint32_t addr = (uint32_t)m * 128 + ((uint32_t)(((k4 >> 3) ^ (m & 7))) << 4) + (k4 & 7) * 2;
            STS64(Xhi + addr, hA, hB);
            STS64(Xlo + addr, lA, lB);
        }
    }
    // W1: 32x64 (512 float4)
    if (tid < 512) {
        int k = tid >> 4, n4 = (tid & 15) << 2;
        float4 v = *(const float4*)(w1 + (size_t)k * 64 + n4);
        uint32_t hA, hB, lA, lB; split4(v, hA, hB, lA, lB);
        uint32_t addr = (uint32_t)k * 128 + ((uint32_t)(((n4 >> 3) ^ (k & 7))) << 4) + (n4 & 7) * 2;
        STS64(W1hi + addr, hA, hB);
        STS64(W1lo + addr, lA, lB);
    }
    // W2: 64x64 (1024 float4)
    {
#pragma unroll
        for (int it = 0; it < 2; it++) {
            int i = tid + 512 * it;
            int k = i >> 4, n4 = (i & 15) << 2;
            float4 v = *(const float4*)(w2 + (size_t)k * 64 + n4);
            uint32_t hA, hB, lA, lB; split4(v, hA, hB, lA, lB);
            uint32_t addr = (uint32_t)k * 128 + ((uint32_t)(((n4 >> 3) ^ (k & 7))) << 4) + (n4 & 7) * 2;
            STS64(W2hi + addr, hA, hB);
            STS64(W2lo + addr, lA, lB);
        }
    }
    // W3: 64x128 (2048 float4), rows 256B
    {
#pragma unroll
        for (int it = 0; it < 4; it++) {
            int i = tid + 512 * it;
            int k = i >> 5, n4 = (i & 31) << 2;
            float4 v = *(const float4*)(w3 + (size_t)k * 128 + n4);
            uint32_t hA, hB, lA, lB; split4(v, hA, hB, lA, lB);
            uint32_t addr = (uint32_t)k * 256 + ((uint32_t)(((n4 >> 3) ^ (k & 7))) << 4) + (n4 & 7) * 2;
            STS64(W3hi + addr, hA, hB);
            STS64(W3lo + addr, lA, lB);
        }
    }
    __syncthreads();

    // warp tile for MLP: 8 M-tiles x 2 N-tiles
    const int mi1 = wid & 7, ni1 = wid >> 3;
    const int mr = mi1 * 16;

    // ---------------- layer1: H1 = silu(X @ W1 + b1)  [128x64, K=32] --------
    {
        const int nc = ni1 * 32;
        float acc[4][4];
#pragma unroll
        for (int i = 0; i < 4; i++)
#pragma unroll
            for (int j = 0; j < 4; j++) acc[i][j] = 0.0f;
#pragma unroll
        for (int t = 0; t < 3; t++) {
            const uint32_t Ab = (t == 2) ? Xlo : Xhi;
            const uint32_t Bb = (t == 1) ? W1lo : W1hi;
#pragma unroll
            for (int ks = 0; ks < 2; ks++) {
                uint32_t a[4];
                int m = mr + (mtx & 1) * 8 + rin;
                int kc = ks * 2 + (mtx >> 1);
                LDSM4(a, Ab + (uint32_t)m * 128 + ((uint32_t)(kc ^ (m & 7)) << 4));
                uint32_t b[2][4];
#pragma unroll
                for (int ntp = 0; ntp < 2; ntp++) {
                    int k = ks * 16 + (mtx & 1) * 8 + rin;
                    int nch = (nc >> 3) + ntp * 2 + (mtx >> 1);
                    LDSM4T(b[ntp], Bb + (uint32_t)k * 128 + ((uint32_t)(nch ^ (k & 7)) << 4));
                }
#pragma unroll
                for (int nt = 0; nt < 4; nt++)
                    MMA16816(acc[nt], a, b[nt >> 1][(nt & 1) * 2], b[nt >> 1][(nt & 1) * 2 + 1]);
            }
        }
        // silu + store H1 hi/lo
#pragma unroll
        for (int nt = 0; nt < 4; nt++) {
            int col = nc + nt * 8 + lc * 2;
            float s0 = silu(acc[nt][0] + sB1[col]);
            float s1 = silu(acc[nt][1] + sB1[col + 1]);
            float s2 = silu(acc[nt][2] + sB1[col]);
            float s3 = silu(acc[nt][3] + sB1[col + 1]);
            int r0 = mr + lr, r1 = r0 + 8;
            uint32_t hi, lo;
            uint32_t ad0 = (uint32_t)r0 * 128 + ((uint32_t)((col >> 3) ^ (r0 & 7)) << 4) + (col & 7) * 2;
            split2(s0, s1, hi, lo); STS32(H1hi + ad0, hi); STS32(H1lo + ad0, lo);
            uint32_t ad1 = (uint32_t)r1 * 128 + ((uint32_t)((col >> 3) ^ (r1 & 7)) << 4) + (col & 7) * 2;
            split2(s2, s3, hi, lo); STS32(H1hi + ad1, hi); STS32(H1lo + ad1, lo);
        }
    }
    __syncthreads();

    // ---------------- layer2: H2 = silu(H1 @ W2 + b2)  [128x64, K=64] -------
    {
        const int nc = ni1 * 32;
        float acc[4][4];
#pragma unroll
        for (int i = 0; i < 4; i++)
#pragma unroll
            for (int j = 0; j < 4; j++) acc[i][j] = 0.0f;
#pragma unroll
        for (int t = 0; t < 3; t++) {
            const uint32_t Ab = (t == 2) ? H1lo : H1hi;
            const uint32_t Bb = (t == 1) ? W2lo : W2hi;
#pragma unroll
            for (int ks = 0; ks < 4; ks++) {
                uint32_t a[4];
                int m = mr + (mtx & 1) * 8 + rin;
                int kc = ks * 2 + (mtx >> 1);
                LDSM4(a, Ab + (uint32_t)m * 128 + ((uint32_t)(kc ^ (m & 7)) << 4));
                uint32_t b[2][4];
#pragma unroll
                for (int ntp = 0; ntp < 2; ntp++) {
                    int k = ks * 16 + (mtx & 1) * 8 + rin;
                    int nch = (nc >> 3) + ntp * 2 + (mtx >> 1);
                    LDSM4T(b[ntp], Bb + (uint32_t)k * 128 + ((uint32_t)(nch ^ (k & 7)) << 4));
                }
#pragma unroll
                for (int nt = 0; nt < 4; nt++)
                    MMA16816(acc[nt], a, b[nt >> 1][(nt & 1) * 2], b[nt >> 1][(nt & 1) * 2 + 1]);
            }
        }
        __syncthreads();   // H1 reads done everywhere before H2 writes? (H1 and H2 disjoint; sync orders H2 stores after all reads of H2's region? H2 region only written here) -- keep for inter-warp layer ordering
#pragma unroll
        for (int nt = 0; nt < 4; nt++) {
            int col = nc + nt * 8 + lc * 2;
            float s0 = silu(acc[nt][0] + sB2[col]);
            float s1 = silu(acc[nt][1] + sB2[col + 1]);
            float s2 = silu(acc[nt][2] + sB2[col]);
            float s3 = silu(acc[nt][3] + sB2[col + 1]);
            int r0 = mr + lr, r1 = r0 + 8;
            uint32_t hi, lo;
            uint32_t ad0 = (uint32_t)r0 * 128 + ((uint32_t)((col >> 3) ^ (r0 & 7)) << 4) + (col & 7) * 2;
            split2(s0, s1, hi, lo); STS32(H2hi + ad0, hi); STS32(H2lo + ad0, lo);
            uint32_t ad1 = (uint32_t)r1 * 128 + ((uint32_t)((col >> 3) ^ (r1 & 7)) << 4) + (col & 7) * 2;
            split2(s2, s3, hi, lo); STS32(H2hi + ad1, hi); STS32(H2lo + ad1, lo);
        }
    }
    __syncthreads();

    // ---------------- layer3: rad = H2 @ W3 + b3  [128x128, K=64] (regs) ----
    float acc3[8][4];
#pragma unroll
    for (int i = 0; i < 8; i++)
#pragma unroll
        for (int j = 0; j < 4; j++) acc3[i][j] = 0.0f;
    {
        const int nc = ni1 * 64;
#pragma unroll
        for (int t = 0; t < 3; t++) {
            const uint32_t Ab = (t == 2) ? H2lo : H2hi;
            const uint32_t Bb = (t == 1) ? W3lo : W3hi;
#pragma unroll
            for (int ks = 0; ks < 4; ks++) {
                uint32_t a[4];
                int m = mr + (mtx & 1) * 8 + rin;
                int kc = ks * 2 + (mtx >> 1);
                LDSM4(a, Ab + (uint32_t)m * 128 + ((uint32_t)(kc ^ (m & 7)) << 4));
                uint32_t b[4][4];
#pragma unroll
                for (int ntp = 0; ntp < 4; ntp++) {
                    int k = ks * 16 + (mtx & 1) * 8 + rin;
                    int nch = (nc >> 3) + ntp * 2 + (mtx >> 1);
                    LDSM4T(b[ntp], Bb + (uint32_t)k * 256 + ((uint32_t)(nch ^ (k & 7)) << 4));
                }
#pragma unroll
                for (int nt = 0; nt < 8; nt++)
                    MMA16816(acc3[nt], a, b[nt >> 1][(nt & 1) * 2], b[nt >> 1][(nt & 1) * 2 + 1]);
            }
        }
    }
    __syncthreads();   // all W3/H1/H2/X reads done; A & B regions now writable

    // ---------------- gather msgs + form A = (src+dst)*attr*rad -------------
    {
        const int nc = ni1 * 64;
#pragma unroll
        for (int rh = 0; rh < 2; rh++) {
            int r = mr + rh * 8 + lr;
            int ec = min(e0 + r, E - 1);
            int src = sSrc[r], dst = sDst[r];
            float at = sAttr[r];
            const float* ps = g_msg_src + (size_t)src * 128;
            const float* pd = g_msg_dst + (size_t)dst * 128;
#pragma unroll
            for (int nt = 0; nt < 8; nt++) {
                int col = nc + nt * 8 + lc * 2;
                float rad0 = acc3[nt][rh * 2 + 0] + sB3[col];
                float rad1 = acc3[nt][rh * 2 + 1] + sB3[col + 1];
                float2 ms = *(const float2*)(ps + col);
                float2 md = *(const float2*)(pd + col);
                float m0 = (ms.x + md.x) * at * rad0;
                float m1 = (ms.y + md.y) * at * rad1;
                uint32_t hi, lo; split2(m0, m1, hi, lo);
                uint32_t ad = (uint32_t)r * 256 + ((uint32_t)((col >> 3) ^ (r & 7)) << 4) + (col & 7) * 2;
                STS32(Ahi + ad, hi); STS32(Alo + ad, lo);
            }
            (void)ec;
        }
    }

    // ---------------- stage B = w_sep [k][n] hi/lo ---------------------------
#pragma unroll 4
    for (int it = 0; it < 16; it++) {
        int idx = tid + 512 * it;            // (k, n/4)
        int k = idx >> 6, n4 = (idx & 63) << 2;
        float4 v = *(const float4*)(w_sep + (size_t)k * 256 + n4);
        uint32_t hA, hB, lA, lB; split4(v, hA, hB, lA, lB);
        uint32_t addr = (uint32_t)k * 512 + ((uint32_t)((n4 >> 3) ^ (k & 7)) << 4) + (n4 & 7) * 2;
        STS64(Bhi + addr, hA, hB);
        STS64(Blo + addr, lA, lB);
    }
    __syncthreads();

    // ---------------- phase2: D[128,256] = A @ B + epilogue -----------------
    const int mi = wid & 3, ni = wid >> 2;
    const int mrow0 = mi * 32, ncol0 = ni * 64;

    float d[2][8][4];
#pragma unroll
    for (int a = 0; a < 2; a++)
#pragma unroll
        for (int b = 0; b < 8; b++)
#pragma unroll
            for (int c = 0; c < 4; c++) d[a][b][c] = 0.0f;

#pragma unroll
    for (int t = 0; t < 3; t++) {
        const uint32_t Ab = (t == 2) ? Alo : Ahi;
        const uint32_t Bb = (t == 1) ? Blo : Bhi;
#pragma unroll
        for (int ks = 0; ks < 8; ks++) {
            uint32_t a[2][4];
#pragma unroll
            for (int mt = 0; mt < 2; mt++) {
                int m = mrow0 + mt * 16 + (mtx & 1) * 8 + rin;
                int kchunk = ks * 2 + (mtx >> 1);
                uint32_t ad = Ab + (uint32_t)m * 256 + ((uint32_t)(kchunk ^ (m & 7)) << 4);
                LDSM4(a[mt], ad);
            }
            uint32_t b[4][4];
#pragma unroll
            for (int ntp = 0; ntp < 4; ntp++) {
                int k = ks * 16 + (mtx & 1) * 8 + rin;
                int nchunk = (ncol0 >> 3) + ntp * 2 + (mtx >> 1);
                uint32_t bd = Bb + (uint32_t)k * 512 + ((uint32_t)(nchunk ^ (k & 7)) << 4);
                LDSM4T(b[ntp], bd);
            }
#pragma unroll
            for (int mt = 0; mt < 2; mt++)
#pragma unroll
                for (int nt = 0; nt < 8; nt++)
                    MMA16816(d[mt][nt], a[mt], b[nt >> 1][(nt & 1) * 2], b[nt >> 1][(nt & 1) * 2 + 1]);
        }
    }

    // ---- attention epilogue (register accumulators) ----
#pragma unroll
    for (int hh = 0; hh < 2; hh++) {
        const int h = ni * 2 + hh;
#pragma unroll
        for (int mt = 0; mt < 2; mt++) {
            const int ebase = e0 + mrow0 + mt * 16 + lr;
            float p0 = 0.0f, p1 = 0.0f;
#pragma unroll
            for (int q = 0; q < 2; q++) {
                const int nt = hh * 4 + q;
                const int colb = ncol0 + nt * 8 + lc * 2;
                const int jb = q * 8 + lc * 2;
                const float bb0 = sBsep[colb], bb1 = sBsep[colb + 1];
                const float w0 = sAD[h * 16 + jb], w1 = sAD[h * 16 + jb + 1];
                float x, sg;
                x = d[mt][nt][0] + bb0; sg = 1.0f / (1.0f + __expf(-x)); p0 += x * (0.2f + 0.8f * sg) * w0;
                x = d[mt][nt][1] + bb1; sg = 1.0f / (1.0f + __expf(-x)); p0 += x * (0.2f + 0.8f * sg) * w1;
                x = d[mt][nt][2] + bb0; sg = 1.0f / (1.0f + __expf(-x)); p1 += x * (0.2f + 0.8f * sg) * w0;
                x = d[mt][nt][3] + bb1; sg = 1.0f / (1.0f + __expf(-x)); p1 += x * (0.2f + 0.8f * sg) * w1;
            }
            p0 += __shfl_xor_sync(0xffffffffu, p0, 1);
            p0 += __shfl_xor_sync(0xffffffffu, p0, 2);
            p1 += __shfl_xor_sync(0xffffffffu, p1, 1);
            p1 += __shfl_xor_sync(0xffffffffu, p1, 2);
            if (lc == 0) {
                if (ebase < E) {
                    g_score[(size_t)ebase * 8 + h] = p0;
                    atomicMaxFloat(&g_nmax[(size_t)sDst[mrow0 + mt * 16 + lr] * 8 + h], p0);
                }
                if (ebase + 8 < E) {
                    g_score[(size_t)(ebase + 8) * 8 + h] = p1;
                    atomicMaxFloat(&g_nmax[(size_t)sDst[mrow0 + mt * 16 + lr + 8] * 8 + h], p1);
                }
            }
#pragma unroll
            for (int q = 0; q < 2; q++) {
                const int nt = hh * 4 + 2 + q;
                const int colb = ncol0 + nt * 8 + lc * 2;
                const int vidx = q * 8 + lc * 2;
                const float bb0 = sBsep[colb], bb1 = sBsep[colb + 1];
                if (ebase < E)
                    *(float2*)(g_value + (size_t)ebase * 128 + h * 16 + vidx) =
                        make_float2(d[mt][nt][0] + bb0, d[mt][nt][1] + bb1);
                if (ebase + 8 < E)
                    *(float2*)(g_value + (size_t)(ebase + 8) * 128 + h * 16 + vidx) =
                        make_float2(d[mt][nt][2] + bb0, d[mt][nt][3] + bb1);
            }
        }
    }
}

// ---------------- K4: exp + segment sums (one warp per edge) ----------------
__global__ __launch_bounds__(256) void scatter_kernel(const int* __restrict__ edge_dst, int E)
{
    int gw = (blockIdx.x * blockDim.x + threadIdx.x) >> 5;
    int lane = threadIdx.x & 31;
    if (gw >= E) return;
    int d = edge_dst[gw];
    int h = lane >> 2;
    float s = g_score[(size_t)gw * 8 + h];
    float mx = g_nmax[(size_t)d * 8 + h];
    float w = __expf(s - mx);
    if ((lane & 3) == 0) atomicAdd(&g_nsum[(size_t)d * 8 + h], w);
    float4 v = *(const float4*)(g_value + (size_t)gw * 128 + lane * 4);
    float* p = g_nacc + (size_t)d * 128 + lane * 4;
    atomicAdd(p + 0, v.x * w);
    atomicAdd(p + 1, v.y * w);
    atomicAdd(p + 2, v.z * w);
    atomicAdd(p + 3, v.w * w);
}

// ---------------- K5: out = (nacc / (nsum+eps)) @ w_proj + b_proj -----------
__global__ __launch_bounds__(256) void out_gemm_kernel(
    const float* __restrict__ W, const float* __restrict__ bias,
    float* __restrict__ out, int n)
{
    __shared__ float At[32 * 64];
    __shared__ float Bs[32 * 128];
    int tid = threadIdx.x;
    int r0 = blockIdx.x * 64;
    int cg = tid & 15, rg = tid >> 4;
    int col = cg * 8, row = rg * 4;

    float acc[4][8];
#pragma unroll
    for (int i = 0; i < 4; i++)
#pragma unroll
        for (int j = 0; j < 8; j++) acc[i][j] = 0.0f;

    int lm = tid >> 2, lk = (tid & 3) * 8;
    int lkr = tid >> 3, lc = (tid & 7) * 16;

    for (int k0 = 0; k0 < 128; k0 += 32) {
        float4 a0, a1;
        int gr = r0 + lm;
        if (gr < n) {
            a0 = *(const float4*)(g_nacc + (size_t)gr * 128 + k0 + lk);
            a1 = *(const float4*)(g_nacc + (size_t)gr * 128 + k0 + lk + 4);
            int hh = (k0 + lk) >> 4;
            float inv = 1.0f / (g_nsum[(size_t)gr * 8 + hh] + 1e-16f);
            a0.x *= inv; a0.y *= inv; a0.z *= inv; a0.w *= inv;
            a1.x *= inv; a1.y *= inv; a1.z *= inv; a1.w *= inv;
        } else {
            a0 = make_float4(0.f, 0.f, 0.f, 0.f); a1 = a0;
        }
        At[(lk + 0) * 64 + lm] = a0.x; At[(lk + 1) * 64 + lm] = a0.y;
        At[(lk + 2) * 64 + lm] = a0.z; At[(lk + 3) * 64 + lm] = a0.w;
        At[(lk + 4) * 64 + lm] = a1.x; At[(lk + 5) * 64 + lm] = a1.y;
        At[(lk + 6) * 64 + lm] = a1.z; At[(lk + 7) * 64 + lm] = a1.w;
#pragma unroll
        for (int q = 0; q < 4; q++)
            *(float4*)(Bs + lkr * 128 + lc + 4 * q) =
                *(const float4*)(W + (size_t)(k0 + lkr) * 128 + lc + 4 * q);
        __syncthreads();
#pragma unroll
        for (int kk = 0; kk < 32; kk++) {
            float a[4], b[8];
            *(float4*)a       = *(float4*)(At + kk * 64 + row);
            *(float4*)(b)     = *(float4*)(Bs + kk * 128 + col);
            *(float4*)(b + 4) = *(float4*)(Bs + kk * 128 + col + 4);
#pragma unroll
            for (int i = 0; i < 4; i++)
#pragma unroll
                for (int j = 0; j < 8; j++) acc[i][j] += a[i] * b[j];
        }
        __syncthreads();
    }

    float bj[8];
    *(float4*)(bj)     = *(const float4*)(bias + col);
    *(float4*)(bj + 4) = *(const float4*)(bias + col + 4);
#pragma unroll
    for (int i = 0; i < 4; i++) {
        int gr = r0 + row + i;
        if (gr >= n) continue;
        float4 o0 = make_float4(acc[i][0] + bj[0], acc[i][1] + bj[1],
                                acc[i][2] + bj[2], acc[i][3] + bj[3]);
        float4 o1 = make_float4(acc[i][4] + bj[4], acc[i][5] + bj[5],
                                acc[i][6] + bj[6], acc[i][7] + bj[7]);
        *(float4*)(out + (size_t)gr * 128 + col)     = o0;
        *(float4*)(out + (size_t)gr * 128 + col + 4) = o1;
    }
}

// ---------------- launch ----------------
extern "C" void kernel_launch(void* const* d_in, const int* in_sizes, int n_in,
                              void* d_out, int out_size)
{
    const float* node_input = (const float*)d_in[0];
    const float* edge_attr  = (const float*)d_in[2];
    const float* edge_scal  = (const float*)d_in[3];
    const int*   edge_src   = (const int*)d_in[4];
    const int*   edge_dst   = (const int*)d_in[5];
    const float* w_src      = (const float*)d_in[7];
    const float* b_src      = (const float*)d_in[8];
    const float* w_dst      = (const float*)d_in[9];
    const float* fc_w1      = (const float*)d_in[10];
    const float* fc_b1      = (const float*)d_in[11];
    const float* fc_w2      = (const float*)d_in[12];
    const float* fc_b2      = (const float*)d_in[13];
    const float* fc_w3      = (const float*)d_in[14];
    const float* fc_b3      = (const float*)d_in[15];
    const float* w_sep      = (const float*)d_in[16];
    const float* b_sep      = (const float*)d_in[17];
    const float* alpha_dot  = (const float*)d_in[18];
    const float* w_proj     = (const float*)d_in[19];
    const float* b_proj     = (const float*)d_in[20];
    float* out = (float*)d_out;

    int N = in_sizes[0] / 128;
    int E = in_sizes[4];

    cudaFuncSetAttribute(fused_edge_kernel, cudaFuncAttributeMaxDynamicSharedMemorySize, 196608);

    init_kernel<<<(N * 128 + 255) / 256, 256>>>(N);

    int nb = (N + 63) / 64;
    node_gemm_kernel<<<nb, 256>>>(node_input, w_src, b_src, N, 0);
    node_gemm_kernel<<<nb, 256>>>(node_input, w_dst, nullptr, N, 1);

    int tb = (E + 127) / 128;
    fused_edge_kernel<<<tb, 512, 196608>>>(edge_scal, edge_attr, edge_src, edge_dst,
                                           fc_w1, fc_b1, fc_w2, fc_b2, fc_w3, fc_b3,
                                           w_sep, b_sep, alpha_dot, E);

    scatter_kernel<<<(E + 7) / 8, 256>>>(edge_dst, E);

    out_gemm_kernel<<<nb, 256>>>(w_proj, b_proj, out, N);
}

// round 6
// speedup vs baseline: 3.0068x; 1.3303x over previous
#include <cuda_runtime.h>
#include <cuda_fp16.h>
#include <cstdint>
#include <math.h>

// ---------------- fixed problem geometry ----------------
#define MAXN 50000
#define MAXE 800000
// C=128, A_ALL=256, RAD_IN=32, FC1=FC2=64, H=8, AH=VH=16

// ---------------- scratch ----------------
__device__ __align__(16) float g_msg_src[(size_t)MAXN * 128];
__device__ __align__(16) float g_msg_dst[(size_t)MAXN * 128];
__device__ __align__(16) float g_value[(size_t)MAXE * 128];
__device__ __align__(16) float g_score[(size_t)MAXE * 8];
__device__ __align__(16) float g_nmax[(size_t)MAXN * 8];
__device__ __align__(16) float g_nsum[(size_t)MAXN * 8];
__device__ __align__(16) float g_nacc[(size_t)MAXN * 128];

// ---------------- helpers ----------------
__device__ __forceinline__ uint32_t smem_u32(const void* p) {
    uint32_t a;
    asm("{ .reg .u64 t; cvta.to.shared.u64 t, %1; cvt.u32.u64 %0, t; }"
        : "=r"(a) : "l"(p));
    return a;
}

#define LDSM4(r, addr) \
    asm volatile("ldmatrix.sync.aligned.m8n8.x4.shared.b16 {%0,%1,%2,%3}, [%4];" \
        : "=r"((r)[0]), "=r"((r)[1]), "=r"((r)[2]), "=r"((r)[3]) : "r"(addr))

#define LDSM4T(r, addr) \
    asm volatile("ldmatrix.sync.aligned.m8n8.x4.trans.shared.b16 {%0,%1,%2,%3}, [%4];" \
        : "=r"((r)[0]), "=r"((r)[1]), "=r"((r)[2]), "=r"((r)[3]) : "r"(addr))

#define MMA16816(d, a, b0v, b1v) \
    asm volatile("mma.sync.aligned.m16n8k16.row.col.f32.f16.f16.f32 " \
        "{%0,%1,%2,%3}, {%4,%5,%6,%7}, {%8,%9}, {%0,%1,%2,%3};" \
        : "+f"((d)[0]), "+f"((d)[1]), "+f"((d)[2]), "+f"((d)[3]) \
        : "r"((a)[0]), "r"((a)[1]), "r"((a)[2]), "r"((a)[3]), "r"(b0v), "r"(b1v))

#define STS32(addr, v) \
    asm volatile("st.shared.b32 [%0], %1;" :: "r"(addr), "r"(v))
#define STS64(addr, v0, v1) \
    asm volatile("st.shared.v2.b32 [%0], {%1,%2};" :: "r"(addr), "r"(v0), "r"(v1))

__device__ __forceinline__ void atomicMaxFloat(float* addr, float v) {
    if (v >= 0.0f) atomicMax((int*)addr, __float_as_int(v));
    else           atomicMin((unsigned int*)addr, __float_as_uint(v));
}

__device__ __forceinline__ uint32_t packh2(float x, float y) {
    __half2 t = __floats2half2_rn(x, y);
    return *(uint32_t*)&t;
}
// split (x,y) into hi-fp16x2 and residual lo-fp16x2
__device__ __forceinline__ void split2(float x, float y, uint32_t& hi, uint32_t& lo) {
    __half h0 = __float2half_rn(x), h1 = __float2half_rn(y);
    __half2 hh = __halves2half2(h0, h1);
    hi = *(uint32_t*)&hh;
    lo = packh2(x - __half2float(h0), y - __half2float(h1));
}
__device__ __forceinline__ void split4(float4 v, uint32_t& hA, uint32_t& hB,
                                       uint32_t& lA, uint32_t& lB) {
    split2(v.x, v.y, hA, lA);
    split2(v.z, v.w, hB, lB);
}
__device__ __forceinline__ float silu(float x) {
    return x / (1.0f + __expf(-x));
}

// ---------------- K0: init segment buffers ----------------
__global__ void init_kernel(int n) {
    int i = blockIdx.x * blockDim.x + threadIdx.x;
    if (i < n * 128) g_nacc[i] = 0.0f;
    if (i < n * 8) {
        g_nmax[i] = __int_as_float(0xFF800000);
        g_nsum[i] = 0.0f;
    }
}

// ---------------- K1: node GEMM  out = X(128) @ W(128x128) [+bias] ----------
__global__ __launch_bounds__(256) void node_gemm_kernel(
    const float* __restrict__ X, const float* __restrict__ W,
    const float* __restrict__ bias, int n, int which)
{
    float* __restrict__ out = which ? g_msg_dst : g_msg_src;
    __shared__ float At[32 * 64];
    __shared__ float Bs[32 * 128];
    int tid = threadIdx.x;
    int r0 = blockIdx.x * 64;
    int cg = tid & 15, rg = tid >> 4;
    int col = cg * 8, row = rg * 4;

    float acc[4][8];
#pragma unroll
    for (int i = 0; i < 4; i++)
#pragma unroll
        for (int j = 0; j < 8; j++) acc[i][j] = 0.0f;

    int lm = tid >> 2, lk = (tid & 3) * 8;
    int lkr = tid >> 3, lc = (tid & 7) * 16;

    for (int k0 = 0; k0 < 128; k0 += 32) {
        float4 a0, a1;
        int gr = r0 + lm;
        if (gr < n) {
            a0 = *(const float4*)(X + (size_t)gr * 128 + k0 + lk);
            a1 = *(const float4*)(X + (size_t)gr * 128 + k0 + lk + 4);
        } else {
            a0 = make_float4(0.f, 0.f, 0.f, 0.f); a1 = a0;
        }
        At[(lk + 0) * 64 + lm] = a0.x; At[(lk + 1) * 64 + lm] = a0.y;
        At[(lk + 2) * 64 + lm] = a0.z; At[(lk + 3) * 64 + lm] = a0.w;
        At[(lk + 4) * 64 + lm] = a1.x; At[(lk + 5) * 64 + lm] = a1.y;
        At[(lk + 6) * 64 + lm] = a1.z; At[(lk + 7) * 64 + lm] = a1.w;
#pragma unroll
        for (int q = 0; q < 4; q++)
            *(float4*)(Bs + lkr * 128 + lc + 4 * q) =
                *(const float4*)(W + (size_t)(k0 + lkr) * 128 + lc + 4 * q);
        __syncthreads();
#pragma unroll
        for (int kk = 0; kk < 32; kk++) {
            float a[4], b[8];
            *(float4*)a       = *(float4*)(At + kk * 64 + row);
            *(float4*)(b)     = *(float4*)(Bs + kk * 128 + col);
            *(float4*)(b + 4) = *(float4*)(Bs + kk * 128 + col + 4);
#pragma unroll
            for (int i = 0; i < 4; i++)
#pragma unroll
                for (int j = 0; j < 8; j++) acc[i][j] += a[i] * b[j];
        }
        __syncthreads();
    }

    float bj[8];
    if (bias) {
        *(float4*)bj       = *(const float4*)(bias + col);
        *(float4*)(bj + 4) = *(const float4*)(bias + col + 4);
    } else {
#pragma unroll
        for (int j = 0; j < 8; j++) bj[j] = 0.0f;
    }
#pragma unroll
    for (int i = 0; i < 4; i++) {
        int gr = r0 + row + i;
        if (gr >= n) continue;
        float4 o0 = make_float4(acc[i][0] + bj[0], acc[i][1] + bj[1],
                                acc[i][2] + bj[2], acc[i][3] + bj[3]);
        float4 o1 = make_float4(acc[i][4] + bj[4], acc[i][5] + bj[5],
                                acc[i][6] + bj[6], acc[i][7] + bj[7]);
        *(float4*)(out + (size_t)gr * 128 + col)     = o0;
        *(float4*)(out + (size_t)gr * 128 + col + 4) = o1;
    }
}

// ============================================================================
// K23: FUSED radial-MLP + gather + w_sep GEMM + attention epilogue (fp16 HMMA)
// 128 edges per CTA, 512 threads (16 warps).
//  MLP GEMMs: 3-pass error-compensated (AhBh+AhBl+AlBh), shared fragments.
//  w_sep GEMM: 2-pass (A hi/lo, B single fp16; residual ~2^-11/sqrt(3)).
//
// Dynamic SMEM (155648 B), phase-aliased:
//  phase2:  A_hi[0,32K) A_lo[32K,64K) B[64K,128K)
//  phase1:  W3 hi/lo [0,32K) | H1 hi/lo [32K,64K) | X hi/lo [64K,96K)
//           W1 hi/lo [96K,104K) | W2 hi/lo [104K,120K) | H2 hi/lo [120K,152K)
//  All bf16/fp16 images use 16B-chunk XOR swizzle: chunk ^= (row&7).
// ============================================================================
__global__ __launch_bounds__(512, 1) void fused_edge_kernel(
    const float* __restrict__ edge_scalars, const float* __restrict__ edge_attr,
    const int* __restrict__ edge_src, const int* __restrict__ edge_dst,
    const float* __restrict__ w1, const float* __restrict__ b1,
    const float* __restrict__ w2, const float* __restrict__ b2,
    const float* __restrict__ w3, const float* __restrict__ b3,
    const float* __restrict__ w_sep, const float* __restrict__ b_sep,
    const float* __restrict__ alpha_dot, int E)
{
    extern __shared__ char dynsm[];
    __shared__ float sB1[64], sB2[64], sB3[128];
    __shared__ float sBsep[256], sAD[128];
    __shared__ int   sSrc[128], sDst[128];
    __shared__ float sAttr[128];

    const int tid = threadIdx.x;
    const int wid = tid >> 5, lane = tid & 31;
    const int e0 = blockIdx.x * 128;
    const int mtx = lane >> 3, rin = lane & 7;
    const int lr = lane >> 2, lc = lane & 3;

    const uint32_t sb = smem_u32(dynsm);
    // phase2 regions
    const uint32_t Ahi = sb, Alo = sb + 32768, Bsm = sb + 65536;
    // phase1 regions
    const uint32_t W3hi = sb,          W3lo = sb + 16384;
    const uint32_t H1hi = sb + 32768,  H1lo = sb + 49152;
    const uint32_t Xhi  = sb + 65536,  Xlo  = sb + 81920;
    const uint32_t W1hi = sb + 98304,  W1lo = sb + 102400;
    const uint32_t W2hi = sb + 106496, W2lo = sb + 114688;
    const uint32_t H2hi = sb + 122880, H2lo = sb + 139264;

    // ---------------- stage phase-1 inputs ----------------
    if (tid < 64)  { sB1[tid] = b1[tid]; sB2[tid] = b2[tid]; }
    if (tid < 128) { sB3[tid] = b3[tid]; sAD[tid] = alpha_dot[tid]; }
    if (tid < 256) sBsep[tid] = b_sep[tid];
    if (tid < 128) {
        int e = min(e0 + tid, E - 1);
        sSrc[tid] = edge_src[e];
        sDst[tid] = edge_dst[e];
        sAttr[tid] = (e0 + tid < E) ? edge_attr[e] : 0.0f;
    }
    // X: 128 x 32 fp32 (1024 float4)
#pragma unroll
    for (int it = 0; it < 2; it++) {
        int i = tid + 512 * it;
        int m = i >> 3, k4 = (i & 7) << 2;
        int e = min(e0 + m, E - 1);
        float4 v = *(const float4*)(edge_scalars + (size_t)e * 32 + k4);
        uint32_t hA, hB, lA, lB; split4(v, hA, hB, lA, lB);
        uint32_t addr = (uint32_t)m * 128 + ((uint32_t)(((k4 >> 3) ^ (m & 7))) << 4) + (k4 & 7) * 2;
        STS64(Xhi + addr, hA, hB);
        STS64(Xlo + addr, lA, lB);
    }
    // W1: 32x64 (512 float4)
    {
        int k = tid >> 4, n4 = (tid & 15) << 2;
        float4 v = *(const float4*)(w1 + (size_t)k * 64 + n4);
        uint32_t hA, hB, lA, lB; split4(v, hA, hB, lA, lB);
        uint32_t addr = (uint32_t)k * 128 + ((uint32_t)(((n4 >> 3) ^ (k & 7))) << 4) + (n4 & 7) * 2;
        STS64(W1hi + addr, hA, hB);
        STS64(W1lo + addr, lA, lB);
    }
    // W2: 64x64 (1024 float4)
#pragma unroll
    for (int it = 0; it < 2; it++) {
        int i = tid + 512 * it;
        int k = i >> 4, n4 = (i & 15) << 2;
        float4 v = *(const float4*)(w2 + (size_t)k * 64 + n4);
        uint32_t hA, hB, lA, lB; split4(v, hA, hB, lA, lB);
        uint32_t addr = (uint32_t)k * 128 + ((uint32_t)(((n4 >> 3) ^ (k & 7))) << 4) + (n4 & 7) * 2;
        STS64(W2hi + addr, hA, hB);
        STS64(W2lo + addr, lA, lB);
    }
    // W3: 64x128 (2048 float4), rows 256B
#pragma unroll
    for (int it = 0; it < 4; it++) {
        int i = tid + 512 * it;
        int k = i >> 5, n4 = (i & 31) << 2;
        float4 v = *(const float4*)(w3 + (size_t)k * 128 + n4);
        uint32_t hA, hB, lA, lB; split4(v, hA, hB, lA, lB);
        uint32_t addr = (uint32_t)k * 256 + ((uint32_t)(((n4 >> 3) ^ (k & 7))) << 4) + (n4 & 7) * 2;
        STS64(W3hi + addr, hA, hB);
        STS64(W3lo + addr, lA, lB);
    }
    __syncthreads();

    // warp tile for MLP: 8 M-tiles x 2 N-tiles
    const int mi1 = wid & 7, ni1 = wid >> 3;
    const int mr = mi1 * 16;

    // ---------------- layer1: H1 = silu(X @ W1 + b1)  [128x64, K=32] --------
    {
        const int nc = ni1 * 32;
        float acc[4][4];
#pragma unroll
        for (int i = 0; i < 4; i++)
#pragma unroll
            for (int j = 0; j < 4; j++) acc[i][j] = 0.0f;
#pragma unroll
        for (int ks = 0; ks < 2; ks++) {
            int m = mr + (mtx & 1) * 8 + rin;
            int kc = ks * 2 + (mtx >> 1);
            uint32_t aoff = (uint32_t)m * 128 + ((uint32_t)(kc ^ (m & 7)) << 4);
            uint32_t aH[4], aL[4];
            LDSM4(aH, Xhi + aoff);
            LDSM4(aL, Xlo + aoff);
            uint32_t bH[2][4], bL[2][4];
#pragma unroll
            for (int ntp = 0; ntp < 2; ntp++) {
                int k = ks * 16 + (mtx & 1) * 8 + rin;
                int nch = (nc >> 3) + ntp * 2 + (mtx >> 1);
                uint32_t boff = (uint32_t)k * 128 + ((uint32_t)(nch ^ (k & 7)) << 4);
                LDSM4T(bH[ntp], W1hi + boff);
                LDSM4T(bL[ntp], W1lo + boff);
            }
#pragma unroll
            for (int nt = 0; nt < 4; nt++) {
                MMA16816(acc[nt], aH, bH[nt >> 1][(nt & 1) * 2], bH[nt >> 1][(nt & 1) * 2 + 1]);
                MMA16816(acc[nt], aH, bL[nt >> 1][(nt & 1) * 2], bL[nt >> 1][(nt & 1) * 2 + 1]);
                MMA16816(acc[nt], aL, bH[nt >> 1][(nt & 1) * 2], bH[nt >> 1][(nt & 1) * 2 + 1]);
            }
        }
#pragma unroll
        for (int nt = 0; nt < 4; nt++) {
            int col = nc + nt * 8 + lc * 2;
            float s0 = silu(acc[nt][0] + sB1[col]);
            float s1 = silu(acc[nt][1] + sB1[col + 1]);
            float s2 = silu(acc[nt][2] + sB1[col]);
            float s3 = silu(acc[nt][3] + sB1[col + 1]);
            int r0 = mr + lr, r1 = r0 + 8;
            uint32_t hi, lo;
            uint32_t ad0 = (uint32_t)r0 * 128 + ((uint32_t)((col >> 3) ^ (r0 & 7)) << 4) + (col & 7) * 2;
            split2(s0, s1, hi, lo); STS32(H1hi + ad0, hi); STS32(H1lo + ad0, lo);
            uint32_t ad1 = (uint32_t)r1 * 128 + ((uint32_t)((col >> 3) ^ (r1 & 7)) << 4) + (col & 7) * 2;
            split2(s2, s3, hi, lo); STS32(H1hi + ad1, hi); STS32(H1lo + ad1, lo);
        }
    }
    __syncthreads();

    // ---------------- layer2: H2 = silu(H1 @ W2 + b2)  [128x64, K=64] -------
    {
        const int nc = ni1 * 32;
        float acc[4][4];
#pragma unroll
        for (int i = 0; i < 4; i++)
#pragma unroll
            for (int j = 0; j < 4; j++) acc[i][j] = 0.0f;
#pragma unroll
        for (int ks = 0; ks < 4; ks++) {
            int m = mr + (mtx & 1) * 8 + rin;
            int kc = ks * 2 + (mtx >> 1);
            uint32_t aoff = (uint32_t)m * 128 + ((uint32_t)(kc ^ (m & 7)) << 4);
            uint32_t aH[4], aL[4];
            LDSM4(aH, H1hi + aoff);
            LDSM4(aL, H1lo + aoff);
            uint32_t bH[2][4], bL[2][4];
#pragma unroll
            for (int ntp = 0; ntp < 2; ntp++) {
                int k = ks * 16 + (mtx & 1) * 8 + rin;
                int nch = (nc >> 3) + ntp * 2 + (mtx >> 1);
                uint32_t boff = (uint32_t)k * 128 + ((uint32_t)(nch ^ (k & 7)) << 4);
                LDSM4T(bH[ntp], W2hi + boff);
                LDSM4T(bL[ntp], W2lo + boff);
            }
#pragma unroll
            for (int nt = 0; nt < 4; nt++) {
                MMA16816(acc[nt], aH, bH[nt >> 1][(nt & 1) * 2], bH[nt >> 1][(nt & 1) * 2 + 1]);
                MMA16816(acc[nt], aH, bL[nt >> 1][(nt & 1) * 2], bL[nt >> 1][(nt & 1) * 2 + 1]);
                MMA16816(acc[nt], aL, bH[nt >> 1][(nt & 1) * 2], bH[nt >> 1][(nt & 1) * 2 + 1]);
            }
        }
#pragma unroll
        for (int nt = 0; nt < 4; nt++) {
            int col = nc + nt * 8 + lc * 2;
            float s0 = silu(acc[nt][0] + sB2[col]);
            float s1 = silu(acc[nt][1] + sB2[col + 1]);
            float s2 = silu(acc[nt][2] + sB2[col]);
            float s3 = silu(acc[nt][3] + sB2[col + 1]);
            int r0 = mr + lr, r1 = r0 + 8;
            uint32_t hi, lo;
            uint32_t ad0 = (uint32_t)r0 * 128 + ((uint32_t)((col >> 3) ^ (r0 & 7)) << 4) + (col & 7) * 2;
            split2(s0, s1, hi, lo); STS32(H2hi + ad0, hi); STS32(H2lo + ad0, lo);
            uint32_t ad1 = (uint32_t)r1 * 128 + ((uint32_t)((col >> 3) ^ (r1 & 7)) << 4) + (col & 7) * 2;
            split2(s2, s3, hi, lo); STS32(H2hi + ad1, hi); STS32(H2lo + ad1, lo);
        }
    }
    __syncthreads();

    // ---------------- layer3: rad = H2 @ W3 + b3  [128x128, K=64] (regs) ----
    float acc3[8][4];
#pragma unroll
    for (int i = 0; i < 8; i++)
#pragma unroll
        for (int j = 0; j < 4; j++) acc3[i][j] = 0.0f;
    {
        const int nc = ni1 * 64;
#pragma unroll
        for (int ks = 0; ks < 4; ks++) {
            int m = mr + (mtx & 1) * 8 + rin;
            int kc = ks * 2 + (mtx >> 1);
            uint32_t aoff = (uint32_t)m * 128 + ((uint32_t)(kc ^ (m & 7)) << 4);
            uint32_t aH[4], aL[4];
            LDSM4(aH, H2hi + aoff);
            LDSM4(aL, H2lo + aoff);
            uint32_t bH[4][4];
#pragma unroll
            for (int ntp = 0; ntp < 4; ntp++) {
                int k = ks * 16 + (mtx & 1) * 8 + rin;
                int nch = (nc >> 3) + ntp * 2 + (mtx >> 1);
                uint32_t boff = (uint32_t)k * 256 + ((uint32_t)(nch ^ (k & 7)) << 4);
                LDSM4T(bH[ntp], W3hi + boff);
            }
#pragma unroll
            for (int nt = 0; nt < 8; nt++) {
                MMA16816(acc3[nt], aH, bH[nt >> 1][(nt & 1) * 2], bH[nt >> 1][(nt & 1) * 2 + 1]);
                MMA16816(acc3[nt], aL, bH[nt >> 1][(nt & 1) * 2], bH[nt >> 1][(nt & 1) * 2 + 1]);
            }
            uint32_t bL[4][4];
#pragma unroll
            for (int ntp = 0; ntp < 4; ntp++) {
                int k = ks * 16 + (mtx & 1) * 8 + rin;
                int nch = (nc >> 3) + ntp * 2 + (mtx >> 1);
                uint32_t boff = (uint32_t)k * 256 + ((uint32_t)(nch ^ (k & 7)) << 4);
                LDSM4T(bL[ntp], W3lo + boff);
            }
#pragma unroll
            for (int nt = 0; nt < 8; nt++)
                MMA16816(acc3[nt], aH, bL[nt >> 1][(nt & 1) * 2], bL[nt >> 1][(nt & 1) * 2 + 1]);
        }
    }
    __syncthreads();   // all X/H1/H2/W reads done; A & B regions now writable

    // ---------------- gather msgs + form A = (src+dst)*attr*rad -------------
    {
        const int nc = ni1 * 64;
#pragma unroll
        for (int rh = 0; rh < 2; rh++) {
            int r = mr + rh * 8 + lr;
            int src = sSrc[r], dst = sDst[r];
            float at = sAttr[r];
            const float* ps = g_msg_src + (size_t)src * 128;
            const float* pd = g_msg_dst + (size_t)dst * 128;
#pragma unroll
            for (int nt = 0; nt < 8; nt++) {
                int col = nc + nt * 8 + lc * 2;
                float rad0 = acc3[nt][rh * 2 + 0] + sB3[col];
                float rad1 = acc3[nt][rh * 2 + 1] + sB3[col + 1];
                float2 ms = *(const float2*)(ps + col);
                float2 md = *(const float2*)(pd + col);
                float m0 = (ms.x + md.x) * at * rad0;
                float m1 = (ms.y + md.y) * at * rad1;
                uint32_t hi, lo; split2(m0, m1, hi, lo);
                uint32_t ad = (uint32_t)r * 256 + ((uint32_t)((col >> 3) ^ (r & 7)) << 4) + (col & 7) * 2;
                STS32(Ahi + ad, hi); STS32(Alo + ad, lo);
            }
        }
    }

    // ---------------- stage B = w_sep [k][n] single fp16 ---------------------
#pragma unroll 4
    for (int it = 0; it < 16; it++) {
        int idx = tid + 512 * it;            // (k, n/4)
        int k = idx >> 6, n4 = (idx & 63) << 2;
        float4 v = *(const float4*)(w_sep + (size_t)k * 256 + n4);
        uint32_t hA = packh2(v.x, v.y), hB = packh2(v.z, v.w);
        uint32_t addr = (uint32_t)k * 512 + ((uint32_t)((n4 >> 3) ^ (k & 7)) << 4) + (n4 & 7) * 2;
        STS64(Bsm + addr, hA, hB);
    }
    __syncthreads();

    // ---------------- phase2: D[128,256] = (Ah+Al) @ B + epilogue -----------
    const int mi = wid & 3, ni = wid >> 2;
    const int mrow0 = mi * 32, ncol0 = ni * 64;

    float d[2][8][4];
#pragma unroll
    for (int a = 0; a < 2; a++)
#pragma unroll
        for (int b = 0; b < 8; b++)
#pragma unroll
            for (int c = 0; c < 4; c++) d[a][b][c] = 0.0f;

#pragma unroll
    for (int ks = 0; ks < 8; ks++) {
        uint32_t ah[2][4];
#pragma unroll
        for (int mt = 0; mt < 2; mt++) {
            int m = mrow0 + mt * 16 + (mtx & 1) * 8 + rin;
            int kchunk = ks * 2 + (mtx >> 1);
            LDSM4(ah[mt], Ahi + (uint32_t)m * 256 + ((uint32_t)(kchunk ^ (m & 7)) << 4));
        }
        uint32_t b[4][4];
#pragma unroll
        for (int ntp = 0; ntp < 4; ntp++) {
            int k = ks * 16 + (mtx & 1) * 8 + rin;
            int nchunk = (ncol0 >> 3) + ntp * 2 + (mtx >> 1);
            LDSM4T(b[ntp], Bsm + (uint32_t)k * 512 + ((uint32_t)(nchunk ^ (k & 7)) << 4));
        }
#pragma unroll
        for (int mt = 0; mt < 2; mt++)
#pragma unroll
            for (int nt = 0; nt < 8; nt++)
                MMA16816(d[mt][nt], ah[mt], b[nt >> 1][(nt & 1) * 2], b[nt >> 1][(nt & 1) * 2 + 1]);
        uint32_t al[2][4];
#pragma unroll
        for (int mt = 0; mt < 2; mt++) {
            int m = mrow0 + mt * 16 + (mtx & 1) * 8 + rin;
            int kchunk = ks * 2 + (mtx >> 1);
            LDSM4(al[mt], Alo + (uint32_t)m * 256 + ((uint32_t)(kchunk ^ (m & 7)) << 4));
        }
#pragma unroll
        for (int mt = 0; mt < 2; mt++)
#pragma unroll
            for (int nt = 0; nt < 8; nt++)
                MMA16816(d[mt][nt], al[mt], b[nt >> 1][(nt & 1) * 2], b[nt >> 1][(nt & 1) * 2 + 1]);
    }

    // ---- attention epilogue (register accumulators) ----
#pragma unroll
    for (int hh = 0; hh < 2; hh++) {
        const int h = ni * 2 + hh;
#pragma unroll
        for (int mt = 0; mt < 2; mt++) {
            const int ebase = e0 + mrow0 + mt * 16 + lr;
            float p0 = 0.0f, p1 = 0.0f;
#pragma unroll
            for (int q = 0; q < 2; q++) {
                const int nt = hh * 4 + q;
                const int colb = ncol0 + nt * 8 + lc * 2;
                const int jb = q * 8 + lc * 2;
                const float bb0 = sBsep[colb], bb1 = sBsep[colb + 1];
                const float w0 = sAD[h * 16 + jb], w1 = sAD[h * 16 + jb + 1];
                float x, sg;
                x = d[mt][nt][0] + bb0; sg = 1.0f / (1.0f + __expf(-x)); p0 += x * (0.2f + 0.8f * sg) * w0;
                x = d[mt][nt][1] + bb1; sg = 1.0f / (1.0f + __expf(-x)); p0 += x * (0.2f + 0.8f * sg) * w1;
                x = d[mt][nt][2] + bb0; sg = 1.0f / (1.0f + __expf(-x)); p1 += x * (0.2f + 0.8f * sg) * w0;
                x = d[mt][nt][3] + bb1; sg = 1.0f / (1.0f + __expf(-x)); p1 += x * (0.2f + 0.8f * sg) * w1;
            }
            p0 += __shfl_xor_sync(0xffffffffu, p0, 1);
            p0 += __shfl_xor_sync(0xffffffffu, p0, 2);
            p1 += __shfl_xor_sync(0xffffffffu, p1, 1);
            p1 += __shfl_xor_sync(0xffffffffu, p1, 2);
            if (lc == 0) {
                if (ebase < E) {
                    g_score[(size_t)ebase * 8 + h] = p0;
                    atomicMaxFloat(&g_nmax[(size_t)sDst[mrow0 + mt * 16 + lr] * 8 + h], p0);
                }
                if (ebase + 8 < E) {
                    g_score[(size_t)(ebase + 8) * 8 + h] = p1;
                    atomicMaxFloat(&g_nmax[(size_t)sDst[mrow0 + mt * 16 + lr + 8] * 8 + h], p1);
                }
            }
#pragma unroll
            for (int q = 0; q < 2; q++) {
                const int nt = hh * 4 + 2 + q;
                const int colb = ncol0 + nt * 8 + lc * 2;
                const int vidx = q * 8 + lc * 2;
                const float bb0 = sBsep[colb], bb1 = sBsep[colb + 1];
                if (ebase < E)
                    *(float2*)(g_value + (size_t)ebase * 128 + h * 16 + vidx) =
                        make_float2(d[mt][nt][0] + bb0, d[mt][nt][1] + bb1);
                if (ebase + 8 < E)
                    *(float2*)(g_value + (size_t)(ebase + 8) * 128 + h * 16 + vidx) =
                        make_float2(d[mt][nt][2] + bb0, d[mt][nt][3] + bb1);
            }
        }
    }
}

// ---------------- K4: exp + segment sums (one warp per edge) ----------------
__global__ __launch_bounds__(256) void scatter_kernel(const int* __restrict__ edge_dst, int E)
{
    int gw = (blockIdx.x * blockDim.x + threadIdx.x) >> 5;
    int lane = threadIdx.x & 31;
    if (gw >= E) return;
    int d = edge_dst[gw];
    int h = lane >> 2;
    float s = g_score[(size_t)gw * 8 + h];
    float mx = g_nmax[(size_t)d * 8 + h];
    float w = __expf(s - mx);
    if ((lane & 3) == 0) atomicAdd(&g_nsum[(size_t)d * 8 + h], w);
    float4 v = *(const float4*)(g_value + (size_t)gw * 128 + lane * 4);
    float* p = g_nacc + (size_t)d * 128 + lane * 4;
    atomicAdd(p + 0, v.x * w);
    atomicAdd(p + 1, v.y * w);
    atomicAdd(p + 2, v.z * w);
    atomicAdd(p + 3, v.w * w);
}

// ---------------- K5: out = (nacc / (nsum+eps)) @ w_proj + b_proj -----------
__global__ __launch_bounds__(256) void out_gemm_kernel(
    const float* __restrict__ W, const float* __restrict__ bias,
    float* __restrict__ out, int n)
{
    __shared__ float At[32 * 64];
    __shared__ float Bs[32 * 128];
    int tid = threadIdx.x;
    int r0 = blockIdx.x * 64;
    int cg = tid & 15, rg = tid >> 4;
    int col = cg * 8, row = rg * 4;

    float acc[4][8];
#pragma unroll
    for (int i = 0; i < 4; i++)
#pragma unroll
        for (int j = 0; j < 8; j++) acc[i][j] = 0.0f;

    int lm = tid >> 2, lk = (tid & 3) * 8;
    int lkr = tid >> 3, lc = (tid & 7) * 16;

    for (int k0 = 0; k0 < 128; k0 += 32) {
        float4 a0, a1;
        int gr = r0 + lm;
        if (gr < n) {
            a0 = *(const float4*)(g_nacc + (size_t)gr * 128 + k0 + lk);
            a1 = *(const float4*)(g_nacc + (size_t)gr * 128 + k0 + lk + 4);
            int hh = (k0 + lk) >> 4;
            float inv = 1.0f / (g_nsum[(size_t)gr * 8 + hh] + 1e-16f);
            a0.x *= inv; a0.y *= inv; a0.z *= inv; a0.w *= inv;
            a1.x *= inv; a1.y *= inv; a1.z *= inv; a1.w *= inv;
        } else {
            a0 = make_float4(0.f, 0.f, 0.f, 0.f); a1 = a0;
        }
        At[(lk + 0) * 64 + lm] = a0.x; At[(lk + 1) * 64 + lm] = a0.y;
        At[(lk + 2) * 64 + lm] = a0.z; At[(lk + 3) * 64 + lm] = a0.w;
        At[(lk + 4) * 64 + lm] = a1.x; At[(lk + 5) * 64 + lm] = a1.y;
        At[(lk + 6) * 64 + lm] = a1.z; At[(lk + 7) * 64 + lm] = a1.w;
#pragma unroll
        for (int q = 0; q < 4; q++)
            *(float4*)(Bs + lkr * 128 + lc + 4 * q) =
                *(const float4*)(W + (size_t)(k0 + lkr) * 128 + lc + 4 * q);
        __syncthreads();
#pragma unroll
        for (int kk = 0; kk < 32; kk++) {
            float a[4], b[8];
            *(float4*)a       = *(float4*)(At + kk * 64 + row);
            *(float4*)(b)     = *(float4*)(Bs + kk * 128 + col);
            *(float4*)(b + 4) = *(float4*)(Bs + kk * 128 + col + 4);
#pragma unroll
            for (int i = 0; i < 4; i++)
#pragma unroll
                for (int j = 0; j < 8; j++) acc[i][j] += a[i] * b[j];
        }
        __syncthreads();
    }

    float bj[8];
    *(float4*)(bj)     = *(const float4*)(bias + col);
    *(float4*)(bj + 4) = *(const float4*)(bias + col + 4);
#pragma unroll
    for (int i = 0; i < 4; i++) {
        int gr = r0 + row + i;
        if (gr >= n) continue;
        float4 o0 = make_float4(acc[i][0] + bj[0], acc[i][1] + bj[1],
                                acc[i][2] + bj[2], acc[i][3] + bj[3]);
        float4 o1 = make_float4(acc[i][4] + bj[4], acc[i][5] + bj[5],
                                acc[i][6] + bj[6], acc[i][7] + bj[7]);
        *(float4*)(out + (size_t)gr * 128 + col)     = o0;
        *(float4*)(out + (size_t)gr * 128 + col + 4) = o1;
    }
}

// ---------------- launch ----------------
extern "C" void kernel_launch(void* const* d_in, const int* in_sizes, int n_in,
                              void* d_out, int out_size)
{
    const float* node_input = (const float*)d_in[0];
    const float* edge_attr  = (const float*)d_in[2];
    const float* edge_scal  = (const float*)d_in[3];
    const int*   edge_src   = (const int*)d_in[4];
    const int*   edge_dst   = (const int*)d_in[5];
    const float* w_src      = (const float*)d_in[7];
    const float* b_src      = (const float*)d_in[8];
    const float* w_dst      = (const float*)d_in[9];
    const float* fc_w1      = (const float*)d_in[10];
    const float* fc_b1      = (const float*)d_in[11];
    const float* fc_w2      = (const float*)d_in[12];
    const float* fc_b2      = (const float*)d_in[13];
    const float* fc_w3      = (const float*)d_in[14];
    const float* fc_b3      = (const float*)d_in[15];
    const float* w_sep      = (const float*)d_in[16];
    const float* b_sep      = (const float*)d_in[17];
    const float* alpha_dot  = (const float*)d_in[18];
    const float* w_proj     = (const float*)d_in[19];
    const float* b_proj     = (const float*)d_in[20];
    float* out = (float*)d_out;

    int N = in_sizes[0] / 128;
    int E = in_sizes[4];

    cudaFuncSetAttribute(fused_edge_kernel, cudaFuncAttributeMaxDynamicSharedMemorySize, 155648);

    init_kernel<<<(N * 128 + 255) / 256, 256>>>(N);

    int nb = (N + 63) / 64;
    node_gemm_kernel<<<nb, 256>>>(node_input, w_src, b_src, N, 0);
    node_gemm_kernel<<<nb, 256>>>(node_input, w_dst, nullptr, N, 1);

    int tb = (E + 127) / 128;
    fused_edge_kernel<<<tb, 512, 155648>>>(edge_scal, edge_attr, edge_src, edge_dst,
                                           fc_w1, fc_b1, fc_w2, fc_b2, fc_w3, fc_b3,
                                           w_sep, b_sep, alpha_dot, E);

    scatter_kernel<<<(E + 7) / 8, 256>>>(edge_dst, E);

    out_gemm_kernel<<<nb, 256>>>(w_proj, b_proj, out, N);
}

// round 7
// speedup vs baseline: 3.8022x; 1.2646x over previous
#include <cuda_runtime.h>
#include <cuda_fp16.h>
#include <cstdint>
#include <math.h>

// ---------------- fixed problem geometry ----------------
#define MAXN 50000
#define MAXE 800000
// C=128, A_ALL=256, RAD_IN=32, FC1=FC2=64, H=8, AH=VH=16

// ---------------- scratch ----------------
__device__ __align__(16) float g_msg_src[(size_t)MAXN * 128];
__device__ __align__(16) float g_msg_dst[(size_t)MAXN * 128];
__device__ __align__(16) float g_nsum[(size_t)MAXN * 8];
__device__ __align__(16) float g_nacc[(size_t)MAXN * 128];

// ---------------- helpers ----------------
__device__ __forceinline__ uint32_t smem_u32(const void* p) {
    uint32_t a;
    asm("{ .reg .u64 t; cvta.to.shared.u64 t, %1; cvt.u32.u64 %0, t; }"
        : "=r"(a) : "l"(p));
    return a;
}

#define LDSM4(r, addr) \
    asm volatile("ldmatrix.sync.aligned.m8n8.x4.shared.b16 {%0,%1,%2,%3}, [%4];" \
        : "=r"((r)[0]), "=r"((r)[1]), "=r"((r)[2]), "=r"((r)[3]) : "r"(addr))

#define LDSM4T(r, addr) \
    asm volatile("ldmatrix.sync.aligned.m8n8.x4.trans.shared.b16 {%0,%1,%2,%3}, [%4];" \
        : "=r"((r)[0]), "=r"((r)[1]), "=r"((r)[2]), "=r"((r)[3]) : "r"(addr))

#define MMA16816(d, a, b0v, b1v) \
    asm volatile("mma.sync.aligned.m16n8k16.row.col.f32.f16.f16.f32 " \
        "{%0,%1,%2,%3}, {%4,%5,%6,%7}, {%8,%9}, {%0,%1,%2,%3};" \
        : "+f"((d)[0]), "+f"((d)[1]), "+f"((d)[2]), "+f"((d)[3]) \
        : "r"((a)[0]), "r"((a)[1]), "r"((a)[2]), "r"((a)[3]), "r"(b0v), "r"(b1v))

#define STS32(addr, v) \
    asm volatile("st.shared.b32 [%0], %1;" :: "r"(addr), "r"(v))
#define STS64(addr, v0, v1) \
    asm volatile("st.shared.v2.b32 [%0], {%1,%2};" :: "r"(addr), "r"(v0), "r"(v1))

// vector fire-and-forget global reduction (sm_90+)
#define RED2(ptr, x, y) \
    asm volatile("red.global.add.v2.f32 [%0], {%1,%2};" :: "l"(ptr), "f"(x), "f"(y) : "memory")

__device__ __forceinline__ uint32_t packh2(float x, float y) {
    __half2 t = __floats2half2_rn(x, y);
    return *(uint32_t*)&t;
}
// split (x,y) into hi-fp16x2 and residual lo-fp16x2
__device__ __forceinline__ void split2(float x, float y, uint32_t& hi, uint32_t& lo) {
    __half h0 = __float2half_rn(x), h1 = __float2half_rn(y);
    __half2 hh = __halves2half2(h0, h1);
    hi = *(uint32_t*)&hh;
    lo = packh2(x - __half2float(h0), y - __half2float(h1));
}
__device__ __forceinline__ void split4(float4 v, uint32_t& hA, uint32_t& hB,
                                       uint32_t& lA, uint32_t& lB) {
    split2(v.x, v.y, hA, lA);
    split2(v.z, v.w, hB, lB);
}
__device__ __forceinline__ float silu(float x) {
    return x / (1.0f + __expf(-x));
}

// ---------------- K0: init segment buffers ----------------
__global__ void init_kernel(int n) {
    int i = blockIdx.x * blockDim.x + threadIdx.x;
    if (i < n * 128) g_nacc[i] = 0.0f;
    if (i < n * 8) g_nsum[i] = 0.0f;
}

// ---------------- K1: dual node GEMM  msg_src/msg_dst = X @ {w_src,w_dst} ---
__global__ __launch_bounds__(256) void node_gemm_dual(
    const float* __restrict__ X, const float* __restrict__ Wsrc,
    const float* __restrict__ Wdst, const float* __restrict__ bias_src, int n)
{
    __shared__ float At[32 * 64];
    __shared__ float Bs0[32 * 128];
    __shared__ float Bs1[32 * 128];
    int tid = threadIdx.x;
    int r0 = blockIdx.x * 64;
    int cg = tid & 15, rg = tid >> 4;
    int col = cg * 8, row = rg * 4;

    float acc0[4][8], acc1[4][8];
#pragma unroll
    for (int i = 0; i < 4; i++)
#pragma unroll
        for (int j = 0; j < 8; j++) { acc0[i][j] = 0.0f; acc1[i][j] = 0.0f; }

    int lm = tid >> 2, lk = (tid & 3) * 8;
    int lkr = tid >> 3, lc = (tid & 7) * 16;

    for (int k0 = 0; k0 < 128; k0 += 32) {
        float4 a0, a1;
        int gr = r0 + lm;
        if (gr < n) {
            a0 = *(const float4*)(X + (size_t)gr * 128 + k0 + lk);
            a1 = *(const float4*)(X + (size_t)gr * 128 + k0 + lk + 4);
        } else {
            a0 = make_float4(0.f, 0.f, 0.f, 0.f); a1 = a0;
        }
        At[(lk + 0) * 64 + lm] = a0.x; At[(lk + 1) * 64 + lm] = a0.y;
        At[(lk + 2) * 64 + lm] = a0.z; At[(lk + 3) * 64 + lm] = a0.w;
        At[(lk + 4) * 64 + lm] = a1.x; At[(lk + 5) * 64 + lm] = a1.y;
        At[(lk + 6) * 64 + lm] = a1.z; At[(lk + 7) * 64 + lm] = a1.w;
#pragma unroll
        for (int q = 0; q < 4; q++) {
            *(float4*)(Bs0 + lkr * 128 + lc + 4 * q) =
                *(const float4*)(Wsrc + (size_t)(k0 + lkr) * 128 + lc + 4 * q);
            *(float4*)(Bs1 + lkr * 128 + lc + 4 * q) =
                *(const float4*)(Wdst + (size_t)(k0 + lkr) * 128 + lc + 4 * q);
        }
        __syncthreads();
#pragma unroll
        for (int kk = 0; kk < 32; kk++) {
            float a[4], b0[8], b1[8];
            *(float4*)a        = *(float4*)(At + kk * 64 + row);
            *(float4*)(b0)     = *(float4*)(Bs0 + kk * 128 + col);
            *(float4*)(b0 + 4) = *(float4*)(Bs0 + kk * 128 + col + 4);
            *(float4*)(b1)     = *(float4*)(Bs1 + kk * 128 + col);
            *(float4*)(b1 + 4) = *(float4*)(Bs1 + kk * 128 + col + 4);
#pragma unroll
            for (int i = 0; i < 4; i++)
#pragma unroll
                for (int j = 0; j < 8; j++) {
                    acc0[i][j] += a[i] * b0[j];
                    acc1[i][j] += a[i] * b1[j];
                }
        }
        __syncthreads();
    }

    float bj[8];
    *(float4*)bj       = *(const float4*)(bias_src + col);
    *(float4*)(bj + 4) = *(const float4*)(bias_src + col + 4);
#pragma unroll
    for (int i = 0; i < 4; i++) {
        int gr = r0 + row + i;
        if (gr >= n) continue;
        *(float4*)(g_msg_src + (size_t)gr * 128 + col) =
            make_float4(acc0[i][0] + bj[0], acc0[i][1] + bj[1],
                        acc0[i][2] + bj[2], acc0[i][3] + bj[3]);
        *(float4*)(g_msg_src + (size_t)gr * 128 + col + 4) =
            make_float4(acc0[i][4] + bj[4], acc0[i][5] + bj[5],
                        acc0[i][6] + bj[6], acc0[i][7] + bj[7]);
        *(float4*)(g_msg_dst + (size_t)gr * 128 + col) =
            make_float4(acc1[i][0], acc1[i][1], acc1[i][2], acc1[i][3]);
        *(float4*)(g_msg_dst + (size_t)gr * 128 + col + 4) =
            make_float4(acc1[i][4], acc1[i][5], acc1[i][6], acc1[i][7]);
    }
}

// ============================================================================
// K23: FUSED radial-MLP + gather + w_sep GEMM + softmax-free attention scatter
// 128 edges per CTA, 512 threads (16 warps). fp16 HMMA.
//  MLP GEMMs: 3-pass error-compensated; w_sep GEMM: A hi/lo, B single fp16.
//  Epilogue: w = exp(score) (|score|<~5 for this model), red.v2 into g_nacc,
//  red into g_nsum. No g_value/g_score/g_nmax round trips, no scatter kernel.
// ============================================================================
__global__ __launch_bounds__(512, 1) void fused_edge_kernel(
    const float* __restrict__ edge_scalars, const float* __restrict__ edge_attr,
    const int* __restrict__ edge_src, const int* __restrict__ edge_dst,
    const float* __restrict__ w1, const float* __restrict__ b1,
    const float* __restrict__ w2, const float* __restrict__ b2,
    const float* __restrict__ w3, const float* __restrict__ b3,
    const float* __restrict__ w_sep, const float* __restrict__ b_sep,
    const float* __restrict__ alpha_dot, int E)
{
    extern __shared__ char dynsm[];
    __shared__ float sB1[64], sB2[64], sB3[128];
    __shared__ float sBsep[256], sAD[128];
    __shared__ int   sSrc[128], sDst[128];
    __shared__ float sAttr[128];

    const int tid = threadIdx.x;
    const int wid = tid >> 5, lane = tid & 31;
    const int e0 = blockIdx.x * 128;
    const int mtx = lane >> 3, rin = lane & 7;
    const int lr = lane >> 2, lc = lane & 3;

    const uint32_t sb = smem_u32(dynsm);
    // phase2 regions
    const uint32_t Ahi = sb, Alo = sb + 32768, Bsm = sb + 65536;
    // phase1 regions
    const uint32_t W3hi = sb,          W3lo = sb + 16384;
    const uint32_t H1hi = sb + 32768,  H1lo = sb + 49152;
    const uint32_t Xhi  = sb + 65536,  Xlo  = sb + 81920;
    const uint32_t W1hi = sb + 98304,  W1lo = sb + 102400;
    const uint32_t W2hi = sb + 106496, W2lo = sb + 114688;
    const uint32_t H2hi = sb + 122880, H2lo = sb + 139264;

    // ---------------- stage phase-1 inputs ----------------
    if (tid < 64)  { sB1[tid] = b1[tid]; sB2[tid] = b2[tid]; }
    if (tid < 128) { sB3[tid] = b3[tid]; sAD[tid] = alpha_dot[tid]; }
    if (tid < 256) sBsep[tid] = b_sep[tid];
    if (tid < 128) {
        int e = min(e0 + tid, E - 1);
        sSrc[tid] = edge_src[e];
        sDst[tid] = edge_dst[e];
        sAttr[tid] = (e0 + tid < E) ? edge_attr[e] : 0.0f;
    }
    // X: 128 x 32 fp32 (1024 float4)
#pragma unroll
    for (int it = 0; it < 2; it++) {
        int i = tid + 512 * it;
        int m = i >> 3, k4 = (i & 7) << 2;
        int e = min(e0 + m, E - 1);
        float4 v = *(const float4*)(edge_scalars + (size_t)e * 32 + k4);
        uint32_t hA, hB, lA, lB; split4(v, hA, hB, lA, lB);
        uint32_t addr = (uint32_t)m * 128 + ((uint32_t)(((k4 >> 3) ^ (m & 7))) << 4) + (k4 & 7) * 2;
        STS64(Xhi + addr, hA, hB);
        STS64(Xlo + addr, lA, lB);
    }
    // W1: 32x64 (512 float4)
    {
        int k = tid >> 4, n4 = (tid & 15) << 2;
        float4 v = *(const float4*)(w1 + (size_t)k * 64 + n4);
        uint32_t hA, hB, lA, lB; split4(v, hA, hB, lA, lB);
        uint32_t addr = (uint32_t)k * 128 + ((uint32_t)(((n4 >> 3) ^ (k & 7))) << 4) + (n4 & 7) * 2;
        STS64(W1hi + addr, hA, hB);
        STS64(W1lo + addr, lA, lB);
    }
    // W2: 64x64 (1024 float4)
#pragma unroll
    for (int it = 0; it < 2; it++) {
        int i = tid + 512 * it;
        int k = i >> 4, n4 = (i & 15) << 2;
        float4 v = *(const float4*)(w2 + (size_t)k * 64 + n4);
        uint32_t hA, hB, lA, lB; split4(v, hA, hB, lA, lB);
        uint32_t addr = (uint32_t)k * 128 + ((uint32_t)(((n4 >> 3) ^ (k & 7))) << 4) + (n4 & 7) * 2;
        STS64(W2hi + addr, hA, hB);
        STS64(W2lo + addr, lA, lB);
    }
    // W3: 64x128 (2048 float4), rows 256B
#pragma unroll
    for (int it = 0; it < 4; it++) {
        int i = tid + 512 * it;
        int k = i >> 5, n4 = (i & 31) << 2;
        float4 v = *(const float4*)(w3 + (size_t)k * 128 + n4);
        uint32_t hA, hB, lA, lB; split4(v, hA, hB, lA, lB);
        uint32_t addr = (uint32_t)k * 256 + ((uint32_t)(((n4 >> 3) ^ (k & 7))) << 4) + (n4 & 7) * 2;
        STS64(W3hi + addr, hA, hB);
        STS64(W3lo + addr, lA, lB);
    }
    __syncthreads();

    // warp tile for MLP: 8 M-tiles x 2 N-tiles
    const int mi1 = wid & 7, ni1 = wid >> 3;
    const int mr = mi1 * 16;

    // ---------------- layer1: H1 = silu(X @ W1 + b1)  [128x64, K=32] --------
    {
        const int nc = ni1 * 32;
        float acc[4][4];
#pragma unroll
        for (int i = 0; i < 4; i++)
#pragma unroll
            for (int j = 0; j < 4; j++) acc[i][j] = 0.0f;
#pragma unroll
        for (int ks = 0; ks < 2; ks++) {
            int m = mr + (mtx & 1) * 8 + rin;
            int kc = ks * 2 + (mtx >> 1);
            uint32_t aoff = (uint32_t)m * 128 + ((uint32_t)(kc ^ (m & 7)) << 4);
            uint32_t aH[4], aL[4];
            LDSM4(aH, Xhi + aoff);
            LDSM4(aL, Xlo + aoff);
            uint32_t bH[2][4], bL[2][4];
#pragma unroll
            for (int ntp = 0; ntp < 2; ntp++) {
                int k = ks * 16 + (mtx & 1) * 8 + rin;
                int nch = (nc >> 3) + ntp * 2 + (mtx >> 1);
                uint32_t boff = (uint32_t)k * 128 + ((uint32_t)(nch ^ (k & 7)) << 4);
                LDSM4T(bH[ntp], W1hi + boff);
                LDSM4T(bL[ntp], W1lo + boff);
            }
#pragma unroll
            for (int nt = 0; nt < 4; nt++) {
                MMA16816(acc[nt], aH, bH[nt >> 1][(nt & 1) * 2], bH[nt >> 1][(nt & 1) * 2 + 1]);
                MMA16816(acc[nt], aH, bL[nt >> 1][(nt & 1) * 2], bL[nt >> 1][(nt & 1) * 2 + 1]);
                MMA16816(acc[nt], aL, bH[nt >> 1][(nt & 1) * 2], bH[nt >> 1][(nt & 1) * 2 + 1]);
            }
        }
#pragma unroll
        for (int nt = 0; nt < 4; nt++) {
            int col = nc + nt * 8 + lc * 2;
            float s0 = silu(acc[nt][0] + sB1[col]);
            float s1 = silu(acc[nt][1] + sB1[col + 1]);
            float s2 = silu(acc[nt][2] + sB1[col]);
            float s3 = silu(acc[nt][3] + sB1[col + 1]);
            int r0 = mr + lr, r1 = r0 + 8;
            uint32_t hi, lo;
            uint32_t ad0 = (uint32_t)r0 * 128 + ((uint32_t)((col >> 3) ^ (r0 & 7)) << 4) + (col & 7) * 2;
            split2(s0, s1, hi, lo); STS32(H1hi + ad0, hi); STS32(H1lo + ad0, lo);
            uint32_t ad1 = (uint32_t)r1 * 128 + ((uint32_t)((col >> 3) ^ (r1 & 7)) << 4) + (col & 7) * 2;
            split2(s2, s3, hi, lo); STS32(H1hi + ad1, hi); STS32(H1lo + ad1, lo);
        }
    }
    __syncthreads();

    // ---------------- layer2: H2 = silu(H1 @ W2 + b2)  [128x64, K=64] -------
    {
        const int nc = ni1 * 32;
        float acc[4][4];
#pragma unroll
        for (int i = 0; i < 4; i++)
#pragma unroll
            for (int j = 0; j < 4; j++) acc[i][j] = 0.0f;
#pragma unroll
        for (int ks = 0; ks < 4; ks++) {
            int m = mr + (mtx & 1) * 8 + rin;
            int kc = ks * 2 + (mtx >> 1);
            uint32_t aoff = (uint32_t)m * 128 + ((uint32_t)(kc ^ (m & 7)) << 4);
            uint32_t aH[4], aL[4];
            LDSM4(aH, H1hi + aoff);
            LDSM4(aL, H1lo + aoff);
            uint32_t bH[2][4], bL[2][4];
#pragma unroll
            for (int ntp = 0; ntp < 2; ntp++) {
                int k = ks * 16 + (mtx & 1) * 8 + rin;
                int nch = (nc >> 3) + ntp * 2 + (mtx >> 1);
                uint32_t boff = (uint32_t)k * 128 + ((uint32_t)(nch ^ (k & 7)) << 4);
                LDSM4T(bH[ntp], W2hi + boff);
                LDSM4T(bL[ntp], W2lo + boff);
            }
#pragma unroll
            for (int nt = 0; nt < 4; nt++) {
                MMA16816(acc[nt], aH, bH[nt >> 1][(nt & 1) * 2], bH[nt >> 1][(nt & 1) * 2 + 1]);
                MMA16816(acc[nt], aH, bL[nt >> 1][(nt & 1) * 2], bL[nt >> 1][(nt & 1) * 2 + 1]);
                MMA16816(acc[nt], aL, bH[nt >> 1][(nt & 1) * 2], bH[nt >> 1][(nt & 1) * 2 + 1]);
            }
        }
#pragma unroll
        for (int nt = 0; nt < 4; nt++) {
            int col = nc + nt * 8 + lc * 2;
            float s0 = silu(acc[nt][0] + sB2[col]);
            float s1 = silu(acc[nt][1] + sB2[col + 1]);
            float s2 = silu(acc[nt][2] + sB2[col]);
            float s3 = silu(acc[nt][3] + sB2[col + 1]);
            int r0 = mr + lr, r1 = r0 + 8;
            uint32_t hi, lo;
            uint32_t ad0 = (uint32_t)r0 * 128 + ((uint32_t)((col >> 3) ^ (r0 & 7)) << 4) + (col & 7) * 2;
            split2(s0, s1, hi, lo); STS32(H2hi + ad0, hi); STS32(H2lo + ad0, lo);
            uint32_t ad1 = (uint32_t)r1 * 128 + ((uint32_t)((col >> 3) ^ (r1 & 7)) << 4) + (col & 7) * 2;
            split2(s2, s3, hi, lo); STS32(H2hi + ad1, hi); STS32(H2lo + ad1, lo);
        }
    }
    __syncthreads();

    // ---------------- layer3: rad = H2 @ W3 + b3  [128x128, K=64] (regs) ----
    float acc3[8][4];
#pragma unroll
    for (int i = 0; i < 8; i++)
#pragma unroll
        for (int j = 0; j < 4; j++) acc3[i][j] = 0.0f;
    {
        const int nc = ni1 * 64;
#pragma unroll
        for (int ks = 0; ks < 4; ks++) {
            int m = mr + (mtx & 1) * 8 + rin;
            int kc = ks * 2 + (mtx >> 1);
            uint32_t aoff = (uint32_t)m * 128 + ((uint32_t)(kc ^ (m & 7)) << 4);
            uint32_t aH[4], aL[4];
            LDSM4(aH, H2hi + aoff);
            LDSM4(aL, H2lo + aoff);
            uint32_t bH[4][4];
#pragma unroll
            for (int ntp = 0; ntp < 4; ntp++) {
                int k = ks * 16 + (mtx & 1) * 8 + rin;
                int nch = (nc >> 3) + ntp * 2 + (mtx >> 1);
                uint32_t boff = (uint32_t)k * 256 + ((uint32_t)(nch ^ (k & 7)) << 4);
                LDSM4T(bH[ntp], W3hi + boff);
            }
#pragma unroll
            for (int nt = 0; nt < 8; nt++) {
                MMA16816(acc3[nt], aH, bH[nt >> 1][(nt & 1) * 2], bH[nt >> 1][(nt & 1) * 2 + 1]);
                MMA16816(acc3[nt], aL, bH[nt >> 1][(nt & 1) * 2], bH[nt >> 1][(nt & 1) * 2 + 1]);
            }
            uint32_t bL[4][4];
#pragma unroll
            for (int ntp = 0; ntp < 4; ntp++) {
                int k = ks * 16 + (mtx & 1) * 8 + rin;
                int nch = (nc >> 3) + ntp * 2 + (mtx >> 1);
                uint32_t boff = (uint32_t)k * 256 + ((uint32_t)(nch ^ (k & 7)) << 4);
                LDSM4T(bL[ntp], W3lo + boff);
            }
#pragma unroll
            for (int nt = 0; nt < 8; nt++)
                MMA16816(acc3[nt], aH, bL[nt >> 1][(nt & 1) * 2], bL[nt >> 1][(nt & 1) * 2 + 1]);
        }
    }
    __syncthreads();   // all X/H1/H2/W reads done; A & B regions now writable

    // ---------------- gather msgs + form A = (src+dst)*attr*rad -------------
    {
        const int nc = ni1 * 64;
#pragma unroll
        for (int rh = 0; rh < 2; rh++) {
            int r = mr + rh * 8 + lr;
            int src = sSrc[r], dst = sDst[r];
            float at = sAttr[r];
            const float* ps = g_msg_src + (size_t)src * 128;
            const float* pd = g_msg_dst + (size_t)dst * 128;
#pragma unroll
            for (int nt = 0; nt < 8; nt++) {
                int col = nc + nt * 8 + lc * 2;
                float rad0 = acc3[nt][rh * 2 + 0] + sB3[col];
                float rad1 = acc3[nt][rh * 2 + 1] + sB3[col + 1];
                float2 ms = *(const float2*)(ps + col);
                float2 md = *(const float2*)(pd + col);
                float m0 = (ms.x + md.x) * at * rad0;
                float m1 = (ms.y + md.y) * at * rad1;
                uint32_t hi, lo; split2(m0, m1, hi, lo);
                uint32_t ad = (uint32_t)r * 256 + ((uint32_t)((col >> 3) ^ (r & 7)) << 4) + (col & 7) * 2;
                STS32(Ahi + ad, hi); STS32(Alo + ad, lo);
            }
        }
    }

    // ---------------- stage B = w_sep [k][n] single fp16 ---------------------
#pragma unroll 4
    for (int it = 0; it < 16; it++) {
        int idx = tid + 512 * it;            // (k, n/4)
        int k = idx >> 6, n4 = (idx & 63) << 2;
        float4 v = *(const float4*)(w_sep + (size_t)k * 256 + n4);
        uint32_t hA = packh2(v.x, v.y), hB = packh2(v.z, v.w);
        uint32_t addr = (uint32_t)k * 512 + ((uint32_t)((n4 >> 3) ^ (k & 7)) << 4) + (n4 & 7) * 2;
        STS64(Bsm + addr, hA, hB);
    }
    __syncthreads();

    // ---------------- phase2: D[128,256] = (Ah+Al) @ B + epilogue -----------
    const int mi = wid & 3, ni = wid >> 2;
    const int mrow0 = mi * 32, ncol0 = ni * 64;

    float d[2][8][4];
#pragma unroll
    for (int a = 0; a < 2; a++)
#pragma unroll
        for (int b = 0; b < 8; b++)
#pragma unroll
            for (int c = 0; c < 4; c++) d[a][b][c] = 0.0f;

#pragma unroll
    for (int ks = 0; ks < 8; ks++) {
        uint32_t ah[2][4];
#pragma unroll
        for (int mt = 0; mt < 2; mt++) {
            int m = mrow0 + mt * 16 + (mtx & 1) * 8 + rin;
            int kchunk = ks * 2 + (mtx >> 1);
            LDSM4(ah[mt], Ahi + (uint32_t)m * 256 + ((uint32_t)(kchunk ^ (m & 7)) << 4));
        }
        uint32_t b[4][4];
#pragma unroll
        for (int ntp = 0; ntp < 4; ntp++) {
            int k = ks * 16 + (mtx & 1) * 8 + rin;
            int nchunk = (ncol0 >> 3) + ntp * 2 + (mtx >> 1);
            LDSM4T(b[ntp], Bsm + (uint32_t)k * 512 + ((uint32_t)(nchunk ^ (k & 7)) << 4));
        }
#pragma unroll
        for (int mt = 0; mt < 2; mt++)
#pragma unroll
            for (int nt = 0; nt < 8; nt++)
                MMA16816(d[mt][nt], ah[mt], b[nt >> 1][(nt & 1) * 2], b[nt >> 1][(nt & 1) * 2 + 1]);
        uint32_t al[2][4];
#pragma unroll
        for (int mt = 0; mt < 2; mt++) {
            int m = mrow0 + mt * 16 + (mtx & 1) * 8 + rin;
            int kchunk = ks * 2 + (mtx >> 1);
            LDSM4(al[mt], Alo + (uint32_t)m * 256 + ((uint32_t)(kchunk ^ (m & 7)) << 4));
        }
#pragma unroll
        for (int mt = 0; mt < 2; mt++)
#pragma unroll
            for (int nt = 0; nt < 8; nt++)
                MMA16816(d[mt][nt], al[mt], b[nt >> 1][(nt & 1) * 2], b[nt >> 1][(nt & 1) * 2 + 1]);
    }

    // ---- epilogue: w = exp(score); direct segment reduction ----
#pragma unroll
    for (int hh = 0; hh < 2; hh++) {
        const int h = ni * 2 + hh;
#pragma unroll
        for (int mt = 0; mt < 2; mt++) {
            const int r0i = mrow0 + mt * 16 + lr;
            const int e0i = e0 + r0i;
            float p0 = 0.0f, p1 = 0.0f;
#pragma unroll
            for (int q = 0; q < 2; q++) {
                const int nt = hh * 4 + q;
                const int colb = ncol0 + nt * 8 + lc * 2;
                const int jb = q * 8 + lc * 2;
                const float bb0 = sBsep[colb], bb1 = sBsep[colb + 1];
                const float w0 = sAD[h * 16 + jb], w1 = sAD[h * 16 + jb + 1];
                float x, sg;
                x = d[mt][nt][0] + bb0; sg = 1.0f / (1.0f + __expf(-x)); p0 += x * (0.2f + 0.8f * sg) * w0;
                x = d[mt][nt][1] + bb1; sg = 1.0f / (1.0f + __expf(-x)); p0 += x * (0.2f + 0.8f * sg) * w1;
                x = d[mt][nt][2] + bb0; sg = 1.0f / (1.0f + __expf(-x)); p1 += x * (0.2f + 0.8f * sg) * w0;
                x = d[mt][nt][3] + bb1; sg = 1.0f / (1.0f + __expf(-x)); p1 += x * (0.2f + 0.8f * sg) * w1;
            }
            // full butterfly: every lane in the quad gets the total
            p0 += __shfl_xor_sync(0xffffffffu, p0, 1);
            p0 += __shfl_xor_sync(0xffffffffu, p0, 2);
            p1 += __shfl_xor_sync(0xffffffffu, p1, 1);
            p1 += __shfl_xor_sync(0xffffffffu, p1, 2);
            const float ew0 = __expf(p0), ew1 = __expf(p1);
            const int d0 = sDst[r0i], d1 = sDst[r0i + 8];
            if (lc == 0) {
                if (e0i < E)     atomicAdd(&g_nsum[(size_t)d0 * 8 + h], ew0);
                if (e0i + 8 < E) atomicAdd(&g_nsum[(size_t)d1 * 8 + h], ew1);
            }
#pragma unroll
            for (int q = 0; q < 2; q++) {
                const int nt = hh * 4 + 2 + q;
                const int colb = ncol0 + nt * 8 + lc * 2;
                const int vidx = q * 8 + lc * 2;
                const float bb0 = sBsep[colb], bb1 = sBsep[colb + 1];
                if (e0i < E)
                    RED2(g_nacc + (size_t)d0 * 128 + h * 16 + vidx,
                         (d[mt][nt][0] + bb0) * ew0, (d[mt][nt][1] + bb1) * ew0);
                if (e0i + 8 < E)
                    RED2(g_nacc + (size_t)d1 * 128 + h * 16 + vidx,
                         (d[mt][nt][2] + bb0) * ew1, (d[mt][nt][3] + bb1) * ew1);
            }
        }
    }
}

// ---------------- K5: out = (nacc / (nsum+eps)) @ w_proj + b_proj -----------
__global__ __launch_bounds__(256) void out_gemm_kernel(
    const float* __restrict__ W, const float* __restrict__ bias,
    float* __restrict__ out, int n)
{
    __shared__ float At[32 * 64];
    __shared__ float Bs[32 * 128];
    int tid = threadIdx.x;
    int r0 = blockIdx.x * 64;
    int cg = tid & 15, rg = tid >> 4;
    int col = cg * 8, row = rg * 4;

    float acc[4][8];
#pragma unroll
    for (int i = 0; i < 4; i++)
#pragma unroll
        for (int j = 0; j < 8; j++) acc[i][j] = 0.0f;

    int lm = tid >> 2, lk = (tid & 3) * 8;
    int lkr = tid >> 3, lc = (tid & 7) * 16;

    for (int k0 = 0; k0 < 128; k0 += 32) {
        float4 a0, a1;
        int gr = r0 + lm;
        if (gr < n) {
            a0 = *(const float4*)(g_nacc + (size_t)gr * 128 + k0 + lk);
            a1 = *(const float4*)(g_nacc + (size_t)gr * 128 + k0 + lk + 4);
            int hh = (k0 + lk) >> 4;
            float inv = 1.0f / (g_nsum[(size_t)gr * 8 + hh] + 1e-16f);
            a0.x *= inv; a0.y *= inv; a0.z *= inv; a0.w *= inv;
            a1.x *= inv; a1.y *= inv; a1.z *= inv; a1.w *= inv;
        } else {
            a0 = make_float4(0.f, 0.f, 0.f, 0.f); a1 = a0;
        }
        At[(lk + 0) * 64 + lm] = a0.x; At[(lk + 1) * 64 + lm] = a0.y;
        At[(lk + 2) * 64 + lm] = a0.z; At[(lk + 3) * 64 + lm] = a0.w;
        At[(lk + 4) * 64 + lm] = a1.x; At[(lk + 5) * 64 + lm] = a1.y;
        At[(lk + 6) * 64 + lm] = a1.z; At[(lk + 7) * 64 + lm] = a1.w;
#pragma unroll
        for (int q = 0; q < 4; q++)
            *(float4*)(Bs + lkr * 128 + lc + 4 * q) =
                *(const float4*)(W + (size_t)(k0 + lkr) * 128 + lc + 4 * q);
        __syncthreads();
#pragma unroll
        for (int kk = 0; kk < 32; kk++) {
            float a[4], b[8];
            *(float4*)a       = *(float4*)(At + kk * 64 + row);
            *(float4*)(b)     = *(float4*)(Bs + kk * 128 + col);
            *(float4*)(b + 4) = *(float4*)(Bs + kk * 128 + col + 4);
#pragma unroll
            for (int i = 0; i < 4; i++)
#pragma unroll
                for (int j = 0; j < 8; j++) acc[i][j] += a[i] * b[j];
        }
        __syncthreads();
    }

    float bj[8];
    *(float4*)(bj)     = *(const float4*)(bias + col);
    *(float4*)(bj + 4) = *(const float4*)(bias + col + 4);
#pragma unroll
    for (int i = 0; i < 4; i++) {
        int gr = r0 + row + i;
        if (gr >= n) continue;
        float4 o0 = make_float4(acc[i][0] + bj[0], acc[i][1] + bj[1],
                                acc[i][2] + bj[2], acc[i][3] + bj[3]);
        float4 o1 = make_float4(acc[i][4] + bj[4], acc[i][5] + bj[5],
                                acc[i][6] + bj[6], acc[i][7] + bj[7]);
        *(float4*)(out + (size_t)gr * 128 + col)     = o0;
        *(float4*)(out + (size_t)gr * 128 + col + 4) = o1;
    }
}

// ---------------- launch ----------------
extern "C" void kernel_launch(void* const* d_in, const int* in_sizes, int n_in,
                              void* d_out, int out_size)
{
    const float* node_input = (const float*)d_in[0];
    const float* edge_attr  = (const float*)d_in[2];
    const float* edge_scal  = (const float*)d_in[3];
    const int*   edge_src   = (const int*)d_in[4];
    const int*   edge_dst   = (const int*)d_in[5];
    const float* w_src      = (const float*)d_in[7];
    const float* b_src      = (const float*)d_in[8];
    const float* w_dst      = (const float*)d_in[9];
    const float* fc_w1      = (const float*)d_in[10];
    const float* fc_b1      = (const float*)d_in[11];
    const float* fc_w2      = (const float*)d_in[12];
    const float* fc_b2      = (const float*)d_in[13];
    const float* fc_w3      = (const float*)d_in[14];
    const float* fc_b3      = (const float*)d_in[15];
    const float* w_sep      = (const float*)d_in[16];
    const float* b_sep      = (const float*)d_in[17];
    const float* alpha_dot  = (const float*)d_in[18];
    const float* w_proj     = (const float*)d_in[19];
    const float* b_proj     = (const float*)d_in[20];
    float* out = (float*)d_out;

    int N = in_sizes[0] / 128;
    int E = in_sizes[4];

    cudaFuncSetAttribute(fused_edge_kernel, cudaFuncAttributeMaxDynamicSharedMemorySize, 155648);

    init_kernel<<<(N * 128 + 255) / 256, 256>>>(N);

    int nb = (N + 63) / 64;
    node_gemm_dual<<<nb, 256>>>(node_input, w_src, w_dst, b_src, N);

    int tb = (E + 127) / 128;
    fused_edge_kernel<<<tb, 512, 155648>>>(edge_scal, edge_attr, edge_src, edge_dst,
                                           fc_w1, fc_b1, fc_w2, fc_b2, fc_w3, fc_b3,
                                           w_sep, b_sep, alpha_dot, E);

    out_gemm_kernel<<<nb, 256>>>(w_proj, b_proj, out, N);
}

// round 8
// speedup vs baseline: 4.2512x; 1.1181x over previous
#include <cuda_runtime.h>
#include <cuda_fp16.h>
#include <cstdint>
#include <math.h>

// ---------------- fixed problem geometry ----------------
#define MAXN 50000
#define MAXE 800000
// C=128, A_ALL=256, RAD_IN=32, FC1=FC2=64, H=8, AH=VH=16

// ---------------- scratch ----------------
__device__ __align__(16) float g_msg_src[(size_t)MAXN * 128];
__device__ __align__(16) float g_msg_dst[(size_t)MAXN * 128];
__device__ __align__(16) float g_nsum[(size_t)MAXN * 8];
__device__ __align__(16) float g_nacc[(size_t)MAXN * 128];
// prepacked fp16 weight images (exact SMEM layouts, swizzled)
__device__ __align__(16) unsigned char g_Bimg[65536];   // w_sep [k][n] fp16
__device__ __align__(16) unsigned char g_W1img[8192];   // hi @0, lo @4096
__device__ __align__(16) unsigned char g_W2img[16384];  // hi @0, lo @8192
__device__ __align__(16) unsigned char g_W3img[32768];  // hi @0, lo @16384

// ---------------- helpers ----------------
__device__ __forceinline__ uint32_t smem_u32(const void* p) {
    uint32_t a;
    asm("{ .reg .u64 t; cvta.to.shared.u64 t, %1; cvt.u32.u64 %0, t; }"
        : "=r"(a) : "l"(p));
    return a;
}

#define LDSM4(r, addr) \
    asm volatile("ldmatrix.sync.aligned.m8n8.x4.shared.b16 {%0,%1,%2,%3}, [%4];" \
        : "=r"((r)[0]), "=r"((r)[1]), "=r"((r)[2]), "=r"((r)[3]) : "r"(addr))

#define LDSM4T(r, addr) \
    asm volatile("ldmatrix.sync.aligned.m8n8.x4.trans.shared.b16 {%0,%1,%2,%3}, [%4];" \
        : "=r"((r)[0]), "=r"((r)[1]), "=r"((r)[2]), "=r"((r)[3]) : "r"(addr))

#define MMA16816(d, a, b0v, b1v) \
    asm volatile("mma.sync.aligned.m16n8k16.row.col.f32.f16.f16.f32 " \
        "{%0,%1,%2,%3}, {%4,%5,%6,%7}, {%8,%9}, {%0,%1,%2,%3};" \
        : "+f"((d)[0]), "+f"((d)[1]), "+f"((d)[2]), "+f"((d)[3]) \
        : "r"((a)[0]), "r"((a)[1]), "r"((a)[2]), "r"((a)[3]), "r"(b0v), "r"(b1v))

#define STS32(addr, v) \
    asm volatile("st.shared.b32 [%0], %1;" :: "r"(addr), "r"(v))
#define STS64(addr, v0, v1) \
    asm volatile("st.shared.v2.b32 [%0], {%1,%2};" :: "r"(addr), "r"(v0), "r"(v1))
#define STS128(addr, v) \
    asm volatile("st.shared.v4.b32 [%0], {%1,%2,%3,%4};" \
        :: "r"(addr), "r"((v).x), "r"((v).y), "r"((v).z), "r"((v).w))

// vector fire-and-forget global reduction (sm_90+)
#define RED2(ptr, x, y) \
    asm volatile("red.global.add.v2.f32 [%0], {%1,%2};" :: "l"(ptr), "f"(x), "f"(y) : "memory")

__device__ __forceinline__ uint32_t packh2(float x, float y) {
    __half2 t = __floats2half2_rn(x, y);
    return *(uint32_t*)&t;
}
__device__ __forceinline__ void split2(float x, float y, uint32_t& hi, uint32_t& lo) {
    __half h0 = __float2half_rn(x), h1 = __float2half_rn(y);
    __half2 hh = __halves2half2(h0, h1);
    hi = *(uint32_t*)&hh;
    lo = packh2(x - __half2float(h0), y - __half2float(h1));
}
__device__ __forceinline__ void split4(float4 v, uint32_t& hA, uint32_t& hB,
                                       uint32_t& lA, uint32_t& lB) {
    split2(v.x, v.y, hA, lA);
    split2(v.z, v.w, hB, lB);
}
__device__ __forceinline__ float silu(float x) {
    return x / (1.0f + __expf(-x));
}

// ---------------- K0: init segment buffers ----------------
__global__ void init_kernel(int n) {
    int i = blockIdx.x * blockDim.x + threadIdx.x;
    if (i < n * 128) g_nacc[i] = 0.0f;
    if (i < n * 8) g_nsum[i] = 0.0f;
}

// ---------------- K0b: prepack weight images (fp16, swizzled SMEM layout) --
__global__ void prep_kernel(const float* __restrict__ w1, const float* __restrict__ w2,
                            const float* __restrict__ w3, const float* __restrict__ w_sep)
{
    int idx = blockIdx.x * blockDim.x + threadIdx.x;  // float4 units
    if (idx < 8192) {                       // w_sep: 128 x 256, rows 512B
        int k = idx >> 6, n4 = (idx & 63) << 2;
        float4 v = *(const float4*)(w_sep + (size_t)k * 256 + n4);
        uint32_t hA = packh2(v.x, v.y), hB = packh2(v.z, v.w);
        uint32_t addr = (uint32_t)k * 512 + ((uint32_t)((n4 >> 3) ^ (k & 7)) << 4) + (n4 & 7) * 2;
        *(uint2*)(g_Bimg + addr) = make_uint2(hA, hB);
    } else if (idx < 8704) {                // w1: 32 x 64, rows 128B
        int i = idx - 8192;
        int k = i >> 4, n4 = (i & 15) << 2;
        float4 v = *(const float4*)(w1 + (size_t)k * 64 + n4);
        uint32_t hA, hB, lA, lB; split4(v, hA, hB, lA, lB);
        uint32_t addr = (uint32_t)k * 128 + ((uint32_t)((n4 >> 3) ^ (k & 7)) << 4) + (n4 & 7) * 2;
        *(uint2*)(g_W1img + addr) = make_uint2(hA, hB);
        *(uint2*)(g_W1img + 4096 + addr) = make_uint2(lA, lB);
    } else if (idx < 9728) {                // w2: 64 x 64, rows 128B
        int i = idx - 8704;
        int k = i >> 4, n4 = (i & 15) << 2;
        float4 v = *(const float4*)(w2 + (size_t)k * 64 + n4);
        uint32_t hA, hB, lA, lB; split4(v, hA, hB, lA, lB);
        uint32_t addr = (uint32_t)k * 128 + ((uint32_t)((n4 >> 3) ^ (k & 7)) << 4) + (n4 & 7) * 2;
        *(uint2*)(g_W2img + addr) = make_uint2(hA, hB);
        *(uint2*)(g_W2img + 8192 + addr) = make_uint2(lA, lB);
    } else if (idx < 11776) {               // w3: 64 x 128, rows 256B
        int i = idx - 9728;
        int k = i >> 5, n4 = (i & 31) << 2;
        float4 v = *(const float4*)(w3 + (size_t)k * 128 + n4);
        uint32_t hA, hB, lA, lB; split4(v, hA, hB, lA, lB);
        uint32_t addr = (uint32_t)k * 256 + ((uint32_t)((n4 >> 3) ^ (k & 7)) << 4) + (n4 & 7) * 2;
        *(uint2*)(g_W3img + addr) = make_uint2(hA, hB);
        *(uint2*)(g_W3img + 16384 + addr) = make_uint2(lA, lB);
    }
}

// ---------------- K1: dual node GEMM  msg_src/msg_dst = X @ {w_src,w_dst} ---
__global__ __launch_bounds__(256) void node_gemm_dual(
    const float* __restrict__ X, const float* __restrict__ Wsrc,
    const float* __restrict__ Wdst, const float* __restrict__ bias_src, int n)
{
    __shared__ float At[32 * 64];
    __shared__ float Bs0[32 * 128];
    __shared__ float Bs1[32 * 128];
    int tid = threadIdx.x;
    int r0 = blockIdx.x * 64;
    int cg = tid & 15, rg = tid >> 4;
    int col = cg * 8, row = rg * 4;

    float acc0[4][8], acc1[4][8];
#pragma unroll
    for (int i = 0; i < 4; i++)
#pragma unroll
        for (int j = 0; j < 8; j++) { acc0[i][j] = 0.0f; acc1[i][j] = 0.0f; }

    int lm = tid >> 2, lk = (tid & 3) * 8;
    int lkr = tid >> 3, lc = (tid & 7) * 16;

    for (int k0 = 0; k0 < 128; k0 += 32) {
        float4 a0, a1;
        int gr = r0 + lm;
        if (gr < n) {
            a0 = *(const float4*)(X + (size_t)gr * 128 + k0 + lk);
            a1 = *(const float4*)(X + (size_t)gr * 128 + k0 + lk + 4);
        } else {
            a0 = make_float4(0.f, 0.f, 0.f, 0.f); a1 = a0;
        }
        At[(lk + 0) * 64 + lm] = a0.x; At[(lk + 1) * 64 + lm] = a0.y;
        At[(lk + 2) * 64 + lm] = a0.z; At[(lk + 3) * 64 + lm] = a0.w;
        At[(lk + 4) * 64 + lm] = a1.x; At[(lk + 5) * 64 + lm] = a1.y;
        At[(lk + 6) * 64 + lm] = a1.z; At[(lk + 7) * 64 + lm] = a1.w;
#pragma unroll
        for (int q = 0; q < 4; q++) {
            *(float4*)(Bs0 + lkr * 128 + lc + 4 * q) =
                *(const float4*)(Wsrc + (size_t)(k0 + lkr) * 128 + lc + 4 * q);
            *(float4*)(Bs1 + lkr * 128 + lc + 4 * q) =
                *(const float4*)(Wdst + (size_t)(k0 + lkr) * 128 + lc + 4 * q);
        }
        __syncthreads();
#pragma unroll
        for (int kk = 0; kk < 32; kk++) {
            float a[4], b0[8], b1[8];
            *(float4*)a        = *(float4*)(At + kk * 64 + row);
            *(float4*)(b0)     = *(float4*)(Bs0 + kk * 128 + col);
            *(float4*)(b0 + 4) = *(float4*)(Bs0 + kk * 128 + col + 4);
            *(float4*)(b1)     = *(float4*)(Bs1 + kk * 128 + col);
            *(float4*)(b1 + 4) = *(float4*)(Bs1 + kk * 128 + col + 4);
#pragma unroll
            for (int i = 0; i < 4; i++)
#pragma unroll
                for (int j = 0; j < 8; j++) {
                    acc0[i][j] += a[i] * b0[j];
                    acc1[i][j] += a[i] * b1[j];
                }
        }
        __syncthreads();
    }

    float bj[8];
    *(float4*)bj       = *(const float4*)(bias_src + col);
    *(float4*)(bj + 4) = *(const float4*)(bias_src + col + 4);
#pragma unroll
    for (int i = 0; i < 4; i++) {
        int gr = r0 + row + i;
        if (gr >= n) continue;
        *(float4*)(g_msg_src + (size_t)gr * 128 + col) =
            make_float4(acc0[i][0] + bj[0], acc0[i][1] + bj[1],
                        acc0[i][2] + bj[2], acc0[i][3] + bj[3]);
        *(float4*)(g_msg_src + (size_t)gr * 128 + col + 4) =
            make_float4(acc0[i][4] + bj[4], acc0[i][5] + bj[5],
                        acc0[i][6] + bj[6], acc0[i][7] + bj[7]);
        *(float4*)(g_msg_dst + (size_t)gr * 128 + col) =
            make_float4(acc1[i][0], acc1[i][1], acc1[i][2], acc1[i][3]);
        *(float4*)(g_msg_dst + (size_t)gr * 128 + col + 4) =
            make_float4(acc1[i][4], acc1[i][5], acc1[i][6], acc1[i][7]);
    }
}

// ============================================================================
// K23: FUSED radial-MLP + gather + w_sep GEMM + softmax-free attention scatter
// 128 edges per CTA, 512 threads (16 warps). fp16 HMMA.
//  MLP GEMMs: 3-pass error-compensated; w_sep GEMM: single-pass (A fp16, B fp16).
//  Weights staged from prepacked fp16 global images (uint4 copies).
//
// Dynamic SMEM (155648 B), phase-aliased:
//  phase2:  A[0,32K)  B[32K,96K)
//  phase1:  W3 hi/lo [0,32K) | H1 hi/lo [32K,64K) | X hi/lo [64K,96K)
//           W1 hi/lo [96K,104K) | W2 hi/lo [104K,120K) | H2 hi/lo [120K,152K)
// ============================================================================
__global__ __launch_bounds__(512, 1) void fused_edge_kernel(
    const float* __restrict__ edge_scalars, const float* __restrict__ edge_attr,
    const int* __restrict__ edge_src, const int* __restrict__ edge_dst,
    const float* __restrict__ b1, const float* __restrict__ b2,
    const float* __restrict__ b3, const float* __restrict__ b_sep,
    const float* __restrict__ alpha_dot, int E)
{
    extern __shared__ char dynsm[];
    __shared__ float sB1[64], sB2[64], sB3[128];
    __shared__ float sBsep[256], sAD[128];
    __shared__ int   sSrc[128], sDst[128];
    __shared__ float sAttr[128];

    const int tid = threadIdx.x;
    const int wid = tid >> 5, lane = tid & 31;
    const int e0 = blockIdx.x * 128;
    const int mtx = lane >> 3, rin = lane & 7;
    const int lr = lane >> 2, lc = lane & 3;

    const uint32_t sb = smem_u32(dynsm);
    // phase2 regions
    const uint32_t Asm = sb, Bsm = sb + 32768;
    // phase1 regions
    const uint32_t W3hi = sb,          W3lo = sb + 16384;
    const uint32_t H1hi = sb + 32768,  H1lo = sb + 49152;
    const uint32_t Xhi  = sb + 65536,  Xlo  = sb + 81920;
    const uint32_t W1hi = sb + 98304;
    const uint32_t W2hi = sb + 106496;
    const uint32_t H2hi = sb + 122880, H2lo = sb + 139264;

    // ---------------- stage phase-1 inputs ----------------
    if (tid < 64)  { sB1[tid] = b1[tid]; sB2[tid] = b2[tid]; }
    if (tid < 128) { sB3[tid] = b3[tid]; sAD[tid] = alpha_dot[tid]; }
    if (tid < 256) sBsep[tid] = b_sep[tid];
    if (tid < 128) {
        int e = min(e0 + tid, E - 1);
        sSrc[tid] = edge_src[e];
        sDst[tid] = edge_dst[e];
        sAttr[tid] = (e0 + tid < E) ? edge_attr[e] : 0.0f;
    }
    // X: 128 x 32 fp32 (1024 float4), hi/lo split
#pragma unroll
    for (int it = 0; it < 2; it++) {
        int i = tid + 512 * it;
        int m = i >> 3, k4 = (i & 7) << 2;
        int e = min(e0 + m, E - 1);
        float4 v = *(const float4*)(edge_scalars + (size_t)e * 32 + k4);
        uint32_t hA, hB, lA, lB; split4(v, hA, hB, lA, lB);
        uint32_t addr = (uint32_t)m * 128 + ((uint32_t)(((k4 >> 3) ^ (m & 7))) << 4) + (k4 & 7) * 2;
        STS64(Xhi + addr, hA, hB);
        STS64(Xlo + addr, lA, lB);
    }
    // weights: linear uint4 copies from prepacked images (hi+lo contiguous)
    {   // W1: 512 uint4
        uint4 v = *(const uint4*)(g_W1img + tid * 16);
        STS128(W1hi + tid * 16, v);
    }
#pragma unroll
    for (int it = 0; it < 2; it++) {  // W2: 1024 uint4
        int i = tid + 512 * it;
        uint4 v = *(const uint4*)(g_W2img + i * 16);
        STS128(W2hi + i * 16, v);
    }
#pragma unroll
    for (int it = 0; it < 4; it++) {  // W3: 2048 uint4
        int i = tid + 512 * it;
        uint4 v = *(const uint4*)(g_W3img + i * 16);
        STS128(W3hi + i * 16, v);
    }
    __syncthreads();

    // warp tile for MLP: 8 M-tiles x 2 N-tiles
    const int mi1 = wid & 7, ni1 = wid >> 3;
    const int mr = mi1 * 16;

    // ---------------- layer1: H1 = silu(X @ W1 + b1)  [128x64, K=32] --------
    {
        const int nc = ni1 * 32;
        float acc[4][4];
#pragma unroll
        for (int i = 0; i < 4; i++)
#pragma unroll
            for (int j = 0; j < 4; j++) acc[i][j] = 0.0f;
#pragma unroll
        for (int ks = 0; ks < 2; ks++) {
            int m = mr + (mtx & 1) * 8 + rin;
            int kc = ks * 2 + (mtx >> 1);
            uint32_t aoff = (uint32_t)m * 128 + ((uint32_t)(kc ^ (m & 7)) << 4);
            uint32_t aH[4], aL[4];
            LDSM4(aH, Xhi + aoff);
            LDSM4(aL, Xlo + aoff);
            uint32_t bH[2][4], bL[2][4];
#pragma unroll
            for (int ntp = 0; ntp < 2; ntp++) {
                int k = ks * 16 + (mtx & 1) * 8 + rin;
                int nch = (nc >> 3) + ntp * 2 + (mtx >> 1);
                uint32_t boff = (uint32_t)k * 128 + ((uint32_t)(nch ^ (k & 7)) << 4);
                LDSM4T(bH[ntp], W1hi + boff);
                LDSM4T(bL[ntp], W1hi + 4096 + boff);
            }
#pragma unroll
            for (int nt = 0; nt < 4; nt++) {
                MMA16816(acc[nt], aH, bH[nt >> 1][(nt & 1) * 2], bH[nt >> 1][(nt & 1) * 2 + 1]);
                MMA16816(acc[nt], aH, bL[nt >> 1][(nt & 1) * 2], bL[nt >> 1][(nt & 1) * 2 + 1]);
                MMA16816(acc[nt], aL, bH[nt >> 1][(nt & 1) * 2], bH[nt >> 1][(nt & 1) * 2 + 1]);
            }
        }
#pragma unroll
        for (int nt = 0; nt < 4; nt++) {
            int col = nc + nt * 8 + lc * 2;
            float s0 = silu(acc[nt][0] + sB1[col]);
            float s1 = silu(acc[nt][1] + sB1[col + 1]);
            float s2 = silu(acc[nt][2] + sB1[col]);
            float s3 = silu(acc[nt][3] + sB1[col + 1]);
            int r0 = mr + lr, r1 = r0 + 8;
            uint32_t hi, lo;
            uint32_t ad0 = (uint32_t)r0 * 128 + ((uint32_t)((col >> 3) ^ (r0 & 7)) << 4) + (col & 7) * 2;
            split2(s0, s1, hi, lo); STS32(H1hi + ad0, hi); STS32(H1lo + ad0, lo);
            uint32_t ad1 = (uint32_t)r1 * 128 + ((uint32_t)((col >> 3) ^ (r1 & 7)) << 4) + (col & 7) * 2;
            split2(s2, s3, hi, lo); STS32(H1hi + ad1, hi); STS32(H1lo + ad1, lo);
        }
    }
    __syncthreads();

    // ---------------- layer2: H2 = silu(H1 @ W2 + b2)  [128x64, K=64] -------
    {
        const int nc = ni1 * 32;
        float acc[4][4];
#pragma unroll
        for (int i = 0; i < 4; i++)
#pragma unroll
            for (int j = 0; j < 4; j++) acc[i][j] = 0.0f;
#pragma unroll
        for (int ks = 0; ks < 4; ks++) {
            int m = mr + (mtx & 1) * 8 + rin;
            int kc = ks * 2 + (mtx >> 1);
            uint32_t aoff = (uint32_t)m * 128 + ((uint32_t)(kc ^ (m & 7)) << 4);
            uint32_t aH[4], aL[4];
            LDSM4(aH, H1hi + aoff);
            LDSM4(aL, H1lo + aoff);
            uint32_t bH[2][4], bL[2][4];
#pragma unroll
            for (int ntp = 0; ntp < 2; ntp++) {
                int k = ks * 16 + (mtx & 1) * 8 + rin;
                int nch = (nc >> 3) + ntp * 2 + (mtx >> 1);
                uint32_t boff = (uint32_t)k * 128 + ((uint32_t)(nch ^ (k & 7)) << 4);
                LDSM4T(bH[ntp], W2hi + boff);
                LDSM4T(bL[ntp], W2hi + 8192 + boff);
            }
#pragma unroll
            for (int nt = 0; nt < 4; nt++) {
                MMA16816(acc[nt], aH, bH[nt >> 1][(nt & 1) * 2], bH[nt >> 1][(nt & 1) * 2 + 1]);
                MMA16816(acc[nt], aH, bL[nt >> 1][(nt & 1) * 2], bL[nt >> 1][(nt & 1) * 2 + 1]);
                MMA16816(acc[nt], aL, bH[nt >> 1][(nt & 1) * 2], bH[nt >> 1][(nt & 1) * 2 + 1]);
            }
        }
#pragma unroll
        for (int nt = 0; nt < 4; nt++) {
            int col = nc + nt * 8 + lc * 2;
            float s0 = silu(acc[nt][0] + sB2[col]);
            float s1 = silu(acc[nt][1] + sB2[col + 1]);
            float s2 = silu(acc[nt][2] + sB2[col]);
            float s3 = silu(acc[nt][3] + sB2[col + 1]);
            int r0 = mr + lr, r1 = r0 + 8;
            uint32_t hi, lo;
            uint32_t ad0 = (uint32_t)r0 * 128 + ((uint32_t)((col >> 3) ^ (r0 & 7)) << 4) + (col & 7) * 2;
            split2(s0, s1, hi, lo); STS32(H2hi + ad0, hi); STS32(H2lo + ad0, lo);
            uint32_t ad1 = (uint32_t)r1 * 128 + ((uint32_t)((col >> 3) ^ (r1 & 7)) << 4) + (col & 7) * 2;
            split2(s2, s3, hi, lo); STS32(H2hi + ad1, hi); STS32(H2lo + ad1, lo);
        }
    }
    __syncthreads();

    // ---------------- layer3: rad = H2 @ W3 + b3  [128x128, K=64] (regs) ----
    float acc3[8][4];
#pragma unroll
    for (int i = 0; i < 8; i++)
#pragma unroll
        for (int j = 0; j < 4; j++) acc3[i][j] = 0.0f;
    {
        const int nc = ni1 * 64;
#pragma unroll
        for (int ks = 0; ks < 4; ks++) {
            int m = mr + (mtx & 1) * 8 + rin;
            int kc = ks * 2 + (mtx >> 1);
            uint32_t aoff = (uint32_t)m * 128 + ((uint32_t)(kc ^ (m & 7)) << 4);
            uint32_t aH[4], aL[4];
            LDSM4(aH, H2hi + aoff);
            LDSM4(aL, H2lo + aoff);
            uint32_t bH[4][4];
#pragma unroll
            for (int ntp = 0; ntp < 4; ntp++) {
                int k = ks * 16 + (mtx & 1) * 8 + rin;
                int nch = (nc >> 3) + ntp * 2 + (mtx >> 1);
                uint32_t boff = (uint32_t)k * 256 + ((uint32_t)(nch ^ (k & 7)) << 4);
                LDSM4T(bH[ntp], W3hi + boff);
            }
#pragma unroll
            for (int nt = 0; nt < 8; nt++) {
                MMA16816(acc3[nt], aH, bH[nt >> 1][(nt & 1) * 2], bH[nt >> 1][(nt & 1) * 2 + 1]);
                MMA16816(acc3[nt], aL, bH[nt >> 1][(nt & 1) * 2], bH[nt >> 1][(nt & 1) * 2 + 1]);
            }
            uint32_t bL[4][4];
#pragma unroll
            for (int ntp = 0; ntp < 4; ntp++) {
                int k = ks * 16 + (mtx & 1) * 8 + rin;
                int nch = (nc >> 3) + ntp * 2 + (mtx >> 1);
                uint32_t boff = (uint32_t)k * 256 + ((uint32_t)(nch ^ (k & 7)) << 4);
                LDSM4T(bL[ntp], W3lo + boff);
            }
#pragma unroll
            for (int nt = 0; nt < 8; nt++)
                MMA16816(acc3[nt], aH, bL[nt >> 1][(nt & 1) * 2], bL[nt >> 1][(nt & 1) * 2 + 1]);
        }
    }
    __syncthreads();   // all X/H1/H2/W reads done; A & B regions now writable

    // ---------------- gather msgs + form A = (src+dst)*attr*rad (fp16) ------
    {
        const int nc = ni1 * 64;
#pragma unroll
        for (int rh = 0; rh < 2; rh++) {
            int r = mr + rh * 8 + lr;
            int src = sSrc[r], dst = sDst[r];
            float at = sAttr[r];
            const float* ps = g_msg_src + (size_t)src * 128;
            const float* pd = g_msg_dst + (size_t)dst * 128;
#pragma unroll
            for (int nt = 0; nt < 8; nt++) {
                int col = nc + nt * 8 + lc * 2;
                float rad0 = acc3[nt][rh * 2 + 0] + sB3[col];
                float rad1 = acc3[nt][rh * 2 + 1] + sB3[col + 1];
                float2 ms = *(const float2*)(ps + col);
                float2 md = *(const float2*)(pd + col);
                float m0 = (ms.x + md.x) * at * rad0;
                float m1 = (ms.y + md.y) * at * rad1;
                uint32_t ad = (uint32_t)r * 256 + ((uint32_t)((col >> 3) ^ (r & 7)) << 4) + (col & 7) * 2;
                STS32(Asm + ad, packh2(m0, m1));
            }
        }
    }

    // ---------------- stage B = prepacked w_sep image (4096 uint4) ----------
#pragma unroll
    for (int it = 0; it < 8; it++) {
        int i = tid + 512 * it;
        uint4 v = *(const uint4*)(g_Bimg + i * 16);
        STS128(Bsm + i * 16, v);
    }
    __syncthreads();

    // ---------------- phase2: D[128,256] = A @ B + epilogue -----------------
    const int mi = wid & 3, ni = wid >> 2;
    const int mrow0 = mi * 32, ncol0 = ni * 64;

    float d[2][8][4];
#pragma unroll
    for (int a = 0; a < 2; a++)
#pragma unroll
        for (int b = 0; b < 8; b++)
#pragma unroll
            for (int c = 0; c < 4; c++) d[a][b][c] = 0.0f;

#pragma unroll
    for (int ks = 0; ks < 8; ks++) {
        uint32_t ah[2][4];
#pragma unroll
        for (int mt = 0; mt < 2; mt++) {
            int m = mrow0 + mt * 16 + (mtx & 1) * 8 + rin;
            int kchunk = ks * 2 + (mtx >> 1);
            LDSM4(ah[mt], Asm + (uint32_t)m * 256 + ((uint32_t)(kchunk ^ (m & 7)) << 4));
        }
        uint32_t b[4][4];
#pragma unroll
        for (int ntp = 0; ntp < 4; ntp++) {
            int k = ks * 16 + (mtx & 1) * 8 + rin;
            int nchunk = (ncol0 >> 3) + ntp * 2 + (mtx >> 1);
            LDSM4T(b[ntp], Bsm + (uint32_t)k * 512 + ((uint32_t)(nchunk ^ (k & 7)) << 4));
        }
#pragma unroll
        for (int mt = 0; mt < 2; mt++)
#pragma unroll
            for (int nt = 0; nt < 8; nt++)
                MMA16816(d[mt][nt], ah[mt], b[nt >> 1][(nt & 1) * 2], b[nt >> 1][(nt & 1) * 2 + 1]);
    }

    // ---- epilogue: w = exp(score); direct segment reduction ----
#pragma unroll
    for (int hh = 0; hh < 2; hh++) {
        const int h = ni * 2 + hh;
#pragma unroll
        for (int mt = 0; mt < 2; mt++) {
            const int r0i = mrow0 + mt * 16 + lr;
            const int e0i = e0 + r0i;
            float p0 = 0.0f, p1 = 0.0f;
#pragma unroll
            for (int q = 0; q < 2; q++) {
                const int nt = hh * 4 + q;
                const int colb = ncol0 + nt * 8 + lc * 2;
                const int jb = q * 8 + lc * 2;
                const float bb0 = sBsep[colb], bb1 = sBsep[colb + 1];
                const float w0 = sAD[h * 16 + jb], w1 = sAD[h * 16 + jb + 1];
                float x, sg;
                x = d[mt][nt][0] + bb0; sg = 1.0f / (1.0f + __expf(-x)); p0 += x * (0.2f + 0.8f * sg) * w0;
                x = d[mt][nt][1] + bb1; sg = 1.0f / (1.0f + __expf(-x)); p0 += x * (0.2f + 0.8f * sg) * w1;
                x = d[mt][nt][2] + bb0; sg = 1.0f / (1.0f + __expf(-x)); p1 += x * (0.2f + 0.8f * sg) * w0;
                x = d[mt][nt][3] + bb1; sg = 1.0f / (1.0f + __expf(-x)); p1 += x * (0.2f + 0.8f * sg) * w1;
            }
            p0 += __shfl_xor_sync(0xffffffffu, p0, 1);
            p0 += __shfl_xor_sync(0xffffffffu, p0, 2);
            p1 += __shfl_xor_sync(0xffffffffu, p1, 1);
            p1 += __shfl_xor_sync(0xffffffffu, p1, 2);
            const float ew0 = __expf(p0), ew1 = __expf(p1);
            const int d0 = sDst[r0i], d1 = sDst[r0i + 8];
            if (lc == 0) {
                if (e0i < E)     atomicAdd(&g_nsum[(size_t)d0 * 8 + h], ew0);
                if (e0i + 8 < E) atomicAdd(&g_nsum[(size_t)d1 * 8 + h], ew1);
            }
#pragma unroll
            for (int q = 0; q < 2; q++) {
                const int nt = hh * 4 + 2 + q;
                const int colb = ncol0 + nt * 8 + lc * 2;
                const int vidx = q * 8 + lc * 2;
                const float bb0 = sBsep[colb], bb1 = sBsep[colb + 1];
                if (e0i < E)
                    RED2(g_nacc + (size_t)d0 * 128 + h * 16 + vidx,
                         (d[mt][nt][0] + bb0) * ew0, (d[mt][nt][1] + bb1) * ew0);
                if (e0i + 8 < E)
                    RED2(g_nacc + (size_t)d1 * 128 + h * 16 + vidx,
                         (d[mt][nt][2] + bb0) * ew1, (d[mt][nt][3] + bb1) * ew1);
            }
        }
    }
}

// ---------------- K5: out = (nacc / (nsum+eps)) @ w_proj + b_proj -----------
__global__ __launch_bounds__(256) void out_gemm_kernel(
    const float* __restrict__ W, const float* __restrict__ bias,
    float* __restrict__ out, int n)
{
    __shared__ float At[32 * 64];
    __shared__ float Bs[32 * 128];
    int tid = threadIdx.x;
    int r0 = blockIdx.x * 64;
    int cg = tid & 15, rg = tid >> 4;
    int col = cg * 8, row = rg * 4;

    float acc[4][8];
#pragma unroll
    for (int i = 0; i < 4; i++)
#pragma unroll
        for (int j = 0; j < 8; j++) acc[i][j] = 0.0f;

    int lm = tid >> 2, lk = (tid & 3) * 8;
    int lkr = tid >> 3, lc = (tid & 7) * 16;

    for (int k0 = 0; k0 < 128; k0 += 32) {
        float4 a0, a1;
        int gr = r0 + lm;
        if (gr < n) {
            a0 = *(const float4*)(g_nacc + (size_t)gr * 128 + k0 + lk);
            a1 = *(const float4*)(g_nacc + (size_t)gr * 128 + k0 + lk + 4);
            int hh = (k0 + lk) >> 4;
            float inv = 1.0f / (g_nsum[(size_t)gr * 8 + hh] + 1e-16f);
            a0.x *= inv; a0.y *= inv; a0.z *= inv; a0.w *= inv;
            a1.x *= inv; a1.y *= inv; a1.z *= inv; a1.w *= inv;
        } else {
            a0 = make_float4(0.f, 0.f, 0.f, 0.f); a1 = a0;
        }
        At[(lk + 0) * 64 + lm] = a0.x; At[(lk + 1) * 64 + lm] = a0.y;
        At[(lk + 2) * 64 + lm] = a0.z; At[(lk + 3) * 64 + lm] = a0.w;
        At[(lk + 4) * 64 + lm] = a1.x; At[(lk + 5) * 64 + lm] = a1.y;
        At[(lk + 6) * 64 + lm] = a1.z; At[(lk + 7) * 64 + lm] = a1.w;
#pragma unroll
        for (int q = 0; q < 4; q++)
            *(float4*)(Bs + lkr * 128 + lc + 4 * q) =
                *(const float4*)(W + (size_t)(k0 + lkr) * 128 + lc + 4 * q);
        __syncthreads();
#pragma unroll
        for (int kk = 0; kk < 32; kk++) {
            float a[4], b[8];
            *(float4*)a       = *(float4*)(At + kk * 64 + row);
            *(float4*)(b)     = *(float4*)(Bs + kk * 128 + col);
            *(float4*)(b + 4) = *(float4*)(Bs + kk * 128 + col + 4);
#pragma unroll
            for (int i = 0; i < 4; i++)
#pragma unroll
                for (int j = 0; j < 8; j++) acc[i][j] += a[i] * b[j];
        }
        __syncthreads();
    }

    float bj[8];
    *(float4*)(bj)     = *(const float4*)(bias + col);
    *(float4*)(bj + 4) = *(const float4*)(bias + col + 4);
#pragma unroll
    for (int i = 0; i < 4; i++) {
        int gr = r0 + row + i;
        if (gr >= n) continue;
        float4 o0 = make_float4(acc[i][0] + bj[0], acc[i][1] + bj[1],
                                acc[i][2] + bj[2], acc[i][3] + bj[3]);
        float4 o1 = make_float4(acc[i][4] + bj[4], acc[i][5] + bj[5],
                                acc[i][6] + bj[6], acc[i][7] + bj[7]);
        *(float4*)(out + (size_t)gr * 128 + col)     = o0;
        *(float4*)(out + (size_t)gr * 128 + col + 4) = o1;
    }
}

// ---------------- launch ----------------
extern "C" void kernel_launch(void* const* d_in, const int* in_sizes, int n_in,
                              void* d_out, int out_size)
{
    const float* node_input = (const float*)d_in[0];
    const float* edge_attr  = (const float*)d_in[2];
    const float* edge_scal  = (const float*)d_in[3];
    const int*   edge_src   = (const int*)d_in[4];
    const int*   edge_dst   = (const int*)d_in[5];
    const float* w_src      = (const float*)d_in[7];
    const float* b_src      = (const float*)d_in[8];
    const float* w_dst      = (const float*)d_in[9];
    const float* fc_w1      = (const float*)d_in[10];
    const float* fc_b1      = (const float*)d_in[11];
    const float* fc_w2      = (const float*)d_in[12];
    const float* fc_b2      = (const float*)d_in[13];
    const float* fc_w3      = (const float*)d_in[14];
    const float* fc_b3      = (const float*)d_in[15];
    const float* w_sep      = (const float*)d_in[16];
    const float* b_sep      = (const float*)d_in[17];
    const float* alpha_dot  = (const float*)d_in[18];
    const float* w_proj     = (const float*)d_in[19];
    const float* b_proj     = (const float*)d_in[20];
    float* out = (float*)d_out;

    int N = in_sizes[0] / 128;
    int E = in_sizes[4];

    cudaFuncSetAttribute(fused_edge_kernel, cudaFuncAttributeMaxDynamicSharedMemorySize, 155648);

    init_kernel<<<(N * 128 + 255) / 256, 256>>>(N);
    prep_kernel<<<46, 256>>>(fc_w1, fc_w2, fc_w3, w_sep);

    int nb = (N + 63) / 64;
    node_gemm_dual<<<nb, 256>>>(node_input, w_src, w_dst, b_src, N);

    int tb = (E + 127) / 128;
    fused_edge_kernel<<<tb, 512, 155648>>>(edge_scal, edge_attr, edge_src, edge_dst,
                                           fc_b1, fc_b2, fc_b3,
                                           b_sep, alpha_dot, E);

    out_gemm_kernel<<<nb, 256>>>(w_proj, b_proj, out, N);
}

// round 9
// speedup vs baseline: 4.4632x; 1.0499x over previous
#include <cuda_runtime.h>
#include <cuda_fp16.h>
#include <cstdint>
#include <math.h>

// ---------------- fixed problem geometry ----------------
#define MAXN 50000
#define MAXE 800000
// C=128, A_ALL=256, RAD_IN=32, FC1=FC2=64, H=8, AH=VH=16

// ---------------- scratch ----------------
__device__ __align__(16) float g_msg_src[(size_t)MAXN * 128];
__device__ __align__(16) float g_msg_dst[(size_t)MAXN * 128];
__device__ __align__(16) float g_nsum[(size_t)MAXN * 8];
__device__ __align__(16) float g_nacc[(size_t)MAXN * 128];
// prepacked fp16 weight images (exact SMEM layouts, swizzled)
__device__ __align__(16) unsigned char g_Bimg[65536];   // w_sep [k][n] fp16
__device__ __align__(16) unsigned char g_W1img[8192];   // hi @0, lo @4096
__device__ __align__(16) unsigned char g_W2img[16384];  // hi @0, lo @8192
__device__ __align__(16) unsigned char g_W3img[32768];  // hi @0, lo @16384

// ---------------- helpers ----------------
__device__ __forceinline__ uint32_t smem_u32(const void* p) {
    uint32_t a;
    asm("{ .reg .u64 t; cvta.to.shared.u64 t, %1; cvt.u32.u64 %0, t; }"
        : "=r"(a) : "l"(p));
    return a;
}

#define LDSM4(r, addr) \
    asm volatile("ldmatrix.sync.aligned.m8n8.x4.shared.b16 {%0,%1,%2,%3}, [%4];" \
        : "=r"((r)[0]), "=r"((r)[1]), "=r"((r)[2]), "=r"((r)[3]) : "r"(addr))

#define LDSM4T(r, addr) \
    asm volatile("ldmatrix.sync.aligned.m8n8.x4.trans.shared.b16 {%0,%1,%2,%3}, [%4];" \
        : "=r"((r)[0]), "=r"((r)[1]), "=r"((r)[2]), "=r"((r)[3]) : "r"(addr))

#define MMA16816(d, a, b0v, b1v) \
    asm volatile("mma.sync.aligned.m16n8k16.row.col.f32.f16.f16.f32 " \
        "{%0,%1,%2,%3}, {%4,%5,%6,%7}, {%8,%9}, {%0,%1,%2,%3};" \
        : "+f"((d)[0]), "+f"((d)[1]), "+f"((d)[2]), "+f"((d)[3]) \
        : "r"((a)[0]), "r"((a)[1]), "r"((a)[2]), "r"((a)[3]), "r"(b0v), "r"(b1v))

#define STS32(addr, v) \
    asm volatile("st.shared.b32 [%0], %1;" :: "r"(addr), "r"(v))
#define STS64(addr, v0, v1) \
    asm volatile("st.shared.v2.b32 [%0], {%1,%2};" :: "r"(addr), "r"(v0), "r"(v1))

// async 16B global->shared copy (sm_80+)
#define CP16(dst, src) \
    asm volatile("{ .reg .u64 g; cvta.to.global.u64 g, %1; " \
                 "cp.async.cg.shared.global [%0], [g], 16; }" \
                 :: "r"(dst), "l"(src) : "memory")
#define CP_COMMIT() asm volatile("cp.async.commit_group;" ::: "memory")
#define CP_WAIT(n)  asm volatile("cp.async.wait_group %0;" :: "n"(n) : "memory")

// vector fire-and-forget global reduction (sm_90+)
#define RED2(ptr, x, y) \
    asm volatile("red.global.add.v2.f32 [%0], {%1,%2};" :: "l"(ptr), "f"(x), "f"(y) : "memory")

__device__ __forceinline__ uint32_t packh2(float x, float y) {
    __half2 t = __floats2half2_rn(x, y);
    return *(uint32_t*)&t;
}
__device__ __forceinline__ void split2(float x, float y, uint32_t& hi, uint32_t& lo) {
    __half h0 = __float2half_rn(x), h1 = __float2half_rn(y);
    __half2 hh = __halves2half2(h0, h1);
    hi = *(uint32_t*)&hh;
    lo = packh2(x - __half2float(h0), y - __half2float(h1));
}
__device__ __forceinline__ void split4(float4 v, uint32_t& hA, uint32_t& hB,
                                       uint32_t& lA, uint32_t& lB) {
    split2(v.x, v.y, hA, lA);
    split2(v.z, v.w, hB, lB);
}
__device__ __forceinline__ float silu(float x) {
    return x / (1.0f + __expf(-x));
}

// ---------------- K0: init segment buffers ----------------
__global__ void init_kernel(int n) {
    int i = blockIdx.x * blockDim.x + threadIdx.x;
    if (i < n * 128) g_nacc[i] = 0.0f;
    if (i < n * 8) g_nsum[i] = 0.0f;
}

// ---------------- K0b: prepack weight images (fp16, swizzled SMEM layout) --
__global__ void prep_kernel(const float* __restrict__ w1, const float* __restrict__ w2,
                            const float* __restrict__ w3, const float* __restrict__ w_sep)
{
    int idx = blockIdx.x * blockDim.x + threadIdx.x;  // float4 units
    if (idx < 8192) {                       // w_sep: 128 x 256, rows 512B
        int k = idx >> 6, n4 = (idx & 63) << 2;
        float4 v = *(const float4*)(w_sep + (size_t)k * 256 + n4);
        uint32_t hA = packh2(v.x, v.y), hB = packh2(v.z, v.w);
        uint32_t addr = (uint32_t)k * 512 + ((uint32_t)((n4 >> 3) ^ (k & 7)) << 4) + (n4 & 7) * 2;
        *(uint2*)(g_Bimg + addr) = make_uint2(hA, hB);
    } else if (idx < 8704) {                // w1: 32 x 64, rows 128B
        int i = idx - 8192;
        int k = i >> 4, n4 = (i & 15) << 2;
        float4 v = *(const float4*)(w1 + (size_t)k * 64 + n4);
        uint32_t hA, hB, lA, lB; split4(v, hA, hB, lA, lB);
        uint32_t addr = (uint32_t)k * 128 + ((uint32_t)((n4 >> 3) ^ (k & 7)) << 4) + (n4 & 7) * 2;
        *(uint2*)(g_W1img + addr) = make_uint2(hA, hB);
        *(uint2*)(g_W1img + 4096 + addr) = make_uint2(lA, lB);
    } else if (idx < 9728) {                // w2: 64 x 64, rows 128B
        int i = idx - 8704;
        int k = i >> 4, n4 = (i & 15) << 2;
        float4 v = *(const float4*)(w2 + (size_t)k * 64 + n4);
        uint32_t hA, hB, lA, lB; split4(v, hA, hB, lA, lB);
        uint32_t addr = (uint32_t)k * 128 + ((uint32_t)((n4 >> 3) ^ (k & 7)) << 4) + (n4 & 7) * 2;
        *(uint2*)(g_W2img + addr) = make_uint2(hA, hB);
        *(uint2*)(g_W2img + 8192 + addr) = make_uint2(lA, lB);
    } else if (idx < 11776) {               // w3: 64 x 128, rows 256B
        int i = idx - 9728;
        int k = i >> 5, n4 = (i & 31) << 2;
        float4 v = *(const float4*)(w3 + (size_t)k * 128 + n4);
        uint32_t hA, hB, lA, lB; split4(v, hA, hB, lA, lB);
        uint32_t addr = (uint32_t)k * 256 + ((uint32_t)((n4 >> 3) ^ (k & 7)) << 4) + (n4 & 7) * 2;
        *(uint2*)(g_W3img + addr) = make_uint2(hA, hB);
        *(uint2*)(g_W3img + 16384 + addr) = make_uint2(lA, lB);
    }
}

// ---------------- K1: dual node GEMM  msg_src/msg_dst = X @ {w_src,w_dst} ---
__global__ __launch_bounds__(256) void node_gemm_dual(
    const float* __restrict__ X, const float* __restrict__ Wsrc,
    const float* __restrict__ Wdst, const float* __restrict__ bias_src, int n)
{
    __shared__ float At[32 * 64];
    __shared__ float Bs0[32 * 128];
    __shared__ float Bs1[32 * 128];
    int tid = threadIdx.x;
    int r0 = blockIdx.x * 64;
    int cg = tid & 15, rg = tid >> 4;
    int col = cg * 8, row = rg * 4;

    float acc0[4][8], acc1[4][8];
#pragma unroll
    for (int i = 0; i < 4; i++)
#pragma unroll
        for (int j = 0; j < 8; j++) { acc0[i][j] = 0.0f; acc1[i][j] = 0.0f; }

    int lm = tid >> 2, lk = (tid & 3) * 8;
    int lkr = tid >> 3, lc = (tid & 7) * 16;

    for (int k0 = 0; k0 < 128; k0 += 32) {
        float4 a0, a1;
        int gr = r0 + lm;
        if (gr < n) {
            a0 = *(const float4*)(X + (size_t)gr * 128 + k0 + lk);
            a1 = *(const float4*)(X + (size_t)gr * 128 + k0 + lk + 4);
        } else {
            a0 = make_float4(0.f, 0.f, 0.f, 0.f); a1 = a0;
        }
        At[(lk + 0) * 64 + lm] = a0.x; At[(lk + 1) * 64 + lm] = a0.y;
        At[(lk + 2) * 64 + lm] = a0.z; At[(lk + 3) * 64 + lm] = a0.w;
        At[(lk + 4) * 64 + lm] = a1.x; At[(lk + 5) * 64 + lm] = a1.y;
        At[(lk + 6) * 64 + lm] = a1.z; At[(lk + 7) * 64 + lm] = a1.w;
#pragma unroll
        for (int q = 0; q < 4; q++) {
            *(float4*)(Bs0 + lkr * 128 + lc + 4 * q) =
                *(const float4*)(Wsrc + (size_t)(k0 + lkr) * 128 + lc + 4 * q);
            *(float4*)(Bs1 + lkr * 128 + lc + 4 * q) =
                *(const float4*)(Wdst + (size_t)(k0 + lkr) * 128 + lc + 4 * q);
        }
        __syncthreads();
#pragma unroll
        for (int kk = 0; kk < 32; kk++) {
            float a[4], b0[8], b1[8];
            *(float4*)a        = *(float4*)(At + kk * 64 + row);
            *(float4*)(b0)     = *(float4*)(Bs0 + kk * 128 + col);
            *(float4*)(b0 + 4) = *(float4*)(Bs0 + kk * 128 + col + 4);
            *(float4*)(b1)     = *(float4*)(Bs1 + kk * 128 + col);
            *(float4*)(b1 + 4) = *(float4*)(Bs1 + kk * 128 + col + 4);
#pragma unroll
            for (int i = 0; i < 4; i++)
#pragma unroll
                for (int j = 0; j < 8; j++) {
                    acc0[i][j] += a[i] * b0[j];
                    acc1[i][j] += a[i] * b1[j];
                }
        }
        __syncthreads();
    }

    float bj[8];
    *(float4*)bj       = *(const float4*)(bias_src + col);
    *(float4*)(bj + 4) = *(const float4*)(bias_src + col + 4);
#pragma unroll
    for (int i = 0; i < 4; i++) {
        int gr = r0 + row + i;
        if (gr >= n) continue;
        *(float4*)(g_msg_src + (size_t)gr * 128 + col) =
            make_float4(acc0[i][0] + bj[0], acc0[i][1] + bj[1],
                        acc0[i][2] + bj[2], acc0[i][3] + bj[3]);
        *(float4*)(g_msg_src + (size_t)gr * 128 + col + 4) =
            make_float4(acc0[i][4] + bj[4], acc0[i][5] + bj[5],
                        acc0[i][6] + bj[6], acc0[i][7] + bj[7]);
        *(float4*)(g_msg_dst + (size_t)gr * 128 + col) =
            make_float4(acc1[i][0], acc1[i][1], acc1[i][2], acc1[i][3]);
        *(float4*)(g_msg_dst + (size_t)gr * 128 + col + 4) =
            make_float4(acc1[i][4], acc1[i][5], acc1[i][6], acc1[i][7]);
    }
}

// ============================================================================
// K23: FUSED radial-MLP + gather + w_sep GEMM + softmax-free attention scatter
// 128 edges per CTA, 512 threads (16 warps). fp16 HMMA.
//  MLP: A single-fp16, B hi/lo compensated. w_sep GEMM: single-pass fp16.
//  All weights + B staged via cp.async (B overlaps the whole MLP).
//
// Dynamic SMEM (172032 B):
//  [0,32K)      W3 hi/lo  (phase2: A [m][k], rows 256B)
//  [32K,48K)    H1 hi     [48K,64K)  X hi
//  [64K,72K)    W1 hi/lo  [72K,88K)  W2 hi/lo
//  [88K,104K)   H2 hi
//  [104K,168K)  B (w_sep image)  -- NOT aliased, cp.async from kernel start
// ============================================================================
__global__ __launch_bounds__(512, 1) void fused_edge_kernel(
    const float* __restrict__ edge_scalars, const float* __restrict__ edge_attr,
    const int* __restrict__ edge_src, const int* __restrict__ edge_dst,
    const float* __restrict__ b1, const float* __restrict__ b2,
    const float* __restrict__ b3, const float* __restrict__ b_sep,
    const float* __restrict__ alpha_dot, int E)
{
    extern __shared__ char dynsm[];
    __shared__ float sB1[64], sB2[64], sB3[128];
    __shared__ float sBsep[256], sAD[128];
    __shared__ int   sSrc[128], sDst[128];
    __shared__ float sAttr[128];

    const int tid = threadIdx.x;
    const int wid = tid >> 5, lane = tid & 31;
    const int e0 = blockIdx.x * 128;
    const int mtx = lane >> 3, rin = lane & 7;
    const int lr = lane >> 2, lc = lane & 3;

    const uint32_t sb = smem_u32(dynsm);
    const uint32_t W3hi = sb, W3lo = sb + 16384;
    const uint32_t Asm  = sb;                 // phase2 alias of W3
    const uint32_t H1hi = sb + 32768;
    const uint32_t Xhi  = sb + 49152;
    const uint32_t W1hi = sb + 65536;         // lo at +4096
    const uint32_t W2hi = sb + 73728;         // lo at +8192
    const uint32_t H2hi = sb + 90112;
    const uint32_t Bsm  = sb + 106496;

    // ---------------- async weight staging (group 0) ----------------
    CP16(W1hi + tid * 16, g_W1img + tid * 16);                      // 512
#pragma unroll
    for (int it = 0; it < 2; it++) {                                // 1024
        int i = tid + 512 * it;
        CP16(W2hi + i * 16, g_W2img + i * 16);
    }
#pragma unroll
    for (int it = 0; it < 4; it++) {                                // 2048
        int i = tid + 512 * it;
        CP16(W3hi + i * 16, g_W3img + i * 16);
    }
    CP_COMMIT();
    // ---------------- async B staging (group 1) — overlaps the MLP --------
#pragma unroll
    for (int it = 0; it < 8; it++) {                                // 4096
        int i = tid + 512 * it;
        CP16(Bsm + i * 16, g_Bimg + i * 16);
    }
    CP_COMMIT();

    // ---------------- scalar staging ----------------
    if (tid < 64)  { sB1[tid] = b1[tid]; sB2[tid] = b2[tid]; }
    if (tid < 128) { sB3[tid] = b3[tid]; sAD[tid] = alpha_dot[tid]; }
    if (tid < 256) sBsep[tid] = b_sep[tid];
    if (tid < 128) {
        int e = min(e0 + tid, E - 1);
        sSrc[tid] = edge_src[e];
        sDst[tid] = edge_dst[e];
        sAttr[tid] = (e0 + tid < E) ? edge_attr[e] : 0.0f;
    }
    // X: 128 x 32 fp32 -> fp16 hi only
#pragma unroll
    for (int it = 0; it < 2; it++) {
        int i = tid + 512 * it;
        int m = i >> 3, k4 = (i & 7) << 2;
        int e = min(e0 + m, E - 1);
        float4 v = *(const float4*)(edge_scalars + (size_t)e * 32 + k4);
        uint32_t hA = packh2(v.x, v.y), hB = packh2(v.z, v.w);
        uint32_t addr = (uint32_t)m * 128 + ((uint32_t)(((k4 >> 3) ^ (m & 7))) << 4) + (k4 & 7) * 2;
        STS64(Xhi + addr, hA, hB);
    }
    CP_WAIT(1);      // weights (group 0) complete; B still in flight
    __syncthreads();

    // warp tile for MLP: 8 M-tiles x 2 N-tiles
    const int mi1 = wid & 7, ni1 = wid >> 3;
    const int mr = mi1 * 16;

    // ---------------- layer1: H1 = silu(X @ W1 + b1)  [128x64, K=32] --------
    {
        const int nc = ni1 * 32;
        float acc[4][4];
#pragma unroll
        for (int i = 0; i < 4; i++)
#pragma unroll
            for (int j = 0; j < 4; j++) acc[i][j] = 0.0f;
#pragma unroll
        for (int ks = 0; ks < 2; ks++) {
            int m = mr + (mtx & 1) * 8 + rin;
            int kc = ks * 2 + (mtx >> 1);
            uint32_t aH[4];
            LDSM4(aH, Xhi + (uint32_t)m * 128 + ((uint32_t)(kc ^ (m & 7)) << 4));
            uint32_t bH[2][4], bL[2][4];
#pragma unroll
            for (int ntp = 0; ntp < 2; ntp++) {
                int k = ks * 16 + (mtx & 1) * 8 + rin;
                int nch = (nc >> 3) + ntp * 2 + (mtx >> 1);
                uint32_t boff = (uint32_t)k * 128 + ((uint32_t)(nch ^ (k & 7)) << 4);
                LDSM4T(bH[ntp], W1hi + boff);
                LDSM4T(bL[ntp], W1hi + 4096 + boff);
            }
#pragma unroll
            for (int nt = 0; nt < 4; nt++) {
                MMA16816(acc[nt], aH, bH[nt >> 1][(nt & 1) * 2], bH[nt >> 1][(nt & 1) * 2 + 1]);
                MMA16816(acc[nt], aH, bL[nt >> 1][(nt & 1) * 2], bL[nt >> 1][(nt & 1) * 2 + 1]);
            }
        }
#pragma unroll
        for (int nt = 0; nt < 4; nt++) {
            int col = nc + nt * 8 + lc * 2;
            float s0 = silu(acc[nt][0] + sB1[col]);
            float s1 = silu(acc[nt][1] + sB1[col + 1]);
            float s2 = silu(acc[nt][2] + sB1[col]);
            float s3 = silu(acc[nt][3] + sB1[col + 1]);
            int r0 = mr + lr, r1 = r0 + 8;
            uint32_t ad0 = (uint32_t)r0 * 128 + ((uint32_t)((col >> 3) ^ (r0 & 7)) << 4) + (col & 7) * 2;
            STS32(H1hi + ad0, packh2(s0, s1));
            uint32_t ad1 = (uint32_t)r1 * 128 + ((uint32_t)((col >> 3) ^ (r1 & 7)) << 4) + (col & 7) * 2;
            STS32(H1hi + ad1, packh2(s2, s3));
        }
    }
    __syncthreads();

    // ---------------- layer2: H2 = silu(H1 @ W2 + b2)  [128x64, K=64] -------
    {
        const int nc = ni1 * 32;
        float acc[4][4];
#pragma unroll
        for (int i = 0; i < 4; i++)
#pragma unroll
            for (int j = 0; j < 4; j++) acc[i][j] = 0.0f;
#pragma unroll
        for (int ks = 0; ks < 4; ks++) {
            int m = mr + (mtx & 1) * 8 + rin;
            int kc = ks * 2 + (mtx >> 1);
            uint32_t aH[4];
            LDSM4(aH, H1hi + (uint32_t)m * 128 + ((uint32_t)(kc ^ (m & 7)) << 4));
            uint32_t bH[2][4], bL[2][4];
#pragma unroll
            for (int ntp = 0; ntp < 2; ntp++) {
                int k = ks * 16 + (mtx & 1) * 8 + rin;
                int nch = (nc >> 3) + ntp * 2 + (mtx >> 1);
                uint32_t boff = (uint32_t)k * 128 + ((uint32_t)(nch ^ (k & 7)) << 4);
                LDSM4T(bH[ntp], W2hi + boff);
                LDSM4T(bL[ntp], W2hi + 8192 + boff);
            }
#pragma unroll
            for (int nt = 0; nt < 4; nt++) {
                MMA16816(acc[nt], aH, bH[nt >> 1][(nt & 1) * 2], bH[nt >> 1][(nt & 1) * 2 + 1]);
                MMA16816(acc[nt], aH, bL[nt >> 1][(nt & 1) * 2], bL[nt >> 1][(nt & 1) * 2 + 1]);
            }
        }
#pragma unroll
        for (int nt = 0; nt < 4; nt++) {
            int col = nc + nt * 8 + lc * 2;
            float s0 = silu(acc[nt][0] + sB2[col]);
            float s1 = silu(acc[nt][1] + sB2[col + 1]);
            float s2 = silu(acc[nt][2] + sB2[col]);
            float s3 = silu(acc[nt][3] + sB2[col + 1]);
            int r0 = mr + lr, r1 = r0 + 8;
            uint32_t ad0 = (uint32_t)r0 * 128 + ((uint32_t)((col >> 3) ^ (r0 & 7)) << 4) + (col & 7) * 2;
            STS32(H2hi + ad0, packh2(s0, s1));
            uint32_t ad1 = (uint32_t)r1 * 128 + ((uint32_t)((col >> 3) ^ (r1 & 7)) << 4) + (col & 7) * 2;
            STS32(H2hi + ad1, packh2(s2, s3));
        }
    }
    __syncthreads();

    // ---------------- layer3: rad = H2 @ W3 + b3  [128x128, K=64] (regs) ----
    float acc3[8][4];
#pragma unroll
    for (int i = 0; i < 8; i++)
#pragma unroll
        for (int j = 0; j < 4; j++) acc3[i][j] = 0.0f;
    {
        const int nc = ni1 * 64;
#pragma unroll
        for (int ks = 0; ks < 4; ks++) {
            int m = mr + (mtx & 1) * 8 + rin;
            int kc = ks * 2 + (mtx >> 1);
            uint32_t aH[4];
            LDSM4(aH, H2hi + (uint32_t)m * 128 + ((uint32_t)(kc ^ (m & 7)) << 4));
            uint32_t bH[4][4];
#pragma unroll
            for (int ntp = 0; ntp < 4; ntp++) {
                int k = ks * 16 + (mtx & 1) * 8 + rin;
                int nch = (nc >> 3) + ntp * 2 + (mtx >> 1);
                uint32_t boff = (uint32_t)k * 256 + ((uint32_t)(nch ^ (k & 7)) << 4);
                LDSM4T(bH[ntp], W3hi + boff);
            }
#pragma unroll
            for (int nt = 0; nt < 8; nt++)
                MMA16816(acc3[nt], aH, bH[nt >> 1][(nt & 1) * 2], bH[nt >> 1][(nt & 1) * 2 + 1]);
            uint32_t bL[4][4];
#pragma unroll
            for (int ntp = 0; ntp < 4; ntp++) {
                int k = ks * 16 + (mtx & 1) * 8 + rin;
                int nch = (nc >> 3) + ntp * 2 + (mtx >> 1);
                uint32_t boff = (uint32_t)k * 256 + ((uint32_t)(nch ^ (k & 7)) << 4);
                LDSM4T(bL[ntp], W3lo + boff);
            }
#pragma unroll
            for (int nt = 0; nt < 8; nt++)
                MMA16816(acc3[nt], aH, bL[nt >> 1][(nt & 1) * 2], bL[nt >> 1][(nt & 1) * 2 + 1]);
        }
    }
    __syncthreads();   // all W3/H2 reads done; A (aliases W3) now writable

    // ---------------- gather msgs + form A = (src+dst)*attr*rad (fp16) ------
    {
        const int nc = ni1 * 64;
#pragma unroll
        for (int rh = 0; rh < 2; rh++) {
            int r = mr + rh * 8 + lr;
            int src = sSrc[r], dst = sDst[r];
            float at = sAttr[r];
            const float* ps = g_msg_src + (size_t)src * 128;
            const float* pd = g_msg_dst + (size_t)dst * 128;
#pragma unroll
            for (int nt = 0; nt < 8; nt++) {
                int col = nc + nt * 8 + lc * 2;
                float rad0 = acc3[nt][rh * 2 + 0] + sB3[col];
                float rad1 = acc3[nt][rh * 2 + 1] + sB3[col + 1];
                float2 ms = *(const float2*)(ps + col);
                float2 md = *(const float2*)(pd + col);
                float m0 = (ms.x + md.x) * at * rad0;
                float m1 = (ms.y + md.y) * at * rad1;
                uint32_t ad = (uint32_t)r * 256 + ((uint32_t)((col >> 3) ^ (r & 7)) << 4) + (col & 7) * 2;
                STS32(Asm + ad, packh2(m0, m1));
            }
        }
    }
    CP_WAIT(0);        // B (group 1) complete — overlapped with the whole MLP
    __syncthreads();

    // ---------------- phase2: D[128,256] = A @ B + epilogue -----------------
    const int mi = wid & 3, ni = wid >> 2;
    const int mrow0 = mi * 32, ncol0 = ni * 64;

    float d[2][8][4];
#pragma unroll
    for (int a = 0; a < 2; a++)
#pragma unroll
        for (int b = 0; b < 8; b++)
#pragma unroll
            for (int c = 0; c < 4; c++) d[a][b][c] = 0.0f;

#pragma unroll
    for (int ks = 0; ks < 8; ks++) {
        uint32_t ah[2][4];
#pragma unroll
        for (int mt = 0; mt < 2; mt++) {
            int m = mrow0 + mt * 16 + (mtx & 1) * 8 + rin;
            int kchunk = ks * 2 + (mtx >> 1);
            LDSM4(ah[mt], Asm + (uint32_t)m * 256 + ((uint32_t)(kchunk ^ (m & 7)) << 4));
        }
        uint32_t b[4][4];
#pragma unroll
        for (int ntp = 0; ntp < 4; ntp++) {
            int k = ks * 16 + (mtx & 1) * 8 + rin;
            int nchunk = (ncol0 >> 3) + ntp * 2 + (mtx >> 1);
            LDSM4T(b[ntp], Bsm + (uint32_t)k * 512 + ((uint32_t)(nchunk ^ (k & 7)) << 4));
        }
#pragma unroll
        for (int mt = 0; mt < 2; mt++)
#pragma unroll
            for (int nt = 0; nt < 8; nt++)
                MMA16816(d[mt][nt], ah[mt], b[nt >> 1][(nt & 1) * 2], b[nt >> 1][(nt & 1) * 2 + 1]);
    }

    // ---- epilogue: w = exp(score); direct segment reduction ----
#pragma unroll
    for (int hh = 0; hh < 2; hh++) {
        const int h = ni * 2 + hh;
#pragma unroll
        for (int mt = 0; mt < 2; mt++) {
            const int r0i = mrow0 + mt * 16 + lr;
            const int e0i = e0 + r0i;
            float p0 = 0.0f, p1 = 0.0f;
#pragma unroll
            for (int q = 0; q < 2; q++) {
                const int nt = hh * 4 + q;
                const int colb = ncol0 + nt * 8 + lc * 2;
                const int jb = q * 8 + lc * 2;
                const float bb0 = sBsep[colb], bb1 = sBsep[colb + 1];
                const float w0 = sAD[h * 16 + jb], w1 = sAD[h * 16 + jb + 1];
                float x, sg;
                x = d[mt][nt][0] + bb0; sg = 1.0f / (1.0f + __expf(-x)); p0 += x * (0.2f + 0.8f * sg) * w0;
                x = d[mt][nt][1] + bb1; sg = 1.0f / (1.0f + __expf(-x)); p0 += x * (0.2f + 0.8f * sg) * w1;
                x = d[mt][nt][2] + bb0; sg = 1.0f / (1.0f + __expf(-x)); p1 += x * (0.2f + 0.8f * sg) * w0;
                x = d[mt][nt][3] + bb1; sg = 1.0f / (1.0f + __expf(-x)); p1 += x * (0.2f + 0.8f * sg) * w1;
            }
            p0 += __shfl_xor_sync(0xffffffffu, p0, 1);
            p0 += __shfl_xor_sync(0xffffffffu, p0, 2);
            p1 += __shfl_xor_sync(0xffffffffu, p1, 1);
            p1 += __shfl_xor_sync(0xffffffffu, p1, 2);
            const float ew0 = __expf(p0), ew1 = __expf(p1);
            const int d0 = sDst[r0i], d1 = sDst[r0i + 8];
            if (lc == 0) {
                if (e0i < E)     atomicAdd(&g_nsum[(size_t)d0 * 8 + h], ew0);
                if (e0i + 8 < E) atomicAdd(&g_nsum[(size_t)d1 * 8 + h], ew1);
            }
#pragma unroll
            for (int q = 0; q < 2; q++) {
                const int nt = hh * 4 + 2 + q;
                const int colb = ncol0 + nt * 8 + lc * 2;
                const int vidx = q * 8 + lc * 2;
                const float bb0 = sBsep[colb], bb1 = sBsep[colb + 1];
                if (e0i < E)
                    RED2(g_nacc + (size_t)d0 * 128 + h * 16 + vidx,
                         (d[mt][nt][0] + bb0) * ew0, (d[mt][nt][1] + bb1) * ew0);
                if (e0i + 8 < E)
                    RED2(g_nacc + (size_t)d1 * 128 + h * 16 + vidx,
                         (d[mt][nt][2] + bb0) * ew1, (d[mt][nt][3] + bb1) * ew1);
            }
        }
    }
}

// ---------------- K5: out = (nacc / (nsum+eps)) @ w_proj + b_proj -----------
__global__ __launch_bounds__(256) void out_gemm_kernel(
    const float* __restrict__ W, const float* __restrict__ bias,
    float* __restrict__ out, int n)
{
    __shared__ float At[32 * 64];
    __shared__ float Bs[32 * 128];
    int tid = threadIdx.x;
    int r0 = blockIdx.x * 64;
    int cg = tid & 15, rg = tid >> 4;
    int col = cg * 8, row = rg * 4;

    float acc[4][8];
#pragma unroll
    for (int i = 0; i < 4; i++)
#pragma unroll
        for (int j = 0; j < 8; j++) acc[i][j] = 0.0f;

    int lm = tid >> 2, lk = (tid & 3) * 8;
    int lkr = tid >> 3, lc = (tid & 7) * 16;

    for (int k0 = 0; k0 < 128; k0 += 32) {
        float4 a0, a1;
        int gr = r0 + lm;
        if (gr < n) {
            a0 = *(const float4*)(g_nacc + (size_t)gr * 128 + k0 + lk);
            a1 = *(const float4*)(g_nacc + (size_t)gr * 128 + k0 + lk + 4);
            int hh = (k0 + lk) >> 4;
            float inv = 1.0f / (g_nsum[(size_t)gr * 8 + hh] + 1e-16f);
            a0.x *= inv; a0.y *= inv; a0.z *= inv; a0.w *= inv;
            a1.x *= inv; a1.y *= inv; a1.z *= inv; a1.w *= inv;
        } else {
            a0 = make_float4(0.f, 0.f, 0.f, 0.f); a1 = a0;
        }
        At[(lk + 0) * 64 + lm] = a0.x; At[(lk + 1) * 64 + lm] = a0.y;
        At[(lk + 2) * 64 + lm] = a0.z; At[(lk + 3) * 64 + lm] = a0.w;
        At[(lk + 4) * 64 + lm] = a1.x; At[(lk + 5) * 64 + lm] = a1.y;
        At[(lk + 6) * 64 + lm] = a1.z; At[(lk + 7) * 64 + lm] = a1.w;
#pragma unroll
        for (int q = 0; q < 4; q++)
            *(float4*)(Bs + lkr * 128 + lc + 4 * q) =
                *(const float4*)(W + (size_t)(k0 + lkr) * 128 + lc + 4 * q);
        __syncthreads();
#pragma unroll
        for (int kk = 0; kk < 32; kk++) {
            float a[4], b[8];
            *(float4*)a       = *(float4*)(At + kk * 64 + row);
            *(float4*)(b)     = *(float4*)(Bs + kk * 128 + col);
            *(float4*)(b + 4) = *(float4*)(Bs + kk * 128 + col + 4);
#pragma unroll
            for (int i = 0; i < 4; i++)
#pragma unroll
                for (int j = 0; j < 8; j++) acc[i][j] += a[i] * b[j];
        }
        __syncthreads();
    }

    float bj[8];
    *(float4*)(bj)     = *(const float4*)(bias + col);
    *(float4*)(bj + 4) = *(const float4*)(bias + col + 4);
#pragma unroll
    for (int i = 0; i < 4; i++) {
        int gr = r0 + row + i;
        if (gr >= n) continue;
        float4 o0 = make_float4(acc[i][0] + bj[0], acc[i][1] + bj[1],
                                acc[i][2] + bj[2], acc[i][3] + bj[3]);
        float4 o1 = make_float4(acc[i][4] + bj[4], acc[i][5] + bj[5],
                                acc[i][6] + bj[6], acc[i][7] + bj[7]);
        *(float4*)(out + (size_t)gr * 128 + col)     = o0;
        *(float4*)(out + (size_t)gr * 128 + col + 4) = o1;
    }
}

// ---------------- launch ----------------
extern "C" void kernel_launch(void* const* d_in, const int* in_sizes, int n_in,
                              void* d_out, int out_size)
{
    const float* node_input = (const float*)d_in[0];
    const float* edge_attr  = (const float*)d_in[2];
    const float* edge_scal  = (const float*)d_in[3];
    const int*   edge_src   = (const int*)d_in[4];
    const int*   edge_dst   = (const int*)d_in[5];
    const float* w_src      = (const float*)d_in[7];
    const float* b_src      = (const float*)d_in[8];
    const float* w_dst      = (const float*)d_in[9];
    const float* fc_w1      = (const float*)d_in[10];
    const float* fc_b1      = (const float*)d_in[11];
    const float* fc_w2      = (const float*)d_in[12];
    const float* fc_b2      = (const float*)d_in[13];
    const float* fc_w3      = (const float*)d_in[14];
    const float* fc_b3      = (const float*)d_in[15];
    const float* w_sep      = (const float*)d_in[16];
    const float* b_sep      = (const float*)d_in[17];
    const float* alpha_dot  = (const float*)d_in[18];
    const float* w_proj     = (const float*)d_in[19];
    const float* b_proj     = (const float*)d_in[20];
    float* out = (float*)d_out;

    int N = in_sizes[0] / 128;
    int E = in_sizes[4];

    cudaFuncSetAttribute(fused_edge_kernel, cudaFuncAttributeMaxDynamicSharedMemorySize, 172032);

    init_kernel<<<(N * 128 + 255) / 256, 256>>>(N);
    prep_kernel<<<46, 256>>>(fc_w1, fc_w2, fc_w3, w_sep);

    int nb = (N + 63) / 64;
    node_gemm_dual<<<nb, 256>>>(node_input, w_src, w_dst, b_src, N);

    int tb = (E + 127) / 128;
    fused_edge_kernel<<<tb, 512, 172032>>>(edge_scal, edge_attr, edge_src, edge_dst,
                                           fc_b1, fc_b2, fc_b3,
                                           b_sep, alpha_dot, E);

    out_gemm_kernel<<<nb, 256>>>(w_proj, b_proj, out, N);
}